// round 3
// baseline (speedup 1.0000x reference)
#include <cuda_runtime.h>
#include <cuda_bf16.h>

// Problem constants
#define Bc 4
#define Sc 2048
#define Dc 1024
#define Hc 16
#define HDc 64
#define Mrows (Bc*Sc)   // 8192

// Device scratch
__device__ float g_Qh[(size_t)Bc*Hc*Sc*HDc];   // [B,H,S,64]
__device__ float g_Kh[(size_t)Bc*Hc*Sc*HDc];
__device__ float g_Vh[(size_t)Bc*Hc*Sc*HDc];
__device__ float g_ctx[(size_t)Bc*Sc*Dc];      // [B,S,D]

// ---------------------------------------------------------------------------
// bf16 split helpers: x ~= hi + lo, both bf16. Pack k-adjacent pairs into u32.
// ---------------------------------------------------------------------------
__device__ __forceinline__ void split_pair(float x0, float x1,
                                           unsigned& hi, unsigned& lo)
{
    __nv_bfloat16 h0 = __float2bfloat16_rn(x0);
    __nv_bfloat16 h1 = __float2bfloat16_rn(x1);
    float r0 = x0 - __bfloat162float(h0);
    float r1 = x1 - __bfloat162float(h1);
    __nv_bfloat16 l0 = __float2bfloat16_rn(r0);
    __nv_bfloat16 l1 = __float2bfloat16_rn(r1);
    unsigned uh0 = __bfloat16_as_ushort(h0), uh1 = __bfloat16_as_ushort(h1);
    unsigned ul0 = __bfloat16_as_ushort(l0), ul1 = __bfloat16_as_ushort(l1);
    hi = (uh1 << 16) | uh0;
    lo = (ul1 << 16) | ul0;
}

__device__ __forceinline__ void mma16816(float c[4], const unsigned a[4],
                                         const unsigned b[2])
{
    asm volatile(
        "mma.sync.aligned.m16n8k16.row.col.f32.bf16.bf16.f32 "
        "{%0,%1,%2,%3}, {%4,%5,%6,%7}, {%8,%9}, {%0,%1,%2,%3};\n"
        : "+f"(c[0]), "+f"(c[1]), "+f"(c[2]), "+f"(c[3])
        : "r"(a[0]), "r"(a[1]), "r"(a[2]), "r"(a[3]),
          "r"(b[0]), "r"(b[1]));
}

// ---------------------------------------------------------------------------
// Tensor-core SGEMM via bf16x3: out[m,n] = sum_k X[m,k]*W[n,k] + bias[n]
// X: [8192,1024] rm, W: [1024,1024] rm. Block 128x128, BK=32, 8 warps (2x4).
// OUT_MODE 0: scatter to [B,H,S,64]; OUT_MODE 1: plain [m,n].
// ---------------------------------------------------------------------------
#define KP 20   // u32 stride per row: 16 data pairs + 4 pad (conflict-free)

template <int OUT_MODE>
__global__ __launch_bounds__(256, 1)
void gemm_mma_kernel(const float* __restrict__ X,
                     const float* __restrict__ W,
                     const float* __restrict__ bias,
                     float* __restrict__ out)
{
    __shared__ unsigned As_hi[128][KP];
    __shared__ unsigned As_lo[128][KP];
    __shared__ unsigned Bs_hi[128][KP];
    __shared__ unsigned Bs_lo[128][KP];

    const int t    = threadIdx.x;
    const int lane = t & 31;
    const int wid  = t >> 5;            // 0..7
    const int wm   = wid >> 2;          // 0..1  -> m offset 64*wm
    const int wn   = wid & 3;           // 0..3  -> n offset 32*wn
    const int g    = lane >> 2;         // group 0..7
    const int tig  = lane & 3;          // 0..3

    const int m0 = blockIdx.y * 128;
    const int n0 = blockIdx.x * 128;

    const float* Aptr = X + (size_t)m0 * 1024;
    const float* Bptr = W + (size_t)n0 * 1024;

    // staging slot geometry: 1024 float4 slots per matrix per tile, 4/thread
    int srow[4], scol[4];
#pragma unroll
    for (int p = 0; p < 4; ++p) {
        int slot = t + p * 256;
        srow[p] = slot >> 3;            // 0..127
        scol[p] = (slot & 7) << 2;      // 0,4,..,28
    }

    float c[4][4][4];
#pragma unroll
    for (int i = 0; i < 4; ++i)
#pragma unroll
        for (int j = 0; j < 4; ++j)
#pragma unroll
            for (int e = 0; e < 4; ++e) c[i][j][e] = 0.0f;

    // prefetch tile 0 into registers
    float4 ar[4], br[4];
#pragma unroll
    for (int p = 0; p < 4; ++p) {
        ar[p] = *reinterpret_cast<const float4*>(Aptr + (size_t)srow[p] * 1024 + scol[p]);
        br[p] = *reinterpret_cast<const float4*>(Bptr + (size_t)srow[p] * 1024 + scol[p]);
    }

    const int NT = 1024 / 32;           // 32 k-tiles
    for (int kt = 0; kt < NT; ++kt) {
        // store staged regs -> smem (split bf16 hi/lo)
#pragma unroll
        for (int p = 0; p < 4; ++p) {
            int r = srow[p], cp = scol[p] >> 1;   // pair index base
            unsigned h0, l0, h1, l1;
            split_pair(ar[p].x, ar[p].y, h0, l0);
            split_pair(ar[p].z, ar[p].w, h1, l1);
            As_hi[r][cp] = h0; As_hi[r][cp + 1] = h1;
            As_lo[r][cp] = l0; As_lo[r][cp + 1] = l1;
            split_pair(br[p].x, br[p].y, h0, l0);
            split_pair(br[p].z, br[p].w, h1, l1);
            Bs_hi[r][cp] = h0; Bs_hi[r][cp + 1] = h1;
            Bs_lo[r][cp] = l0; Bs_lo[r][cp + 1] = l1;
        }
        __syncthreads();

        // prefetch next tile while computing this one
        if (kt + 1 < NT) {
            int k0 = (kt + 1) * 32;
#pragma unroll
            for (int p = 0; p < 4; ++p) {
                ar[p] = *reinterpret_cast<const float4*>(Aptr + (size_t)srow[p] * 1024 + k0 + scol[p]);
                br[p] = *reinterpret_cast<const float4*>(Bptr + (size_t)srow[p] * 1024 + k0 + scol[p]);
            }
        }

        // two k16 steps
#pragma unroll
        for (int ks = 0; ks < 2; ++ks) {
            const int pb = ks * 8;
            unsigned ahi[4][4], alo[4][4];
#pragma unroll
            for (int mf = 0; mf < 4; ++mf) {
                int r = wm * 64 + mf * 16 + g;
                ahi[mf][0] = As_hi[r][pb + tig];
                ahi[mf][1] = As_hi[r + 8][pb + tig];
                ahi[mf][2] = As_hi[r][pb + tig + 4];
                ahi[mf][3] = As_hi[r + 8][pb + tig + 4];
                alo[mf][0] = As_lo[r][pb + tig];
                alo[mf][1] = As_lo[r + 8][pb + tig];
                alo[mf][2] = As_lo[r][pb + tig + 4];
                alo[mf][3] = As_lo[r + 8][pb + tig + 4];
            }
            unsigned bhi[4][2], blo[4][2];
#pragma unroll
            for (int nf = 0; nf < 4; ++nf) {
                int cn = wn * 32 + nf * 8 + g;
                bhi[nf][0] = Bs_hi[cn][pb + tig];
                bhi[nf][1] = Bs_hi[cn][pb + tig + 4];
                blo[nf][0] = Bs_lo[cn][pb + tig];
                blo[nf][1] = Bs_lo[cn][pb + tig + 4];
            }
#pragma unroll
            for (int mf = 0; mf < 4; ++mf)
#pragma unroll
                for (int nf = 0; nf < 4; ++nf) {
                    mma16816(c[mf][nf], ahi[mf], bhi[nf]);
                    mma16816(c[mf][nf], ahi[mf], blo[nf]);
                    mma16816(c[mf][nf], alo[mf], bhi[nf]);
                }
        }
        __syncthreads();
    }

    // Epilogue
#pragma unroll
    for (int mf = 0; mf < 4; ++mf) {
#pragma unroll
        for (int nf = 0; nf < 4; ++nf) {
            int m  = m0 + wm * 64 + mf * 16 + g;
            int n  = n0 + wn * 32 + nf * 8 + tig * 2;
            float v0 = c[mf][nf][0] + bias[n];
            float v1 = c[mf][nf][1] + bias[n + 1];
            float v2 = c[mf][nf][2] + bias[n];
            float v3 = c[mf][nf][3] + bias[n + 1];
            if (OUT_MODE == 0) {
                int b = m >> 11, s = m & 2047;
                int h = n >> 6, hd = n & 63;
                size_t base = (((size_t)(b * Hc + h)) * Sc + s) * HDc + hd;
                out[base]     = v0;
                out[base + 1] = v1;
                int m2 = m + 8;
                size_t base2 = (((size_t)(b * Hc + h)) * Sc + (m2 & 2047)) * HDc + hd;
                out[base2]     = v2;
                out[base2 + 1] = v3;
            } else {
                out[(size_t)m * Dc + n]       = v0;
                out[(size_t)m * Dc + n + 1]   = v1;
                out[(size_t)(m + 8) * Dc + n]     = v2;
                out[(size_t)(m + 8) * Dc + n + 1] = v3;
            }
        }
    }
}

// ---------------------------------------------------------------------------
// Flash attention (causal), fp32 SIMT (unchanged from R1).
// ---------------------------------------------------------------------------
#define ATTN_PAD 65
#define ATTN_SMEM (4 * 64 * ATTN_PAD * (int)sizeof(float))

__global__ __launch_bounds__(256)
void attn_kernel(const float* __restrict__ Qh,
                 const float* __restrict__ Kh,
                 const float* __restrict__ Vh,
                 float* __restrict__ ctx)
{
    extern __shared__ float sm[];
    float (*Qs)[ATTN_PAD] = reinterpret_cast<float(*)[ATTN_PAD]>(sm);
    float (*Ks)[ATTN_PAD] = reinterpret_cast<float(*)[ATTN_PAD]>(sm + 64 * ATTN_PAD);
    float (*Vs)[ATTN_PAD] = reinterpret_cast<float(*)[ATTN_PAD]>(sm + 2 * 64 * ATTN_PAD);
    float (*Ps)[ATTN_PAD] = reinterpret_cast<float(*)[ATTN_PAD]>(sm + 3 * 64 * ATTN_PAD);

    const int bh = blockIdx.y;
    const int qt = blockIdx.x;
    const int q0 = qt * 64;
    const int t  = threadIdx.x;
    const int tx = t & 15;
    const int ty = t >> 4;

    const float* Qb = Qh + (size_t)bh * Sc * HDc;
    const float* Kb = Kh + (size_t)bh * Sc * HDc;
    const float* Vb = Vh + (size_t)bh * Sc * HDc;

    for (int i = t; i < 64 * 64; i += 256) {
        int r = i >> 6, d = i & 63;
        Qs[r][d] = Qb[(size_t)(q0 + r) * HDc + d] * 0.125f;
    }

    float m_i[4], l_i[4], acc[4][4];
#pragma unroll
    for (int i = 0; i < 4; ++i) {
        m_i[i] = -1e30f; l_i[i] = 0.0f;
#pragma unroll
        for (int j = 0; j < 4; ++j) acc[i][j] = 0.0f;
    }

    for (int kt = 0; kt <= qt; ++kt) {
        const int k0 = kt * 64;
        __syncthreads();

        for (int i = t; i < 64 * 64; i += 256) {
            int r = i >> 6, d = i & 63;
            Ks[r][d] = Kb[(size_t)(k0 + r) * HDc + d];
            Vs[r][d] = Vb[(size_t)(k0 + r) * HDc + d];
        }
        __syncthreads();

        float s[4][4];
#pragma unroll
        for (int i = 0; i < 4; ++i)
#pragma unroll
            for (int j = 0; j < 4; ++j) s[i][j] = 0.0f;

#pragma unroll 8
        for (int d = 0; d < 64; ++d) {
            float a0 = Qs[ty * 4 + 0][d], a1 = Qs[ty * 4 + 1][d];
            float a2 = Qs[ty * 4 + 2][d], a3 = Qs[ty * 4 + 3][d];
            float b0 = Ks[tx * 4 + 0][d], b1 = Ks[tx * 4 + 1][d];
            float b2 = Ks[tx * 4 + 2][d], b3 = Ks[tx * 4 + 3][d];
            s[0][0] = fmaf(a0, b0, s[0][0]); s[0][1] = fmaf(a0, b1, s[0][1]);
            s[0][2] = fmaf(a0, b2, s[0][2]); s[0][3] = fmaf(a0, b3, s[0][3]);
            s[1][0] = fmaf(a1, b0, s[1][0]); s[1][1] = fmaf(a1, b1, s[1][1]);
            s[1][2] = fmaf(a1, b2, s[1][2]); s[1][3] = fmaf(a1, b3, s[1][3]);
            s[2][0] = fmaf(a2, b0, s[2][0]); s[2][1] = fmaf(a2, b1, s[2][1]);
            s[2][2] = fmaf(a2, b2, s[2][2]); s[2][3] = fmaf(a2, b3, s[2][3]);
            s[3][0] = fmaf(a3, b0, s[3][0]); s[3][1] = fmaf(a3, b1, s[3][1]);
            s[3][2] = fmaf(a3, b2, s[3][2]); s[3][3] = fmaf(a3, b3, s[3][3]);
        }

        if (kt == qt) {
#pragma unroll
            for (int i = 0; i < 4; ++i)
#pragma unroll
                for (int j = 0; j < 4; ++j)
                    if (tx * 4 + j > ty * 4 + i) s[i][j] = -1e30f;
        }

#pragma unroll
        for (int i = 0; i < 4; ++i) {
            float mm = fmaxf(fmaxf(s[i][0], s[i][1]), fmaxf(s[i][2], s[i][3]));
#pragma unroll
            for (int o = 1; o < 16; o <<= 1)
                mm = fmaxf(mm, __shfl_xor_sync(0xffffffffu, mm, o));
            float mnew = fmaxf(m_i[i], mm);
            float csc  = __expf(m_i[i] - mnew);
            float p0 = __expf(s[i][0] - mnew);
            float p1 = __expf(s[i][1] - mnew);
            float p2 = __expf(s[i][2] - mnew);
            float p3 = __expf(s[i][3] - mnew);
            float lad = p0 + p1 + p2 + p3;
#pragma unroll
            for (int o = 1; o < 16; o <<= 1)
                lad += __shfl_xor_sync(0xffffffffu, lad, o);
            l_i[i] = l_i[i] * csc + lad;
            m_i[i] = mnew;
#pragma unroll
            for (int j = 0; j < 4; ++j) acc[i][j] *= csc;
            Ps[ty * 4 + i][tx * 4 + 0] = p0;
            Ps[ty * 4 + i][tx * 4 + 1] = p1;
            Ps[ty * 4 + i][tx * 4 + 2] = p2;
            Ps[ty * 4 + i][tx * 4 + 3] = p3;
        }
        __syncthreads();

#pragma unroll 8
        for (int kk = 0; kk < 64; ++kk) {
            float a0 = Ps[ty * 4 + 0][kk], a1 = Ps[ty * 4 + 1][kk];
            float a2 = Ps[ty * 4 + 2][kk], a3 = Ps[ty * 4 + 3][kk];
            float b0 = Vs[kk][tx * 4 + 0], b1 = Vs[kk][tx * 4 + 1];
            float b2 = Vs[kk][tx * 4 + 2], b3 = Vs[kk][tx * 4 + 3];
            acc[0][0] = fmaf(a0, b0, acc[0][0]); acc[0][1] = fmaf(a0, b1, acc[0][1]);
            acc[0][2] = fmaf(a0, b2, acc[0][2]); acc[0][3] = fmaf(a0, b3, acc[0][3]);
            acc[1][0] = fmaf(a1, b0, acc[1][0]); acc[1][1] = fmaf(a1, b1, acc[1][1]);
            acc[1][2] = fmaf(a1, b2, acc[1][2]); acc[1][3] = fmaf(a1, b3, acc[1][3]);
            acc[2][0] = fmaf(a2, b0, acc[2][0]); acc[2][1] = fmaf(a2, b1, acc[2][1]);
            acc[2][2] = fmaf(a2, b2, acc[2][2]); acc[2][3] = fmaf(a2, b3, acc[2][3]);
            acc[3][0] = fmaf(a3, b0, acc[3][0]); acc[3][1] = fmaf(a3, b1, acc[3][1]);
            acc[3][2] = fmaf(a3, b2, acc[3][2]); acc[3][3] = fmaf(a3, b3, acc[3][3]);
        }
    }

    const int b = bh >> 4;
    const int h = bh & 15;
#pragma unroll
    for (int i = 0; i < 4; ++i) {
        float inv = 1.0f / l_i[i];
        int srw = q0 + ty * 4 + i;
#pragma unroll
        for (int j = 0; j < 4; ++j) {
            ctx[((size_t)(b * Sc + srw)) * Dc + h * 64 + tx * 4 + j] = acc[i][j] * inv;
        }
    }
}

// ---------------------------------------------------------------------------
// Launch
// ---------------------------------------------------------------------------
extern "C" void kernel_launch(void* const* d_in, const int* in_sizes, int n_in,
                              void* d_out, int out_size)
{
    const float* q  = (const float*)d_in[0];
    const float* k  = (const float*)d_in[1];
    const float* v  = (const float*)d_in[2];
    const float* Wq = (const float*)d_in[4];
    const float* bq = (const float*)d_in[5];
    const float* Wk = (const float*)d_in[6];
    const float* bk = (const float*)d_in[7];
    const float* Wv = (const float*)d_in[8];
    const float* bv = (const float*)d_in[9];
    const float* Wo = (const float*)d_in[10];
    const float* bo = (const float*)d_in[11];
    float* out = (float*)d_out;

    void *pQ, *pK, *pV, *pC;
    cudaGetSymbolAddress(&pQ, g_Qh);
    cudaGetSymbolAddress(&pK, g_Kh);
    cudaGetSymbolAddress(&pV, g_Vh);
    cudaGetSymbolAddress(&pC, g_ctx);

    cudaFuncSetAttribute(attn_kernel, cudaFuncAttributeMaxDynamicSharedMemorySize, ATTN_SMEM);

    dim3 gg(Dc / 128, Mrows / 128);   // (8, 64)
    gemm_mma_kernel<0><<<gg, 256>>>(q, Wq, bq, (float*)pQ);
    gemm_mma_kernel<0><<<gg, 256>>>(k, Wk, bk, (float*)pK);
    gemm_mma_kernel<0><<<gg, 256>>>(v, Wv, bv, (float*)pV);

    dim3 ga(Sc / 64, Bc * Hc);        // (32, 64)
    attn_kernel<<<ga, 256, ATTN_SMEM>>>((const float*)pQ, (const float*)pK,
                                        (const float*)pV, (float*)pC);

    gemm_mma_kernel<1><<<gg, 256>>>((const float*)pC, Wo, bo, out);
}

// round 4
// speedup vs baseline: 1.6282x; 1.6282x over previous
#include <cuda_runtime.h>
#include <cuda_bf16.h>

// Problem constants
#define Bc 4
#define Sc 2048
#define Dc 1024
#define Hc 16
#define HDc 64
#define Mrows (Bc*Sc)   // 8192

// Device scratch
__device__ float g_Qh[(size_t)Bc*Hc*Sc*HDc];   // [B,H,S,64]
__device__ float g_Kh[(size_t)Bc*Hc*Sc*HDc];
__device__ float g_Vh[(size_t)Bc*Hc*Sc*HDc];
__device__ float g_ctx[(size_t)Bc*Sc*Dc];      // [B,S,D]

// ---------------------------------------------------------------------------
// bf16 split helpers: x ~= hi + lo, both bf16. Pack (x0,x1) with x0 in low 16.
// ---------------------------------------------------------------------------
__device__ __forceinline__ void split_pair(float x0, float x1,
                                           unsigned& hi, unsigned& lo)
{
    __nv_bfloat16 h0 = __float2bfloat16_rn(x0);
    __nv_bfloat16 h1 = __float2bfloat16_rn(x1);
    float r0 = x0 - __bfloat162float(h0);
    float r1 = x1 - __bfloat162float(h1);
    __nv_bfloat16 l0 = __float2bfloat16_rn(r0);
    __nv_bfloat16 l1 = __float2bfloat16_rn(r1);
    unsigned uh0 = __bfloat16_as_ushort(h0), uh1 = __bfloat16_as_ushort(h1);
    unsigned ul0 = __bfloat16_as_ushort(l0), ul1 = __bfloat16_as_ushort(l1);
    hi = (uh1 << 16) | uh0;
    lo = (ul1 << 16) | ul0;
}

__device__ __forceinline__ void mma16816(float c[4], const unsigned a[4],
                                         const unsigned b[2])
{
    asm volatile(
        "mma.sync.aligned.m16n8k16.row.col.f32.bf16.bf16.f32 "
        "{%0,%1,%2,%3}, {%4,%5,%6,%7}, {%8,%9}, {%0,%1,%2,%3};\n"
        : "+f"(c[0]), "+f"(c[1]), "+f"(c[2]), "+f"(c[3])
        : "r"(a[0]), "r"(a[1]), "r"(a[2]), "r"(a[3]),
          "r"(b[0]), "r"(b[1]));
}

// ---------------------------------------------------------------------------
// Tensor-core SGEMM via bf16x3 (unchanged from R2)
// ---------------------------------------------------------------------------
#define KP 20

template <int OUT_MODE>
__global__ __launch_bounds__(256, 1)
void gemm_mma_kernel(const float* __restrict__ X,
                     const float* __restrict__ W,
                     const float* __restrict__ bias,
                     float* __restrict__ out)
{
    __shared__ unsigned As_hi[128][KP];
    __shared__ unsigned As_lo[128][KP];
    __shared__ unsigned Bs_hi[128][KP];
    __shared__ unsigned Bs_lo[128][KP];

    const int t    = threadIdx.x;
    const int lane = t & 31;
    const int wid  = t >> 5;
    const int wm   = wid >> 2;
    const int wn   = wid & 3;
    const int g    = lane >> 2;
    const int tig  = lane & 3;

    const int m0 = blockIdx.y * 128;
    const int n0 = blockIdx.x * 128;

    const float* Aptr = X + (size_t)m0 * 1024;
    const float* Bptr = W + (size_t)n0 * 1024;

    int srow[4], scol[4];
#pragma unroll
    for (int p = 0; p < 4; ++p) {
        int slot = t + p * 256;
        srow[p] = slot >> 3;
        scol[p] = (slot & 7) << 2;
    }

    float c[4][4][4];
#pragma unroll
    for (int i = 0; i < 4; ++i)
#pragma unroll
        for (int j = 0; j < 4; ++j)
#pragma unroll
            for (int e = 0; e < 4; ++e) c[i][j][e] = 0.0f;

    float4 ar[4], br[4];
#pragma unroll
    for (int p = 0; p < 4; ++p) {
        ar[p] = *reinterpret_cast<const float4*>(Aptr + (size_t)srow[p] * 1024 + scol[p]);
        br[p] = *reinterpret_cast<const float4*>(Bptr + (size_t)srow[p] * 1024 + scol[p]);
    }

    const int NT = 1024 / 32;
    for (int kt = 0; kt < NT; ++kt) {
#pragma unroll
        for (int p = 0; p < 4; ++p) {
            int r = srow[p], cp = scol[p] >> 1;
            unsigned h0, l0, h1, l1;
            split_pair(ar[p].x, ar[p].y, h0, l0);
            split_pair(ar[p].z, ar[p].w, h1, l1);
            As_hi[r][cp] = h0; As_hi[r][cp + 1] = h1;
            As_lo[r][cp] = l0; As_lo[r][cp + 1] = l1;
            split_pair(br[p].x, br[p].y, h0, l0);
            split_pair(br[p].z, br[p].w, h1, l1);
            Bs_hi[r][cp] = h0; Bs_hi[r][cp + 1] = h1;
            Bs_lo[r][cp] = l0; Bs_lo[r][cp + 1] = l1;
        }
        __syncthreads();

        if (kt + 1 < NT) {
            int k0 = (kt + 1) * 32;
#pragma unroll
            for (int p = 0; p < 4; ++p) {
                ar[p] = *reinterpret_cast<const float4*>(Aptr + (size_t)srow[p] * 1024 + k0 + scol[p]);
                br[p] = *reinterpret_cast<const float4*>(Bptr + (size_t)srow[p] * 1024 + k0 + scol[p]);
            }
        }

#pragma unroll
        for (int ks = 0; ks < 2; ++ks) {
            const int pb = ks * 8;
            unsigned ahi[4][4], alo[4][4];
#pragma unroll
            for (int mf = 0; mf < 4; ++mf) {
                int r = wm * 64 + mf * 16 + g;
                ahi[mf][0] = As_hi[r][pb + tig];
                ahi[mf][1] = As_hi[r + 8][pb + tig];
                ahi[mf][2] = As_hi[r][pb + tig + 4];
                ahi[mf][3] = As_hi[r + 8][pb + tig + 4];
                alo[mf][0] = As_lo[r][pb + tig];
                alo[mf][1] = As_lo[r + 8][pb + tig];
                alo[mf][2] = As_lo[r][pb + tig + 4];
                alo[mf][3] = As_lo[r + 8][pb + tig + 4];
            }
            unsigned bhi[4][2], blo[4][2];
#pragma unroll
            for (int nf = 0; nf < 4; ++nf) {
                int cn = wn * 32 + nf * 8 + g;
                bhi[nf][0] = Bs_hi[cn][pb + tig];
                bhi[nf][1] = Bs_hi[cn][pb + tig + 4];
                blo[nf][0] = Bs_lo[cn][pb + tig];
                blo[nf][1] = Bs_lo[cn][pb + tig + 4];
            }
#pragma unroll
            for (int mf = 0; mf < 4; ++mf)
#pragma unroll
                for (int nf = 0; nf < 4; ++nf) {
                    mma16816(c[mf][nf], ahi[mf], bhi[nf]);
                    mma16816(c[mf][nf], ahi[mf], blo[nf]);
                    mma16816(c[mf][nf], alo[mf], bhi[nf]);
                }
        }
        __syncthreads();
    }

#pragma unroll
    for (int mf = 0; mf < 4; ++mf) {
#pragma unroll
        for (int nf = 0; nf < 4; ++nf) {
            int m  = m0 + wm * 64 + mf * 16 + g;
            int n  = n0 + wn * 32 + nf * 8 + tig * 2;
            float v0 = c[mf][nf][0] + bias[n];
            float v1 = c[mf][nf][1] + bias[n + 1];
            float v2 = c[mf][nf][2] + bias[n];
            float v3 = c[mf][nf][3] + bias[n + 1];
            if (OUT_MODE == 0) {
                int b = m >> 11, s = m & 2047;
                int h = n >> 6, hd = n & 63;
                size_t base = (((size_t)(b * Hc + h)) * Sc + s) * HDc + hd;
                out[base]     = v0;
                out[base + 1] = v1;
                int m2 = m + 8;
                size_t base2 = (((size_t)(b * Hc + h)) * Sc + (m2 & 2047)) * HDc + hd;
                out[base2]     = v2;
                out[base2 + 1] = v3;
            } else {
                out[(size_t)m * Dc + n]       = v0;
                out[(size_t)m * Dc + n + 1]   = v1;
                out[(size_t)(m + 8) * Dc + n]     = v2;
                out[(size_t)(m + 8) * Dc + n + 1] = v3;
            }
        }
    }
}

// ---------------------------------------------------------------------------
// Tensor-core flash attention (causal), bf16x3 split precision.
// Grid: (16, B*H) with qt reversed. 256 threads = 8 warps, 16 q-rows/warp.
// Smem (dynamic u32): Qhi/Qlo [128][36], Khi/Klo [64][36], Vhi/Vlo [32][72]
// ---------------------------------------------------------------------------
#define ATTN2_SMEM_U32 (2*128*36 + 2*64*36 + 2*32*72)   // 18432 u32
#define ATTN2_SMEM_BYTES (ATTN2_SMEM_U32 * 4)           // 73728 B

__global__ __launch_bounds__(256, 2)
void attn_mma_kernel(const float* __restrict__ Qh,
                     const float* __restrict__ Kh,
                     const float* __restrict__ Vh,
                     float* __restrict__ ctx)
{
    extern __shared__ unsigned smu[];
    unsigned* Qhi = smu;                    // [128][36]
    unsigned* Qlo = Qhi + 128 * 36;
    unsigned* Khi = Qlo + 128 * 36;         // [64][36]
    unsigned* Klo = Khi + 64 * 36;
    unsigned* Vhi = Klo + 64 * 36;          // [32][72]  (key-pairs x hd)
    unsigned* Vlo = Vhi + 32 * 72;

    const int bh = blockIdx.y;
    const int qt = (int)(gridDim.x - 1 - blockIdx.x);   // heavy tiles first
    const int q0 = qt * 128;
    const int t    = threadIdx.x;
    const int lane = t & 31;
    const int w    = t >> 5;
    const int g    = lane >> 2;
    const int tig  = lane & 3;

    const float* Qb = Qh + (size_t)bh * Sc * HDc;
    const float* Kb = Kh + (size_t)bh * Sc * HDc;
    const float* Vb = Vh + (size_t)bh * Sc * HDc;

    // Load + split Q tile (128x64), pre-scaled by 1/sqrt(64)
#pragma unroll
    for (int p = 0; p < 8; ++p) {
        int slot = t + p * 256;
        int r  = slot >> 4;
        int c4 = (slot & 15) << 2;
        float4 f = *reinterpret_cast<const float4*>(Qb + (size_t)(q0 + r) * HDc + c4);
        f.x *= 0.125f; f.y *= 0.125f; f.z *= 0.125f; f.w *= 0.125f;
        unsigned h0, l0, h1, l1;
        split_pair(f.x, f.y, h0, l0);
        split_pair(f.z, f.w, h1, l1);
        int cp = c4 >> 1;
        *reinterpret_cast<uint2*>(&Qhi[r * 36 + cp]) = make_uint2(h0, h1);
        *reinterpret_cast<uint2*>(&Qlo[r * 36 + cp]) = make_uint2(l0, l1);
    }

    float m_i[2] = {-1e30f, -1e30f};
    float l_i[2] = {0.0f, 0.0f};
    float o[8][4];
#pragma unroll
    for (int f = 0; f < 8; ++f)
#pragma unroll
        for (int e = 0; e < 4; ++e) o[f][e] = 0.0f;

    const int row0 = q0 + w * 16 + g;       // thread's first q row (g), second = +8

    const int nkt = 2 * qt + 2;
    for (int kt = 0; kt < nkt; ++kt) {
        const int k0 = kt * 64;
        __syncthreads();   // previous iteration's consumers done (covers Q store too)

        // K tile 64x64: pairs along hd
#pragma unroll
        for (int p = 0; p < 4; ++p) {
            int slot = t + p * 256;
            int r  = slot >> 4;
            int c4 = (slot & 15) << 2;
            float4 f = *reinterpret_cast<const float4*>(Kb + (size_t)(k0 + r) * HDc + c4);
            unsigned h0, l0, h1, l1;
            split_pair(f.x, f.y, h0, l0);
            split_pair(f.z, f.w, h1, l1);
            int cp = c4 >> 1;
            *reinterpret_cast<uint2*>(&Khi[r * 36 + cp]) = make_uint2(h0, h1);
            *reinterpret_cast<uint2*>(&Klo[r * 36 + cp]) = make_uint2(l0, l1);
        }
        // V tile 64x64: pairs along key dim -> Vp[kp][hd]
#pragma unroll
        for (int p = 0; p < 2; ++p) {
            int slot = t + p * 256;
            int kp = slot >> 4;
            int c4 = (slot & 15) << 2;
            float4 f0 = *reinterpret_cast<const float4*>(Vb + (size_t)(k0 + 2 * kp) * HDc + c4);
            float4 f1 = *reinterpret_cast<const float4*>(Vb + (size_t)(k0 + 2 * kp + 1) * HDc + c4);
            unsigned h[4], l[4];
            split_pair(f0.x, f1.x, h[0], l[0]);
            split_pair(f0.y, f1.y, h[1], l[1]);
            split_pair(f0.z, f1.z, h[2], l[2]);
            split_pair(f0.w, f1.w, h[3], l[3]);
            *reinterpret_cast<uint4*>(&Vhi[kp * 72 + c4]) = make_uint4(h[0], h[1], h[2], h[3]);
            *reinterpret_cast<uint4*>(&Vlo[kp * 72 + c4]) = make_uint4(l[0], l[1], l[2], l[3]);
        }
        __syncthreads();

        // Warp fully above the diagonal for this k-tile -> nothing to do
        if (q0 + w * 16 + 15 < k0) continue;

        // ---- S = Q K^T (3-pass bf16x3) ----
        float s[8][4];
#pragma unroll
        for (int nf = 0; nf < 8; ++nf)
#pragma unroll
            for (int e = 0; e < 4; ++e) s[nf][e] = 0.0f;

#pragma unroll
        for (int ks = 0; ks < 4; ++ks) {
            const unsigned* q_hi = &Qhi[(w * 16 + g) * 36 + 8 * ks + tig];
            const unsigned* q_lo = &Qlo[(w * 16 + g) * 36 + 8 * ks + tig];
            unsigned aqh[4] = { q_hi[0], q_hi[8 * 36], q_hi[4], q_hi[8 * 36 + 4] };
            unsigned aql[4] = { q_lo[0], q_lo[8 * 36], q_lo[4], q_lo[8 * 36 + 4] };
#pragma unroll
            for (int nf = 0; nf < 8; ++nf) {
                int kr = 8 * nf + g;
                unsigned kh2[2] = { Khi[kr * 36 + 8 * ks + tig], Khi[kr * 36 + 8 * ks + tig + 4] };
                unsigned kl2[2] = { Klo[kr * 36 + 8 * ks + tig], Klo[kr * 36 + 8 * ks + tig + 4] };
                mma16816(s[nf], aqh, kh2);
                mma16816(s[nf], aqh, kl2);
                mma16816(s[nf], aql, kh2);
            }
        }

        // ---- causal mask (only when tile overlaps this warp's rows) ----
        if (k0 + 63 > q0 + w * 16) {
#pragma unroll
            for (int nf = 0; nf < 8; ++nf) {
                int key = k0 + 8 * nf + 2 * tig;
                if (key     > row0)     s[nf][0] = -1e30f;
                if (key + 1 > row0)     s[nf][1] = -1e30f;
                if (key     > row0 + 8) s[nf][2] = -1e30f;
                if (key + 1 > row0 + 8) s[nf][3] = -1e30f;
            }
        }

        // ---- online softmax ----
        float mx0 = -1e30f, mx1 = -1e30f;
#pragma unroll
        for (int nf = 0; nf < 8; ++nf) {
            mx0 = fmaxf(mx0, fmaxf(s[nf][0], s[nf][1]));
            mx1 = fmaxf(mx1, fmaxf(s[nf][2], s[nf][3]));
        }
        mx0 = fmaxf(mx0, __shfl_xor_sync(0xffffffffu, mx0, 1));
        mx0 = fmaxf(mx0, __shfl_xor_sync(0xffffffffu, mx0, 2));
        mx1 = fmaxf(mx1, __shfl_xor_sync(0xffffffffu, mx1, 1));
        mx1 = fmaxf(mx1, __shfl_xor_sync(0xffffffffu, mx1, 2));

        float mn0 = fmaxf(m_i[0], mx0);
        float mn1 = fmaxf(m_i[1], mx1);
        float cs0 = __expf(m_i[0] - mn0);
        float cs1 = __expf(m_i[1] - mn1);
        m_i[0] = mn0; m_i[1] = mn1;

        unsigned phi[8][2], plo[8][2];
        float sum0 = 0.0f, sum1 = 0.0f;
#pragma unroll
        for (int nf = 0; nf < 8; ++nf) {
            float p0 = __expf(s[nf][0] - mn0);
            float p1 = __expf(s[nf][1] - mn0);
            float p2 = __expf(s[nf][2] - mn1);
            float p3 = __expf(s[nf][3] - mn1);
            sum0 += p0 + p1;
            sum1 += p2 + p3;
            split_pair(p0, p1, phi[nf][0], plo[nf][0]);
            split_pair(p2, p3, phi[nf][1], plo[nf][1]);
        }
        sum0 += __shfl_xor_sync(0xffffffffu, sum0, 1);
        sum0 += __shfl_xor_sync(0xffffffffu, sum0, 2);
        sum1 += __shfl_xor_sync(0xffffffffu, sum1, 1);
        sum1 += __shfl_xor_sync(0xffffffffu, sum1, 2);
        l_i[0] = l_i[0] * cs0 + sum0;
        l_i[1] = l_i[1] * cs1 + sum1;

#pragma unroll
        for (int f = 0; f < 8; ++f) {
            o[f][0] *= cs0; o[f][1] *= cs0;
            o[f][2] *= cs1; o[f][3] *= cs1;
        }

        // ---- O += P V (3-pass) ----
#pragma unroll
        for (int ks = 0; ks < 4; ++ks) {
            unsigned pah[4] = { phi[2 * ks][0], phi[2 * ks][1], phi[2 * ks + 1][0], phi[2 * ks + 1][1] };
            unsigned pal[4] = { plo[2 * ks][0], plo[2 * ks][1], plo[2 * ks + 1][0], plo[2 * ks + 1][1] };
#pragma unroll
            for (int nf = 0; nf < 8; ++nf) {
                int kp = 8 * ks + tig;
                int n  = 8 * nf + g;
                unsigned vh2[2] = { Vhi[kp * 72 + n], Vhi[(kp + 4) * 72 + n] };
                unsigned vl2[2] = { Vlo[kp * 72 + n], Vlo[(kp + 4) * 72 + n] };
                mma16816(o[nf], pah, vh2);
                mma16816(o[nf], pah, vl2);
                mma16816(o[nf], pal, vh2);
            }
        }
    }

    // ---- epilogue: normalize and write ctx [B,S,D] ----
    const float inv0 = 1.0f / l_i[0];
    const float inv1 = 1.0f / l_i[1];
    const int b = bh >> 4;
    const int h = bh & 15;
    float* base0 = ctx + ((size_t)b * Sc + row0) * Dc + h * 64;
    float* base1 = ctx + ((size_t)b * Sc + row0 + 8) * Dc + h * 64;
#pragma unroll
    for (int nf = 0; nf < 8; ++nf) {
        int col = 8 * nf + 2 * tig;
        *reinterpret_cast<float2*>(base0 + col) = make_float2(o[nf][0] * inv0, o[nf][1] * inv0);
        *reinterpret_cast<float2*>(base1 + col) = make_float2(o[nf][2] * inv1, o[nf][3] * inv1);
    }
}

// ---------------------------------------------------------------------------
// Launch
// ---------------------------------------------------------------------------
extern "C" void kernel_launch(void* const* d_in, const int* in_sizes, int n_in,
                              void* d_out, int out_size)
{
    const float* q  = (const float*)d_in[0];
    const float* k  = (const float*)d_in[1];
    const float* v  = (const float*)d_in[2];
    const float* Wq = (const float*)d_in[4];
    const float* bq = (const float*)d_in[5];
    const float* Wk = (const float*)d_in[6];
    const float* bk = (const float*)d_in[7];
    const float* Wv = (const float*)d_in[8];
    const float* bv = (const float*)d_in[9];
    const float* Wo = (const float*)d_in[10];
    const float* bo = (const float*)d_in[11];
    float* out = (float*)d_out;

    void *pQ, *pK, *pV, *pC;
    cudaGetSymbolAddress(&pQ, g_Qh);
    cudaGetSymbolAddress(&pK, g_Kh);
    cudaGetSymbolAddress(&pV, g_Vh);
    cudaGetSymbolAddress(&pC, g_ctx);

    cudaFuncSetAttribute(attn_mma_kernel,
                         cudaFuncAttributeMaxDynamicSharedMemorySize, ATTN2_SMEM_BYTES);

    dim3 gg(Dc / 128, Mrows / 128);   // (8, 64)
    gemm_mma_kernel<0><<<gg, 256>>>(q, Wq, bq, (float*)pQ);
    gemm_mma_kernel<0><<<gg, 256>>>(k, Wk, bk, (float*)pK);
    gemm_mma_kernel<0><<<gg, 256>>>(v, Wv, bv, (float*)pV);

    dim3 ga(Sc / 128, Bc * Hc);       // (16, 64)
    attn_mma_kernel<<<ga, 256, ATTN2_SMEM_BYTES>>>((const float*)pQ, (const float*)pK,
                                                   (const float*)pV, (float*)pC);

    gemm_mma_kernel<1><<<gg, 256>>>((const float*)pC, Wo, bo, out);
}

// round 5
// speedup vs baseline: 1.8378x; 1.1287x over previous
#include <cuda_runtime.h>
#include <cuda_bf16.h>

// Problem constants
#define Bc 4
#define Sc 2048
#define Dc 1024
#define Hc 16
#define HDc 64
#define Mrows (Bc*Sc)   // 8192

// ---------------------------------------------------------------------------
// Device scratch: pre-split bf16 hi/lo (u32 = packed pair of bf16)
// ---------------------------------------------------------------------------
__device__ unsigned g_Wqhi[1024*512], g_Wqlo[1024*512];
__device__ unsigned g_Wkhi[1024*512], g_Wklo[1024*512];
__device__ unsigned g_Wvhi[1024*512], g_Wvlo[1024*512];
__device__ unsigned g_Wohi[1024*512], g_Wolo[1024*512];
__device__ unsigned g_Xqhi[(size_t)Mrows*512], g_Xqlo[(size_t)Mrows*512];
__device__ unsigned g_Xkhi[(size_t)Mrows*512], g_Xklo[(size_t)Mrows*512];
__device__ unsigned g_Xvhi[(size_t)Mrows*512], g_Xvlo[(size_t)Mrows*512];
// head layout [B,H,S,32] (u32 pairs along hd)
__device__ unsigned g_Qhi[(size_t)Mrows*512], g_Qlo[(size_t)Mrows*512];
__device__ unsigned g_Khi[(size_t)Mrows*512], g_Klo[(size_t)Mrows*512];
__device__ unsigned g_Vhi[(size_t)Mrows*512], g_Vlo[(size_t)Mrows*512];
// split ctx [B,S,512]
__device__ unsigned g_Chi[(size_t)Mrows*512], g_Clo[(size_t)Mrows*512];

// ---------------------------------------------------------------------------
// Helpers
// ---------------------------------------------------------------------------
__device__ __forceinline__ void split_pair(float x0, float x1,
                                           unsigned& hi, unsigned& lo)
{
    __nv_bfloat16 h0 = __float2bfloat16_rn(x0);
    __nv_bfloat16 h1 = __float2bfloat16_rn(x1);
    float r0 = x0 - __bfloat162float(h0);
    float r1 = x1 - __bfloat162float(h1);
    __nv_bfloat16 l0 = __float2bfloat16_rn(r0);
    __nv_bfloat16 l1 = __float2bfloat16_rn(r1);
    hi = ((unsigned)__bfloat16_as_ushort(h1) << 16) | __bfloat16_as_ushort(h0);
    lo = ((unsigned)__bfloat16_as_ushort(l1) << 16) | __bfloat16_as_ushort(l0);
}

__device__ __forceinline__ void mma16816(float c[4], const unsigned a[4],
                                         const unsigned b[2])
{
    asm volatile(
        "mma.sync.aligned.m16n8k16.row.col.f32.bf16.bf16.f32 "
        "{%0,%1,%2,%3}, {%4,%5,%6,%7}, {%8,%9}, {%0,%1,%2,%3};\n"
        : "+f"(c[0]), "+f"(c[1]), "+f"(c[2]), "+f"(c[3])
        : "r"(a[0]), "r"(a[1]), "r"(a[2]), "r"(a[3]),
          "r"(b[0]), "r"(b[1]));
}

__device__ __forceinline__ void cp16(void* smem, const void* g)
{
    unsigned sa = (unsigned)__cvta_generic_to_shared(smem);
    asm volatile("cp.async.ca.shared.global [%0], [%1], 16;\n"
                 :: "r"(sa), "l"(g) : "memory");
}

// ---------------------------------------------------------------------------
// Split converter: fp32 -> (hi,lo) packed pairs. One float4 (2 pairs)/thread.
// ---------------------------------------------------------------------------
__global__ __launch_bounds__(256)
void split_kernel(const float4* __restrict__ in,
                  uint2* __restrict__ hi, uint2* __restrict__ lo)
{
    int i = blockIdx.x * 256 + threadIdx.x;
    float4 f = in[i];
    unsigned h0, l0, h1, l1;
    split_pair(f.x, f.y, h0, l0);
    split_pair(f.z, f.w, h1, l1);
    hi[i] = make_uint2(h0, h1);
    lo[i] = make_uint2(l0, l1);
}

// ---------------------------------------------------------------------------
// Tensor-core GEMM on pre-split operands, cp.async double-buffered.
// out[m,n] = sum_k X[m,k]*W[n,k] + bias[n]   (M=8192, N=K=1024)
// OUT_MODE 0: scale then split, write head-layout u32 pairs
// OUT_MODE 1: plain fp32 [m,n]
// ---------------------------------------------------------------------------
#define KPAD 20
#define HALF_U32 (128*KPAD)
#define STAGE_U32 (4*HALF_U32)
#define GEMM_SMEM (2*STAGE_U32*4)   // 81920 bytes

template <int OUT_MODE>
__global__ __launch_bounds__(256)
void gemm_split_kernel(const unsigned* __restrict__ Xhi, const unsigned* __restrict__ Xlo,
                       const unsigned* __restrict__ Whi, const unsigned* __restrict__ Wlo,
                       const float* __restrict__ bias, float scale,
                       float* __restrict__ outf,
                       unsigned* __restrict__ ohi, unsigned* __restrict__ olo)
{
    extern __shared__ unsigned sg[];

    const int t    = threadIdx.x;
    const int lane = t & 31;
    const int wid  = t >> 5;
    const int wm   = wid >> 2;
    const int wn   = wid & 3;
    const int g    = lane >> 2;
    const int tig  = lane & 3;
    const int m0 = blockIdx.y * 128;
    const int n0 = blockIdx.x * 128;

    float c[4][4][4];
#pragma unroll
    for (int i = 0; i < 4; ++i)
#pragma unroll
        for (int j = 0; j < 4; ++j)
#pragma unroll
            for (int e = 0; e < 4; ++e) c[i][j][e] = 0.0f;

    auto issue = [&](int stage, int kt) {
        unsigned* base = sg + stage * STAGE_U32;
#pragma unroll
        for (int j = 0; j < 8; ++j) {
            int id   = t + j * 256;
            int half = id >> 9;
            int rem  = id & 511;
            int row  = rem >> 2;
            int c4   = (rem & 3) << 2;
            const unsigned* src;
            if      (half == 0) src = Xhi + (size_t)(m0 + row) * 512 + kt * 16 + c4;
            else if (half == 1) src = Xlo + (size_t)(m0 + row) * 512 + kt * 16 + c4;
            else if (half == 2) src = Whi + (size_t)(n0 + row) * 512 + kt * 16 + c4;
            else                src = Wlo + (size_t)(n0 + row) * 512 + kt * 16 + c4;
            cp16(base + half * HALF_U32 + row * KPAD + c4, src);
        }
        asm volatile("cp.async.commit_group;\n" ::: "memory");
    };

    issue(0, 0);

    const int NT = 32;
    for (int kt = 0; kt < NT; ++kt) {
        if (kt + 1 < NT) {
            issue((kt + 1) & 1, kt + 1);
            asm volatile("cp.async.wait_group 1;\n" ::: "memory");
        } else {
            asm volatile("cp.async.wait_group 0;\n" ::: "memory");
        }
        __syncthreads();

        const unsigned* Ah = sg + (kt & 1) * STAGE_U32;
        const unsigned* Al = Ah + HALF_U32;
        const unsigned* Bh = Ah + 2 * HALF_U32;
        const unsigned* Bl = Ah + 3 * HALF_U32;

#pragma unroll
        for (int ks = 0; ks < 2; ++ks) {
            const int pb = ks * 8;
            unsigned ahi[4][4], alo[4][4];
#pragma unroll
            for (int mf = 0; mf < 4; ++mf) {
                int r = wm * 64 + mf * 16 + g;
                ahi[mf][0] = Ah[r * KPAD + pb + tig];
                ahi[mf][1] = Ah[(r + 8) * KPAD + pb + tig];
                ahi[mf][2] = Ah[r * KPAD + pb + tig + 4];
                ahi[mf][3] = Ah[(r + 8) * KPAD + pb + tig + 4];
                alo[mf][0] = Al[r * KPAD + pb + tig];
                alo[mf][1] = Al[(r + 8) * KPAD + pb + tig];
                alo[mf][2] = Al[r * KPAD + pb + tig + 4];
                alo[mf][3] = Al[(r + 8) * KPAD + pb + tig + 4];
            }
            unsigned bhi[4][2], blo[4][2];
#pragma unroll
            for (int nf = 0; nf < 4; ++nf) {
                int cn = wn * 32 + nf * 8 + g;
                bhi[nf][0] = Bh[cn * KPAD + pb + tig];
                bhi[nf][1] = Bh[cn * KPAD + pb + tig + 4];
                blo[nf][0] = Bl[cn * KPAD + pb + tig];
                blo[nf][1] = Bl[cn * KPAD + pb + tig + 4];
            }
#pragma unroll
            for (int mf = 0; mf < 4; ++mf)
#pragma unroll
                for (int nf = 0; nf < 4; ++nf) {
                    mma16816(c[mf][nf], ahi[mf], bhi[nf]);
                    mma16816(c[mf][nf], ahi[mf], blo[nf]);
                    mma16816(c[mf][nf], alo[mf], bhi[nf]);
                }
        }
        __syncthreads();
    }

    // Epilogue
#pragma unroll
    for (int mf = 0; mf < 4; ++mf) {
#pragma unroll
        for (int nf = 0; nf < 4; ++nf) {
            int m = m0 + wm * 64 + mf * 16 + g;
            int n = n0 + wn * 32 + nf * 8 + tig * 2;
            float v0 = (c[mf][nf][0] + bias[n]) * scale;
            float v1 = (c[mf][nf][1] + bias[n + 1]) * scale;
            float v2 = (c[mf][nf][2] + bias[n]) * scale;
            float v3 = (c[mf][nf][3] + bias[n + 1]) * scale;
            if (OUT_MODE == 0) {
                int b = m >> 11, s = m & 2047;
                int h = n >> 6, hd = n & 63;
                unsigned hh, ll;
                split_pair(v0, v1, hh, ll);
                size_t p0 = (((size_t)(b * Hc + h)) * Sc + s) * 32 + (hd >> 1);
                ohi[p0] = hh; olo[p0] = ll;
                split_pair(v2, v3, hh, ll);
                size_t p1 = (((size_t)(b * Hc + h)) * Sc + (s + 8)) * 32 + (hd >> 1);
                ohi[p1] = hh; olo[p1] = ll;
            } else {
                outf[(size_t)m * Dc + n]           = v0;
                outf[(size_t)m * Dc + n + 1]       = v1;
                outf[(size_t)(m + 8) * Dc + n]     = v2;
                outf[(size_t)(m + 8) * Dc + n + 1] = v3;
            }
        }
    }
}

// ---------------------------------------------------------------------------
// Tensor-core flash attention on pre-split Q/K/V; writes split ctx.
// Grid: (16, B*H) qt reversed. 256 threads, 16 q-rows/warp.
// ---------------------------------------------------------------------------
#define ATTN2_SMEM_U32 (2*128*36 + 2*64*36 + 2*32*72)
#define ATTN2_SMEM_BYTES (ATTN2_SMEM_U32 * 4)   // 73728

__global__ __launch_bounds__(256, 2)
void attn_mma_kernel(const unsigned* __restrict__ Qhg, const unsigned* __restrict__ Qlg,
                     const unsigned* __restrict__ Khg, const unsigned* __restrict__ Klg,
                     const unsigned* __restrict__ Vhg, const unsigned* __restrict__ Vlg,
                     unsigned* __restrict__ Chi, unsigned* __restrict__ Clo)
{
    extern __shared__ unsigned smu[];
    unsigned* Qsh = smu;                    // [128][36]
    unsigned* Qsl = Qsh + 128 * 36;
    unsigned* Ksh = Qsl + 128 * 36;         // [64][36]
    unsigned* Ksl = Ksh + 64 * 36;
    unsigned* Vsh = Ksl + 64 * 36;          // [32][72]
    unsigned* Vsl = Vsh + 32 * 72;

    const int bh = blockIdx.y;
    const int qt = (int)(gridDim.x - 1 - blockIdx.x);
    const int q0 = qt * 128;
    const int t    = threadIdx.x;
    const int lane = t & 31;
    const int w    = t >> 5;
    const int g    = lane >> 2;
    const int tig  = lane & 3;

    const unsigned* Qbh = Qhg + (size_t)bh * Sc * 32;
    const unsigned* Qbl = Qlg + (size_t)bh * Sc * 32;
    const unsigned* Kbh = Khg + (size_t)bh * Sc * 32;
    const unsigned* Kbl = Klg + (size_t)bh * Sc * 32;
    const unsigned* Vbh = Vhg + (size_t)bh * Sc * 32;
    const unsigned* Vbl = Vlg + (size_t)bh * Sc * 32;

    // Q stage (pure copy, already scaled+split)
#pragma unroll
    for (int j = 0; j < 4; ++j) {
        int id = t + j * 256;
        int r = id >> 3, c4 = (id & 7) << 2;
        *reinterpret_cast<uint4*>(&Qsh[r * 36 + c4]) =
            *reinterpret_cast<const uint4*>(&Qbh[(size_t)(q0 + r) * 32 + c4]);
        *reinterpret_cast<uint4*>(&Qsl[r * 36 + c4]) =
            *reinterpret_cast<const uint4*>(&Qbl[(size_t)(q0 + r) * 32 + c4]);
    }

    float m_i[2] = {-1e30f, -1e30f};
    float l_i[2] = {0.0f, 0.0f};
    float o[8][4];
#pragma unroll
    for (int f = 0; f < 8; ++f)
#pragma unroll
        for (int e = 0; e < 4; ++e) o[f][e] = 0.0f;

    const int row0 = q0 + w * 16 + g;

    const int kp_v = t >> 3;      // 0..31 (key pair)
    const int dg_v = t & 7;       // 0..7  (4 u32 = 8 hd)

    const int nkt = 2 * qt + 2;
    for (int kt = 0; kt < nkt; ++kt) {
        const int k0 = kt * 64;
        __syncthreads();

        // K tile: pure copy
#pragma unroll
        for (int j = 0; j < 2; ++j) {
            int id = t + j * 256;
            int r = id >> 3, c4 = (id & 7) << 2;
            *reinterpret_cast<uint4*>(&Ksh[r * 36 + c4]) =
                *reinterpret_cast<const uint4*>(&Kbh[(size_t)(k0 + r) * 32 + c4]);
            *reinterpret_cast<uint4*>(&Ksl[r * 36 + c4]) =
                *reinterpret_cast<const uint4*>(&Kbl[(size_t)(k0 + r) * 32 + c4]);
        }
        // V tile: transpose hd-pairs -> key-pairs via byte_perm
        {
            uint4 a = *reinterpret_cast<const uint4*>(&Vbh[(size_t)(k0 + 2 * kp_v) * 32 + dg_v * 4]);
            uint4 b = *reinterpret_cast<const uint4*>(&Vbh[(size_t)(k0 + 2 * kp_v + 1) * 32 + dg_v * 4]);
            unsigned* dst = &Vsh[kp_v * 72 + dg_v * 8];
            dst[0] = __byte_perm(a.x, b.x, 0x5410); dst[1] = __byte_perm(a.x, b.x, 0x7632);
            dst[2] = __byte_perm(a.y, b.y, 0x5410); dst[3] = __byte_perm(a.y, b.y, 0x7632);
            dst[4] = __byte_perm(a.z, b.z, 0x5410); dst[5] = __byte_perm(a.z, b.z, 0x7632);
            dst[6] = __byte_perm(a.w, b.w, 0x5410); dst[7] = __byte_perm(a.w, b.w, 0x7632);
            a = *reinterpret_cast<const uint4*>(&Vbl[(size_t)(k0 + 2 * kp_v) * 32 + dg_v * 4]);
            b = *reinterpret_cast<const uint4*>(&Vbl[(size_t)(k0 + 2 * kp_v + 1) * 32 + dg_v * 4]);
            dst = &Vsl[kp_v * 72 + dg_v * 8];
            dst[0] = __byte_perm(a.x, b.x, 0x5410); dst[1] = __byte_perm(a.x, b.x, 0x7632);
            dst[2] = __byte_perm(a.y, b.y, 0x5410); dst[3] = __byte_perm(a.y, b.y, 0x7632);
            dst[4] = __byte_perm(a.z, b.z, 0x5410); dst[5] = __byte_perm(a.z, b.z, 0x7632);
            dst[6] = __byte_perm(a.w, b.w, 0x5410); dst[7] = __byte_perm(a.w, b.w, 0x7632);
        }
        __syncthreads();

        if (q0 + w * 16 + 15 < k0) continue;

        // ---- S = Q K^T ----
        float s[8][4];
#pragma unroll
        for (int nf = 0; nf < 8; ++nf)
#pragma unroll
            for (int e = 0; e < 4; ++e) s[nf][e] = 0.0f;

#pragma unroll
        for (int ks = 0; ks < 4; ++ks) {
            const unsigned* q_hi = &Qsh[(w * 16 + g) * 36 + 8 * ks + tig];
            const unsigned* q_lo = &Qsl[(w * 16 + g) * 36 + 8 * ks + tig];
            unsigned aqh[4] = { q_hi[0], q_hi[8 * 36], q_hi[4], q_hi[8 * 36 + 4] };
            unsigned aql[4] = { q_lo[0], q_lo[8 * 36], q_lo[4], q_lo[8 * 36 + 4] };
#pragma unroll
            for (int nf = 0; nf < 8; ++nf) {
                int kr = 8 * nf + g;
                unsigned kh2[2] = { Ksh[kr * 36 + 8 * ks + tig], Ksh[kr * 36 + 8 * ks + tig + 4] };
                unsigned kl2[2] = { Ksl[kr * 36 + 8 * ks + tig], Ksl[kr * 36 + 8 * ks + tig + 4] };
                mma16816(s[nf], aqh, kh2);
                mma16816(s[nf], aqh, kl2);
                mma16816(s[nf], aql, kh2);
            }
        }

        // ---- causal mask ----
        if (k0 + 63 > q0 + w * 16) {
#pragma unroll
            for (int nf = 0; nf < 8; ++nf) {
                int key = k0 + 8 * nf + 2 * tig;
                if (key     > row0)     s[nf][0] = -1e30f;
                if (key + 1 > row0)     s[nf][1] = -1e30f;
                if (key     > row0 + 8) s[nf][2] = -1e30f;
                if (key + 1 > row0 + 8) s[nf][3] = -1e30f;
            }
        }

        // ---- online softmax ----
        float mx0 = -1e30f, mx1 = -1e30f;
#pragma unroll
        for (int nf = 0; nf < 8; ++nf) {
            mx0 = fmaxf(mx0, fmaxf(s[nf][0], s[nf][1]));
            mx1 = fmaxf(mx1, fmaxf(s[nf][2], s[nf][3]));
        }
        mx0 = fmaxf(mx0, __shfl_xor_sync(0xffffffffu, mx0, 1));
        mx0 = fmaxf(mx0, __shfl_xor_sync(0xffffffffu, mx0, 2));
        mx1 = fmaxf(mx1, __shfl_xor_sync(0xffffffffu, mx1, 1));
        mx1 = fmaxf(mx1, __shfl_xor_sync(0xffffffffu, mx1, 2));

        float mn0 = fmaxf(m_i[0], mx0);
        float mn1 = fmaxf(m_i[1], mx1);
        float cs0 = __expf(m_i[0] - mn0);
        float cs1 = __expf(m_i[1] - mn1);
        m_i[0] = mn0; m_i[1] = mn1;

        unsigned phi[8][2], plo[8][2];
        float sum0 = 0.0f, sum1 = 0.0f;
#pragma unroll
        for (int nf = 0; nf < 8; ++nf) {
            float p0 = __expf(s[nf][0] - mn0);
            float p1 = __expf(s[nf][1] - mn0);
            float p2 = __expf(s[nf][2] - mn1);
            float p3 = __expf(s[nf][3] - mn1);
            sum0 += p0 + p1;
            sum1 += p2 + p3;
            split_pair(p0, p1, phi[nf][0], plo[nf][0]);
            split_pair(p2, p3, phi[nf][1], plo[nf][1]);
        }
        sum0 += __shfl_xor_sync(0xffffffffu, sum0, 1);
        sum0 += __shfl_xor_sync(0xffffffffu, sum0, 2);
        sum1 += __shfl_xor_sync(0xffffffffu, sum1, 1);
        sum1 += __shfl_xor_sync(0xffffffffu, sum1, 2);
        l_i[0] = l_i[0] * cs0 + sum0;
        l_i[1] = l_i[1] * cs1 + sum1;

#pragma unroll
        for (int f = 0; f < 8; ++f) {
            o[f][0] *= cs0; o[f][1] *= cs0;
            o[f][2] *= cs1; o[f][3] *= cs1;
        }

        // ---- O += P V ----
#pragma unroll
        for (int ks = 0; ks < 4; ++ks) {
            unsigned pah[4] = { phi[2 * ks][0], phi[2 * ks][1], phi[2 * ks + 1][0], phi[2 * ks + 1][1] };
            unsigned pal[4] = { plo[2 * ks][0], plo[2 * ks][1], plo[2 * ks + 1][0], plo[2 * ks + 1][1] };
#pragma unroll
            for (int nf = 0; nf < 8; ++nf) {
                int kp = 8 * ks + tig;
                int n  = 8 * nf + g;
                unsigned vh2[2] = { Vsh[kp * 72 + n], Vsh[(kp + 4) * 72 + n] };
                unsigned vl2[2] = { Vsl[kp * 72 + n], Vsl[(kp + 4) * 72 + n] };
                mma16816(o[nf], pah, vh2);
                mma16816(o[nf], pah, vl2);
                mma16816(o[nf], pal, vh2);
            }
        }
    }

    // ---- epilogue: normalize, split, write split ctx ----
    const float inv0 = 1.0f / l_i[0];
    const float inv1 = 1.0f / l_i[1];
    const int b = bh >> 4;
    const int h = bh & 15;
#pragma unroll
    for (int nf = 0; nf < 8; ++nf) {
        int col = 8 * nf + 2 * tig;
        unsigned hh, ll;
        split_pair(o[nf][0] * inv0, o[nf][1] * inv0, hh, ll);
        size_t p0 = ((size_t)b * Sc + row0) * 512 + h * 32 + (col >> 1);
        Chi[p0] = hh; Clo[p0] = ll;
        split_pair(o[nf][2] * inv1, o[nf][3] * inv1, hh, ll);
        size_t p1 = ((size_t)b * Sc + row0 + 8) * 512 + h * 32 + (col >> 1);
        Chi[p1] = hh; Clo[p1] = ll;
    }
}

// ---------------------------------------------------------------------------
// Launch
// ---------------------------------------------------------------------------
#define SYMADDR(p, s) do { void* _tmp; cudaGetSymbolAddress(&_tmp, s); p = (unsigned*)_tmp; } while (0)

extern "C" void kernel_launch(void* const* d_in, const int* in_sizes, int n_in,
                              void* d_out, int out_size)
{
    const float* q  = (const float*)d_in[0];
    const float* k  = (const float*)d_in[1];
    const float* v  = (const float*)d_in[2];
    const float* Wq = (const float*)d_in[4];
    const float* bq = (const float*)d_in[5];
    const float* Wk = (const float*)d_in[6];
    const float* bk = (const float*)d_in[7];
    const float* Wv = (const float*)d_in[8];
    const float* bv = (const float*)d_in[9];
    const float* Wo = (const float*)d_in[10];
    const float* bo = (const float*)d_in[11];
    float* out = (float*)d_out;

    unsigned *wqh,*wql,*wkh,*wkl,*wvh,*wvl,*woh,*wol;
    unsigned *xqh,*xql,*xkh,*xkl,*xvh,*xvl;
    unsigned *qh,*ql,*kh,*kl,*vh,*vl,*ch,*cl;
    SYMADDR(wqh, g_Wqhi); SYMADDR(wql, g_Wqlo);
    SYMADDR(wkh, g_Wkhi); SYMADDR(wkl, g_Wklo);
    SYMADDR(wvh, g_Wvhi); SYMADDR(wvl, g_Wvlo);
    SYMADDR(woh, g_Wohi); SYMADDR(wol, g_Wolo);
    SYMADDR(xqh, g_Xqhi); SYMADDR(xql, g_Xqlo);
    SYMADDR(xkh, g_Xkhi); SYMADDR(xkl, g_Xklo);
    SYMADDR(xvh, g_Xvhi); SYMADDR(xvl, g_Xvlo);
    SYMADDR(qh, g_Qhi);  SYMADDR(ql, g_Qlo);
    SYMADDR(kh, g_Khi);  SYMADDR(kl, g_Klo);
    SYMADDR(vh, g_Vhi);  SYMADDR(vl, g_Vlo);
    SYMADDR(ch, g_Chi);  SYMADDR(cl, g_Clo);

    cudaFuncSetAttribute(gemm_split_kernel<0>, cudaFuncAttributeMaxDynamicSharedMemorySize, GEMM_SMEM);
    cudaFuncSetAttribute(gemm_split_kernel<1>, cudaFuncAttributeMaxDynamicSharedMemorySize, GEMM_SMEM);
    cudaFuncSetAttribute(attn_mma_kernel, cudaFuncAttributeMaxDynamicSharedMemorySize, ATTN2_SMEM_BYTES);

    // Pre-split weights (1024x1024 -> 262144 float4) and inputs (8192x1024 -> 2M float4)
    split_kernel<<<1024, 256>>>((const float4*)Wq, (uint2*)wqh, (uint2*)wql);
    split_kernel<<<1024, 256>>>((const float4*)Wk, (uint2*)wkh, (uint2*)wkl);
    split_kernel<<<1024, 256>>>((const float4*)Wv, (uint2*)wvh, (uint2*)wvl);
    split_kernel<<<1024, 256>>>((const float4*)Wo, (uint2*)woh, (uint2*)wol);
    split_kernel<<<8192, 256>>>((const float4*)q, (uint2*)xqh, (uint2*)xql);
    split_kernel<<<8192, 256>>>((const float4*)k, (uint2*)xkh, (uint2*)xkl);
    split_kernel<<<8192, 256>>>((const float4*)v, (uint2*)xvh, (uint2*)xvl);

    dim3 gg(Dc / 128, Mrows / 128);   // (8, 64)
    gemm_split_kernel<0><<<gg, 256, GEMM_SMEM>>>(xqh, xql, wqh, wql, bq, 0.125f, nullptr, qh, ql);
    gemm_split_kernel<0><<<gg, 256, GEMM_SMEM>>>(xkh, xkl, wkh, wkl, bk, 1.0f,   nullptr, kh, kl);
    gemm_split_kernel<0><<<gg, 256, GEMM_SMEM>>>(xvh, xvl, wvh, wvl, bv, 1.0f,   nullptr, vh, vl);

    dim3 ga(Sc / 128, Bc * Hc);       // (16, 64)
    attn_mma_kernel<<<ga, 256, ATTN2_SMEM_BYTES>>>(qh, ql, kh, kl, vh, vl, ch, cl);

    gemm_split_kernel<1><<<gg, 256, GEMM_SMEM>>>(ch, cl, woh, wol, bo, 1.0f, out, nullptr, nullptr);
}

// round 6
// speedup vs baseline: 2.0066x; 1.0919x over previous
#include <cuda_runtime.h>
#include <cuda_bf16.h>

// Problem constants
#define Bc 4
#define Sc 2048
#define Dc 1024
#define Hc 16
#define HDc 64
#define Mrows (Bc*Sc)   // 8192

// ---------------------------------------------------------------------------
// Device scratch: pre-split bf16 hi/lo (u32 = packed pair of bf16)
// ---------------------------------------------------------------------------
__device__ unsigned g_Wqhi[1024*512], g_Wqlo[1024*512];
__device__ unsigned g_Wkhi[1024*512], g_Wklo[1024*512];
__device__ unsigned g_Wvhi[1024*512], g_Wvlo[1024*512];
__device__ unsigned g_Wohi[1024*512], g_Wolo[1024*512];
__device__ unsigned g_Xqhi[(size_t)Mrows*512], g_Xqlo[(size_t)Mrows*512];
__device__ unsigned g_Xkhi[(size_t)Mrows*512], g_Xklo[(size_t)Mrows*512];
__device__ unsigned g_Xvhi[(size_t)Mrows*512], g_Xvlo[(size_t)Mrows*512];
// head layout [B,H,S,32] (u32 pairs along hd)
__device__ unsigned g_Qhi[(size_t)Mrows*512], g_Qlo[(size_t)Mrows*512];
__device__ unsigned g_Khi[(size_t)Mrows*512], g_Klo[(size_t)Mrows*512];
__device__ unsigned g_Vhi[(size_t)Mrows*512], g_Vlo[(size_t)Mrows*512];
// split ctx [B,S,512]
__device__ unsigned g_Chi[(size_t)Mrows*512], g_Clo[(size_t)Mrows*512];

// ---------------------------------------------------------------------------
// Helpers
// ---------------------------------------------------------------------------
__device__ __forceinline__ void split_pair(float x0, float x1,
                                           unsigned& hi, unsigned& lo)
{
    __nv_bfloat16 h0 = __float2bfloat16_rn(x0);
    __nv_bfloat16 h1 = __float2bfloat16_rn(x1);
    float r0 = x0 - __bfloat162float(h0);
    float r1 = x1 - __bfloat162float(h1);
    __nv_bfloat16 l0 = __float2bfloat16_rn(r0);
    __nv_bfloat16 l1 = __float2bfloat16_rn(r1);
    hi = ((unsigned)__bfloat16_as_ushort(h1) << 16) | __bfloat16_as_ushort(h0);
    lo = ((unsigned)__bfloat16_as_ushort(l1) << 16) | __bfloat16_as_ushort(l0);
}

__device__ __forceinline__ void mma16816(float c[4], const unsigned a[4],
                                         const unsigned b[2])
{
    asm volatile(
        "mma.sync.aligned.m16n8k16.row.col.f32.bf16.bf16.f32 "
        "{%0,%1,%2,%3}, {%4,%5,%6,%7}, {%8,%9}, {%0,%1,%2,%3};\n"
        : "+f"(c[0]), "+f"(c[1]), "+f"(c[2]), "+f"(c[3])
        : "r"(a[0]), "r"(a[1]), "r"(a[2]), "r"(a[3]),
          "r"(b[0]), "r"(b[1]));
}

__device__ __forceinline__ void ldsm4(unsigned r[4], const unsigned* p)
{
    unsigned a = (unsigned)__cvta_generic_to_shared(p);
    asm volatile("ldmatrix.sync.aligned.m8n8.x4.shared.b16 {%0,%1,%2,%3}, [%4];\n"
                 : "=r"(r[0]), "=r"(r[1]), "=r"(r[2]), "=r"(r[3]) : "r"(a));
}

__device__ __forceinline__ void cp16(void* smem, const void* g)
{
    unsigned sa = (unsigned)__cvta_generic_to_shared(smem);
    asm volatile("cp.async.ca.shared.global [%0], [%1], 16;\n"
                 :: "r"(sa), "l"(g) : "memory");
}

// ---------------------------------------------------------------------------
// Split converter: fp32 -> (hi,lo) packed pairs.
// ---------------------------------------------------------------------------
__global__ __launch_bounds__(256)
void split_kernel(const float4* __restrict__ in,
                  uint2* __restrict__ hi, uint2* __restrict__ lo)
{
    int i = blockIdx.x * 256 + threadIdx.x;
    float4 f = in[i];
    unsigned h0, l0, h1, l1;
    split_pair(f.x, f.y, h0, l0);
    split_pair(f.z, f.w, h1, l1);
    hi[i] = make_uint2(h0, h1);
    lo[i] = make_uint2(l0, l1);
}

// ---------------------------------------------------------------------------
// Tensor-core GEMM on pre-split operands, cp.async double-buffered, ldmatrix.
// ---------------------------------------------------------------------------
#define KPAD 20
#define HALF_U32 (128*KPAD)
#define STAGE_U32 (4*HALF_U32)
#define GEMM_SMEM (2*STAGE_U32*4)   // 81920 bytes

template <int OUT_MODE>
__global__ __launch_bounds__(256)
void gemm_split_kernel(const unsigned* __restrict__ Xhi, const unsigned* __restrict__ Xlo,
                       const unsigned* __restrict__ Whi, const unsigned* __restrict__ Wlo,
                       const float* __restrict__ bias, float scale,
                       float* __restrict__ outf,
                       unsigned* __restrict__ ohi, unsigned* __restrict__ olo)
{
    extern __shared__ unsigned sg[];

    const int t    = threadIdx.x;
    const int lane = t & 31;
    const int wid  = t >> 5;
    const int wm   = wid >> 2;
    const int wn   = wid & 3;
    const int g    = lane >> 2;
    const int tig  = lane & 3;
    const int m0 = blockIdx.y * 128;
    const int n0 = blockIdx.x * 128;

    // ldmatrix per-lane offsets
    const int agrp  = lane >> 3;
    const int l7    = lane & 7;
    const int a_row = l7 + ((agrp & 1) << 3);
    const int a_col = (agrp >> 1) << 2;
    const int b_row = l7 + ((agrp >> 1) << 3);
    const int b_col = (agrp & 1) << 2;

    float c[4][4][4];
#pragma unroll
    for (int i = 0; i < 4; ++i)
#pragma unroll
        for (int j = 0; j < 4; ++j)
#pragma unroll
            for (int e = 0; e < 4; ++e) c[i][j][e] = 0.0f;

    auto issue = [&](int stage, int kt) {
        unsigned* base = sg + stage * STAGE_U32;
#pragma unroll
        for (int j = 0; j < 8; ++j) {
            int id   = t + j * 256;
            int half = id >> 9;
            int rem  = id & 511;
            int row  = rem >> 2;
            int c4   = (rem & 3) << 2;
            const unsigned* src;
            if      (half == 0) src = Xhi + (size_t)(m0 + row) * 512 + kt * 16 + c4;
            else if (half == 1) src = Xlo + (size_t)(m0 + row) * 512 + kt * 16 + c4;
            else if (half == 2) src = Whi + (size_t)(n0 + row) * 512 + kt * 16 + c4;
            else                src = Wlo + (size_t)(n0 + row) * 512 + kt * 16 + c4;
            cp16(base + half * HALF_U32 + row * KPAD + c4, src);
        }
        asm volatile("cp.async.commit_group;\n" ::: "memory");
    };

    issue(0, 0);

    const int NT = 32;
    for (int kt = 0; kt < NT; ++kt) {
        if (kt + 1 < NT) {
            issue((kt + 1) & 1, kt + 1);
            asm volatile("cp.async.wait_group 1;\n" ::: "memory");
        } else {
            asm volatile("cp.async.wait_group 0;\n" ::: "memory");
        }
        __syncthreads();

        const unsigned* Ah = sg + (kt & 1) * STAGE_U32;
        const unsigned* Al = Ah + HALF_U32;
        const unsigned* Bh = Ah + 2 * HALF_U32;
        const unsigned* Bl = Ah + 3 * HALF_U32;

#pragma unroll
        for (int ks = 0; ks < 2; ++ks) {
            const int pb = ks * 8;
            unsigned ahi[4][4], alo[4][4], bhi[2][4], blo[2][4];
#pragma unroll
            for (int mf = 0; mf < 4; ++mf) {
                const int r = (wm * 64 + mf * 16 + a_row) * KPAD + pb + a_col;
                ldsm4(ahi[mf], Ah + r);
                ldsm4(alo[mf], Al + r);
            }
#pragma unroll
            for (int np = 0; np < 2; ++np) {
                const int r = (wn * 32 + np * 16 + b_row) * KPAD + pb + b_col;
                ldsm4(bhi[np], Bh + r);
                ldsm4(blo[np], Bl + r);
            }
#pragma unroll
            for (int mf = 0; mf < 4; ++mf)
#pragma unroll
                for (int nf = 0; nf < 4; ++nf) {
                    const unsigned* bh2 = &bhi[nf >> 1][(nf & 1) * 2];
                    const unsigned* bl2 = &blo[nf >> 1][(nf & 1) * 2];
                    mma16816(c[mf][nf], ahi[mf], bh2);
                    mma16816(c[mf][nf], ahi[mf], bl2);
                    mma16816(c[mf][nf], alo[mf], bh2);
                }
        }
        __syncthreads();
    }

    // Epilogue
#pragma unroll
    for (int mf = 0; mf < 4; ++mf) {
#pragma unroll
        for (int nf = 0; nf < 4; ++nf) {
            int m = m0 + wm * 64 + mf * 16 + g;
            int n = n0 + wn * 32 + nf * 8 + tig * 2;
            float v0 = (c[mf][nf][0] + bias[n]) * scale;
            float v1 = (c[mf][nf][1] + bias[n + 1]) * scale;
            float v2 = (c[mf][nf][2] + bias[n]) * scale;
            float v3 = (c[mf][nf][3] + bias[n + 1]) * scale;
            if (OUT_MODE == 0) {
                int b = m >> 11, s = m & 2047;
                int h = n >> 6, hd = n & 63;
                unsigned hh, ll;
                split_pair(v0, v1, hh, ll);
                size_t p0 = (((size_t)(b * Hc + h)) * Sc + s) * 32 + (hd >> 1);
                ohi[p0] = hh; olo[p0] = ll;
                split_pair(v2, v3, hh, ll);
                size_t p1 = (((size_t)(b * Hc + h)) * Sc + (s + 8)) * 32 + (hd >> 1);
                ohi[p1] = hh; olo[p1] = ll;
            } else {
                outf[(size_t)m * Dc + n]           = v0;
                outf[(size_t)m * Dc + n + 1]       = v1;
                outf[(size_t)(m + 8) * Dc + n]     = v2;
                outf[(size_t)(m + 8) * Dc + n + 1] = v3;
            }
        }
    }
}

// ---------------------------------------------------------------------------
// Tensor-core flash attention on pre-split Q/K/V; ldmatrix fragments.
// Smem: Qhi/Qlo [128][36], Khi/Klo [64][36], Vhi/Vlo [64][36] (hd-major,
// u32 = key-pair, 16B chunk swizzled by (row>>3)).
// ---------------------------------------------------------------------------
#define ATTN2_SMEM_U32 (2*128*36 + 2*64*36 + 2*64*36)
#define ATTN2_SMEM_BYTES (ATTN2_SMEM_U32 * 4)   // 73728

__global__ __launch_bounds__(256, 2)
void attn_mma_kernel(const unsigned* __restrict__ Qhg, const unsigned* __restrict__ Qlg,
                     const unsigned* __restrict__ Khg, const unsigned* __restrict__ Klg,
                     const unsigned* __restrict__ Vhg, const unsigned* __restrict__ Vlg,
                     unsigned* __restrict__ Chi, unsigned* __restrict__ Clo)
{
    extern __shared__ unsigned smu[];
    unsigned* Qsh = smu;                    // [128][36]
    unsigned* Qsl = Qsh + 128 * 36;
    unsigned* Ksh = Qsl + 128 * 36;         // [64][36]
    unsigned* Ksl = Ksh + 64 * 36;
    unsigned* Vsh = Ksl + 64 * 36;          // [64][36] hd-major, swizzled
    unsigned* Vsl = Vsh + 64 * 36;

    const int bh = blockIdx.y;
    const int qt = (int)(gridDim.x - 1 - blockIdx.x);
    const int q0 = qt * 128;
    const int t    = threadIdx.x;
    const int lane = t & 31;
    const int w    = t >> 5;
    const int g    = lane >> 2;
    const int tig  = lane & 3;

    const int agrp  = lane >> 3;
    const int l7    = lane & 7;
    const int a_row = l7 + ((agrp & 1) << 3);
    const int a_col = (agrp >> 1) << 2;
    const int b_row = l7 + ((agrp >> 1) << 3);
    const int b_col = (agrp & 1) << 2;

    const unsigned* Qbh = Qhg + (size_t)bh * Sc * 32;
    const unsigned* Qbl = Qlg + (size_t)bh * Sc * 32;
    const unsigned* Kbh = Khg + (size_t)bh * Sc * 32;
    const unsigned* Kbl = Klg + (size_t)bh * Sc * 32;
    const unsigned* Vbh = Vhg + (size_t)bh * Sc * 32;
    const unsigned* Vbl = Vlg + (size_t)bh * Sc * 32;

    // Q stage (pure copy, already scaled+split)
#pragma unroll
    for (int j = 0; j < 4; ++j) {
        int id = t + j * 256;
        int r = id >> 3, c4 = (id & 7) << 2;
        *reinterpret_cast<uint4*>(&Qsh[r * 36 + c4]) =
            *reinterpret_cast<const uint4*>(&Qbh[(size_t)(q0 + r) * 32 + c4]);
        *reinterpret_cast<uint4*>(&Qsl[r * 36 + c4]) =
            *reinterpret_cast<const uint4*>(&Qbl[(size_t)(q0 + r) * 32 + c4]);
    }

    float m_i[2] = {-1e30f, -1e30f};
    float l_i[2] = {0.0f, 0.0f};
    float o[8][4];
#pragma unroll
    for (int f = 0; f < 8; ++f)
#pragma unroll
        for (int e = 0; e < 4; ++e) o[f][e] = 0.0f;

    const int row0 = q0 + w * 16 + g;

    const int kp_v = t >> 3;      // key pair 0..31
    const int dg_v = t & 7;       // hd group (8 hd rows)
    const int vcc  = kp_v >> 2;   // source 16B chunk
    const int vci  = kp_v & 3;

    const int nkt = 2 * qt + 2;
    for (int kt = 0; kt < nkt; ++kt) {
        const int k0 = kt * 64;
        __syncthreads();

        // K tile: pure copy
#pragma unroll
        for (int j = 0; j < 2; ++j) {
            int id = t + j * 256;
            int r = id >> 3, c4 = (id & 7) << 2;
            *reinterpret_cast<uint4*>(&Ksh[r * 36 + c4]) =
                *reinterpret_cast<const uint4*>(&Kbh[(size_t)(k0 + r) * 32 + c4]);
            *reinterpret_cast<uint4*>(&Ksl[r * 36 + c4]) =
                *reinterpret_cast<const uint4*>(&Kbl[(size_t)(k0 + r) * 32 + c4]);
        }
        // V tile: transpose to [hd][key-pair], chunk-swizzled by hd>>3 (= dg_v)
        {
            uint4 a = *reinterpret_cast<const uint4*>(&Vbh[(size_t)(k0 + 2 * kp_v) * 32 + dg_v * 4]);
            uint4 b = *reinterpret_cast<const uint4*>(&Vbh[(size_t)(k0 + 2 * kp_v + 1) * 32 + dg_v * 4]);
            const int swc = ((vcc ^ dg_v) << 2) + vci;
#pragma unroll
            for (int rep = 0; rep < 2; ++rep) {
                unsigned* dst = rep ? Vsl : Vsh;
                dst[(dg_v * 8 + 0) * 36 + swc] = __byte_perm(a.x, b.x, 0x5410);
                dst[(dg_v * 8 + 1) * 36 + swc] = __byte_perm(a.x, b.x, 0x7632);
                dst[(dg_v * 8 + 2) * 36 + swc] = __byte_perm(a.y, b.y, 0x5410);
                dst[(dg_v * 8 + 3) * 36 + swc] = __byte_perm(a.y, b.y, 0x7632);
                dst[(dg_v * 8 + 4) * 36 + swc] = __byte_perm(a.z, b.z, 0x5410);
                dst[(dg_v * 8 + 5) * 36 + swc] = __byte_perm(a.z, b.z, 0x7632);
                dst[(dg_v * 8 + 6) * 36 + swc] = __byte_perm(a.w, b.w, 0x5410);
                dst[(dg_v * 8 + 7) * 36 + swc] = __byte_perm(a.w, b.w, 0x7632);
                if (!rep) {
                    a = *reinterpret_cast<const uint4*>(&Vbl[(size_t)(k0 + 2 * kp_v) * 32 + dg_v * 4]);
                    b = *reinterpret_cast<const uint4*>(&Vbl[(size_t)(k0 + 2 * kp_v + 1) * 32 + dg_v * 4]);
                }
            }
        }
        __syncthreads();

        if (q0 + w * 16 + 15 < k0) continue;

        // ---- S = Q K^T ----
        float s[8][4];
#pragma unroll
        for (int nf = 0; nf < 8; ++nf)
#pragma unroll
            for (int e = 0; e < 4; ++e) s[nf][e] = 0.0f;

#pragma unroll
        for (int ks = 0; ks < 4; ++ks) {
            unsigned aqh[4], aql[4];
            const int qoff = (w * 16 + a_row) * 36 + 8 * ks + a_col;
            ldsm4(aqh, Qsh + qoff);
            ldsm4(aql, Qsl + qoff);
            unsigned khi[4][4], klo[4][4];
#pragma unroll
            for (int np = 0; np < 4; ++np) {
                const int koff = (np * 16 + b_row) * 36 + 8 * ks + b_col;
                ldsm4(khi[np], Ksh + koff);
                ldsm4(klo[np], Ksl + koff);
            }
#pragma unroll
            for (int nf = 0; nf < 8; ++nf) {
                const unsigned* kh2 = &khi[nf >> 1][(nf & 1) * 2];
                const unsigned* kl2 = &klo[nf >> 1][(nf & 1) * 2];
                mma16816(s[nf], aqh, kh2);
                mma16816(s[nf], aqh, kl2);
                mma16816(s[nf], aql, kh2);
            }
        }

        // ---- causal mask ----
        if (k0 + 63 > q0 + w * 16) {
#pragma unroll
            for (int nf = 0; nf < 8; ++nf) {
                int key = k0 + 8 * nf + 2 * tig;
                if (key     > row0)     s[nf][0] = -1e30f;
                if (key + 1 > row0)     s[nf][1] = -1e30f;
                if (key     > row0 + 8) s[nf][2] = -1e30f;
                if (key + 1 > row0 + 8) s[nf][3] = -1e30f;
            }
        }

        // ---- online softmax ----
        float mx0 = -1e30f, mx1 = -1e30f;
#pragma unroll
        for (int nf = 0; nf < 8; ++nf) {
            mx0 = fmaxf(mx0, fmaxf(s[nf][0], s[nf][1]));
            mx1 = fmaxf(mx1, fmaxf(s[nf][2], s[nf][3]));
        }
        mx0 = fmaxf(mx0, __shfl_xor_sync(0xffffffffu, mx0, 1));
        mx0 = fmaxf(mx0, __shfl_xor_sync(0xffffffffu, mx0, 2));
        mx1 = fmaxf(mx1, __shfl_xor_sync(0xffffffffu, mx1, 1));
        mx1 = fmaxf(mx1, __shfl_xor_sync(0xffffffffu, mx1, 2));

        float mn0 = fmaxf(m_i[0], mx0);
        float mn1 = fmaxf(m_i[1], mx1);
        float cs0 = __expf(m_i[0] - mn0);
        float cs1 = __expf(m_i[1] - mn1);
        m_i[0] = mn0; m_i[1] = mn1;

        unsigned phi[8][2], plo[8][2];
        float sum0 = 0.0f, sum1 = 0.0f;
#pragma unroll
        for (int nf = 0; nf < 8; ++nf) {
            float p0 = __expf(s[nf][0] - mn0);
            float p1 = __expf(s[nf][1] - mn0);
            float p2 = __expf(s[nf][2] - mn1);
            float p3 = __expf(s[nf][3] - mn1);
            sum0 += p0 + p1;
            sum1 += p2 + p3;
            split_pair(p0, p1, phi[nf][0], plo[nf][0]);
            split_pair(p2, p3, phi[nf][1], plo[nf][1]);
        }
        sum0 += __shfl_xor_sync(0xffffffffu, sum0, 1);
        sum0 += __shfl_xor_sync(0xffffffffu, sum0, 2);
        sum1 += __shfl_xor_sync(0xffffffffu, sum1, 1);
        sum1 += __shfl_xor_sync(0xffffffffu, sum1, 2);
        l_i[0] = l_i[0] * cs0 + sum0;
        l_i[1] = l_i[1] * cs1 + sum1;

#pragma unroll
        for (int f = 0; f < 8; ++f) {
            o[f][0] *= cs0; o[f][1] *= cs0;
            o[f][2] *= cs1; o[f][3] *= cs1;
        }

        // ---- O += P V ----
#pragma unroll
        for (int ks = 0; ks < 4; ++ks) {
            unsigned pah[4] = { phi[2 * ks][0], phi[2 * ks][1], phi[2 * ks + 1][0], phi[2 * ks + 1][1] };
            unsigned pal[4] = { plo[2 * ks][0], plo[2 * ks][1], plo[2 * ks + 1][0], plo[2 * ks + 1][1] };
            unsigned vhi[4][4], vlo[4][4];
#pragma unroll
            for (int np = 0; np < 4; ++np) {
                const int vrow = np * 16 + b_row;
                const int vchunk = (2 * ks + (agrp & 1)) ^ (vrow >> 3);
                const int voff = vrow * 36 + (vchunk << 2);
                ldsm4(vhi[np], Vsh + voff);
                ldsm4(vlo[np], Vsl + voff);
            }
#pragma unroll
            for (int nf = 0; nf < 8; ++nf) {
                const unsigned* vh2 = &vhi[nf >> 1][(nf & 1) * 2];
                const unsigned* vl2 = &vlo[nf >> 1][(nf & 1) * 2];
                mma16816(o[nf], pah, vh2);
                mma16816(o[nf], pah, vl2);
                mma16816(o[nf], pal, vh2);
            }
        }
    }

    // ---- epilogue: normalize, split, write split ctx ----
    const float inv0 = 1.0f / l_i[0];
    const float inv1 = 1.0f / l_i[1];
    const int b = bh >> 4;
    const int h = bh & 15;
#pragma unroll
    for (int nf = 0; nf < 8; ++nf) {
        int col = 8 * nf + 2 * tig;
        unsigned hh, ll;
        split_pair(o[nf][0] * inv0, o[nf][1] * inv0, hh, ll);
        size_t p0 = ((size_t)b * Sc + row0) * 512 + h * 32 + (col >> 1);
        Chi[p0] = hh; Clo[p0] = ll;
        split_pair(o[nf][2] * inv1, o[nf][3] * inv1, hh, ll);
        size_t p1 = ((size_t)b * Sc + row0 + 8) * 512 + h * 32 + (col >> 1);
        Chi[p1] = hh; Clo[p1] = ll;
    }
}

// ---------------------------------------------------------------------------
// Launch
// ---------------------------------------------------------------------------
#define SYMADDR(p, s) do { void* _tmp; cudaGetSymbolAddress(&_tmp, s); p = (unsigned*)_tmp; } while (0)

extern "C" void kernel_launch(void* const* d_in, const int* in_sizes, int n_in,
                              void* d_out, int out_size)
{
    const float* q  = (const float*)d_in[0];
    const float* k  = (const float*)d_in[1];
    const float* v  = (const float*)d_in[2];
    const float* Wq = (const float*)d_in[4];
    const float* bq = (const float*)d_in[5];
    const float* Wk = (const float*)d_in[6];
    const float* bk = (const float*)d_in[7];
    const float* Wv = (const float*)d_in[8];
    const float* bv = (const float*)d_in[9];
    const float* Wo = (const float*)d_in[10];
    const float* bo = (const float*)d_in[11];
    float* out = (float*)d_out;

    unsigned *wqh,*wql,*wkh,*wkl,*wvh,*wvl,*woh,*wol;
    unsigned *xqh,*xql,*xkh,*xkl,*xvh,*xvl;
    unsigned *qh,*ql,*kh,*kl,*vh,*vl,*ch,*cl;
    SYMADDR(wqh, g_Wqhi); SYMADDR(wql, g_Wqlo);
    SYMADDR(wkh, g_Wkhi); SYMADDR(wkl, g_Wklo);
    SYMADDR(wvh, g_Wvhi); SYMADDR(wvl, g_Wvlo);
    SYMADDR(woh, g_Wohi); SYMADDR(wol, g_Wolo);
    SYMADDR(xqh, g_Xqhi); SYMADDR(xql, g_Xqlo);
    SYMADDR(xkh, g_Xkhi); SYMADDR(xkl, g_Xklo);
    SYMADDR(xvh, g_Xvhi); SYMADDR(xvl, g_Xvlo);
    SYMADDR(qh, g_Qhi);  SYMADDR(ql, g_Qlo);
    SYMADDR(kh, g_Khi);  SYMADDR(kl, g_Klo);
    SYMADDR(vh, g_Vhi);  SYMADDR(vl, g_Vlo);
    SYMADDR(ch, g_Chi);  SYMADDR(cl, g_Clo);

    cudaFuncSetAttribute(gemm_split_kernel<0>, cudaFuncAttributeMaxDynamicSharedMemorySize, GEMM_SMEM);
    cudaFuncSetAttribute(gemm_split_kernel<1>, cudaFuncAttributeMaxDynamicSharedMemorySize, GEMM_SMEM);
    cudaFuncSetAttribute(attn_mma_kernel, cudaFuncAttributeMaxDynamicSharedMemorySize, ATTN2_SMEM_BYTES);

    // Pre-split weights and inputs
    split_kernel<<<1024, 256>>>((const float4*)Wq, (uint2*)wqh, (uint2*)wql);
    split_kernel<<<1024, 256>>>((const float4*)Wk, (uint2*)wkh, (uint2*)wkl);
    split_kernel<<<1024, 256>>>((const float4*)Wv, (uint2*)wvh, (uint2*)wvl);
    split_kernel<<<1024, 256>>>((const float4*)Wo, (uint2*)woh, (uint2*)wol);
    split_kernel<<<8192, 256>>>((const float4*)q, (uint2*)xqh, (uint2*)xql);
    split_kernel<<<8192, 256>>>((const float4*)k, (uint2*)xkh, (uint2*)xkl);
    split_kernel<<<8192, 256>>>((const float4*)v, (uint2*)xvh, (uint2*)xvl);

    dim3 gg(Dc / 128, Mrows / 128);   // (8, 64)
    gemm_split_kernel<0><<<gg, 256, GEMM_SMEM>>>(xqh, xql, wqh, wql, bq, 0.125f, nullptr, qh, ql);
    gemm_split_kernel<0><<<gg, 256, GEMM_SMEM>>>(xkh, xkl, wkh, wkl, bk, 1.0f,   nullptr, kh, kl);
    gemm_split_kernel<0><<<gg, 256, GEMM_SMEM>>>(xvh, xvl, wvh, wvl, bv, 1.0f,   nullptr, vh, vl);

    dim3 ga(Sc / 128, Bc * Hc);       // (16, 64)
    attn_mma_kernel<<<ga, 256, ATTN2_SMEM_BYTES>>>(qh, ql, kh, kl, vh, vl, ch, cl);

    gemm_split_kernel<1><<<gg, 256, GEMM_SMEM>>>(ch, cl, woh, wol, bo, 1.0f, out, nullptr, nullptr);
}

// round 7
// speedup vs baseline: 2.0157x; 1.0046x over previous
#include <cuda_runtime.h>
#include <cuda_bf16.h>

// Problem constants
#define Bc 4
#define Sc 2048
#define Dc 1024
#define Hc 16
#define HDc 64
#define Mrows (Bc*Sc)   // 8192

// ---------------------------------------------------------------------------
// Device scratch: pre-split bf16 hi/lo (u32 = packed pair of bf16)
// ---------------------------------------------------------------------------
__device__ unsigned g_Wqhi[1024*512], g_Wqlo[1024*512];
__device__ unsigned g_Wkhi[1024*512], g_Wklo[1024*512];
__device__ unsigned g_Wvhi[1024*512], g_Wvlo[1024*512];
__device__ unsigned g_Wohi[1024*512], g_Wolo[1024*512];
__device__ unsigned g_Xqhi[(size_t)Mrows*512], g_Xqlo[(size_t)Mrows*512];
__device__ unsigned g_Xkhi[(size_t)Mrows*512], g_Xklo[(size_t)Mrows*512];
__device__ unsigned g_Xvhi[(size_t)Mrows*512], g_Xvlo[(size_t)Mrows*512];
// Q/K head layout [B,H,S,32] (u32 pairs along hd)
__device__ unsigned g_Qhi[(size_t)Mrows*512], g_Qlo[(size_t)Mrows*512];
__device__ unsigned g_Khi[(size_t)Mrows*512], g_Klo[(size_t)Mrows*512];
// V transposed head layout [B,H,64(hd),1024(key-pair)]
__device__ unsigned g_Vthi[(size_t)Mrows*512], g_Vtlo[(size_t)Mrows*512];
// split ctx [B,S,512]
__device__ unsigned g_Chi[(size_t)Mrows*512], g_Clo[(size_t)Mrows*512];

// ---------------------------------------------------------------------------
// Helpers
// ---------------------------------------------------------------------------
__device__ __forceinline__ void split_pair(float x0, float x1,
                                           unsigned& hi, unsigned& lo)
{
    __nv_bfloat16 h0 = __float2bfloat16_rn(x0);
    __nv_bfloat16 h1 = __float2bfloat16_rn(x1);
    float r0 = x0 - __bfloat162float(h0);
    float r1 = x1 - __bfloat162float(h1);
    __nv_bfloat16 l0 = __float2bfloat16_rn(r0);
    __nv_bfloat16 l1 = __float2bfloat16_rn(r1);
    hi = ((unsigned)__bfloat16_as_ushort(h1) << 16) | __bfloat16_as_ushort(h0);
    lo = ((unsigned)__bfloat16_as_ushort(l1) << 16) | __bfloat16_as_ushort(l0);
}

__device__ __forceinline__ void mma16816(float c[4], const unsigned a[4],
                                         const unsigned b[2])
{
    asm volatile(
        "mma.sync.aligned.m16n8k16.row.col.f32.bf16.bf16.f32 "
        "{%0,%1,%2,%3}, {%4,%5,%6,%7}, {%8,%9}, {%0,%1,%2,%3};\n"
        : "+f"(c[0]), "+f"(c[1]), "+f"(c[2]), "+f"(c[3])
        : "r"(a[0]), "r"(a[1]), "r"(a[2]), "r"(a[3]),
          "r"(b[0]), "r"(b[1]));
}

__device__ __forceinline__ void ldsm4(unsigned r[4], const unsigned* p)
{
    unsigned a = (unsigned)__cvta_generic_to_shared(p);
    asm volatile("ldmatrix.sync.aligned.m8n8.x4.shared.b16 {%0,%1,%2,%3}, [%4];\n"
                 : "=r"(r[0]), "=r"(r[1]), "=r"(r[2]), "=r"(r[3]) : "r"(a));
}

__device__ __forceinline__ void cp16(void* smem, const void* g)
{
    unsigned sa = (unsigned)__cvta_generic_to_shared(smem);
    asm volatile("cp.async.ca.shared.global [%0], [%1], 16;\n"
                 :: "r"(sa), "l"(g) : "memory");
}

// ---------------------------------------------------------------------------
// Batched split converter: selects one of up to 4 matrices via blockIdx.y.
// ---------------------------------------------------------------------------
__global__ __launch_bounds__(256)
void split4_kernel(const float4* __restrict__ i0, const float4* __restrict__ i1,
                   const float4* __restrict__ i2, const float4* __restrict__ i3,
                   uint2* __restrict__ h0, uint2* __restrict__ h1,
                   uint2* __restrict__ h2, uint2* __restrict__ h3,
                   uint2* __restrict__ l0, uint2* __restrict__ l1,
                   uint2* __restrict__ l2, uint2* __restrict__ l3)
{
    const float4* in; uint2 *hi, *lo;
    switch (blockIdx.y) {
        case 0:  in = i0; hi = h0; lo = l0; break;
        case 1:  in = i1; hi = h1; lo = l1; break;
        case 2:  in = i2; hi = h2; lo = l2; break;
        default: in = i3; hi = h3; lo = l3; break;
    }
    int i = blockIdx.x * 256 + threadIdx.x;
    float4 f = in[i];
    unsigned a0, b0, a1, b1;
    split_pair(f.x, f.y, a0, b0);
    split_pair(f.z, f.w, a1, b1);
    hi[i] = make_uint2(a0, a1);
    lo[i] = make_uint2(b0, b1);
}

// ---------------------------------------------------------------------------
// Tensor-core GEMM on pre-split operands, cp.async double-buffered, ldmatrix.
// OUT_MODE 0: head layout [B,H,S,32] split pairs (for Q,K)
// OUT_MODE 1: plain fp32 [m,n] (final output)
// OUT_MODE 2: transposed head layout [B,H,64,1024] split pairs (for V)
// ---------------------------------------------------------------------------
#define KPAD 20
#define HALF_U32 (128*KPAD)
#define STAGE_U32 (4*HALF_U32)
#define GEMM_SMEM (2*STAGE_U32*4)   // 81920 bytes

template <int OUT_MODE>
__global__ __launch_bounds__(256, 2)
void gemm_split_kernel(const unsigned* __restrict__ Xhi, const unsigned* __restrict__ Xlo,
                       const unsigned* __restrict__ Whi, const unsigned* __restrict__ Wlo,
                       const float* __restrict__ bias, float scale,
                       float* __restrict__ outf,
                       unsigned* __restrict__ ohi, unsigned* __restrict__ olo)
{
    extern __shared__ unsigned sg[];

    const int t    = threadIdx.x;
    const int lane = t & 31;
    const int wid  = t >> 5;
    const int wm   = wid >> 2;
    const int wn   = wid & 3;
    const int g    = lane >> 2;
    const int tig  = lane & 3;
    const int m0 = blockIdx.y * 128;
    const int n0 = blockIdx.x * 128;

    const int agrp  = lane >> 3;
    const int l7    = lane & 7;
    const int a_row = l7 + ((agrp & 1) << 3);
    const int a_col = (agrp >> 1) << 2;
    const int b_row = l7 + ((agrp >> 1) << 3);
    const int b_col = (agrp & 1) << 2;

    float c[4][4][4];
#pragma unroll
    for (int i = 0; i < 4; ++i)
#pragma unroll
        for (int j = 0; j < 4; ++j)
#pragma unroll
            for (int e = 0; e < 4; ++e) c[i][j][e] = 0.0f;

    auto issue = [&](int stage, int kt) {
        unsigned* base = sg + stage * STAGE_U32;
#pragma unroll
        for (int j = 0; j < 8; ++j) {
            int id   = t + j * 256;
            int half = id >> 9;
            int rem  = id & 511;
            int row  = rem >> 2;
            int c4   = (rem & 3) << 2;
            const unsigned* src;
            if      (half == 0) src = Xhi + (size_t)(m0 + row) * 512 + kt * 16 + c4;
            else if (half == 1) src = Xlo + (size_t)(m0 + row) * 512 + kt * 16 + c4;
            else if (half == 2) src = Whi + (size_t)(n0 + row) * 512 + kt * 16 + c4;
            else                src = Wlo + (size_t)(n0 + row) * 512 + kt * 16 + c4;
            cp16(base + half * HALF_U32 + row * KPAD + c4, src);
        }
        asm volatile("cp.async.commit_group;\n" ::: "memory");
    };

    issue(0, 0);

    const int NT = 32;
    for (int kt = 0; kt < NT; ++kt) {
        if (kt + 1 < NT) {
            issue((kt + 1) & 1, kt + 1);
            asm volatile("cp.async.wait_group 1;\n" ::: "memory");
        } else {
            asm volatile("cp.async.wait_group 0;\n" ::: "memory");
        }
        __syncthreads();

        const unsigned* Ah = sg + (kt & 1) * STAGE_U32;
        const unsigned* Al = Ah + HALF_U32;
        const unsigned* Bh = Ah + 2 * HALF_U32;
        const unsigned* Bl = Ah + 3 * HALF_U32;

#pragma unroll
        for (int ks = 0; ks < 2; ++ks) {
            const int pb = ks * 8;
            unsigned ahi[4][4], alo[4][4], bhi[2][4], blo[2][4];
#pragma unroll
            for (int mf = 0; mf < 4; ++mf) {
                const int r = (wm * 64 + mf * 16 + a_row) * KPAD + pb + a_col;
                ldsm4(ahi[mf], Ah + r);
                ldsm4(alo[mf], Al + r);
            }
#pragma unroll
            for (int np = 0; np < 2; ++np) {
                const int r = (wn * 32 + np * 16 + b_row) * KPAD + pb + b_col;
                ldsm4(bhi[np], Bh + r);
                ldsm4(blo[np], Bl + r);
            }
#pragma unroll
            for (int mf = 0; mf < 4; ++mf)
#pragma unroll
                for (int nf = 0; nf < 4; ++nf) {
                    const unsigned* bh2 = &bhi[nf >> 1][(nf & 1) * 2];
                    const unsigned* bl2 = &blo[nf >> 1][(nf & 1) * 2];
                    mma16816(c[mf][nf], ahi[mf], bh2);
                    mma16816(c[mf][nf], ahi[mf], bl2);
                    mma16816(c[mf][nf], alo[mf], bh2);
                }
        }
        __syncthreads();
    }

    // Epilogue
#pragma unroll
    for (int mf = 0; mf < 4; ++mf) {
#pragma unroll
        for (int nf = 0; nf < 4; ++nf) {
            int m = m0 + wm * 64 + mf * 16 + g;
            int n = n0 + wn * 32 + nf * 8 + tig * 2;
            float v0 = (c[mf][nf][0] + bias[n]) * scale;
            float v1 = (c[mf][nf][1] + bias[n + 1]) * scale;
            float v2 = (c[mf][nf][2] + bias[n]) * scale;
            float v3 = (c[mf][nf][3] + bias[n + 1]) * scale;
            if (OUT_MODE == 0) {
                int b = m >> 11, s = m & 2047;
                int h = n >> 6, hd = n & 63;
                unsigned hh, ll;
                split_pair(v0, v1, hh, ll);
                size_t p0 = (((size_t)(b * Hc + h)) * Sc + s) * 32 + (hd >> 1);
                ohi[p0] = hh; olo[p0] = ll;
                split_pair(v2, v3, hh, ll);
                size_t p1 = (((size_t)(b * Hc + h)) * Sc + (s + 8)) * 32 + (hd >> 1);
                ohi[p1] = hh; olo[p1] = ll;
            } else if (OUT_MODE == 1) {
                outf[(size_t)m * Dc + n]           = v0;
                outf[(size_t)m * Dc + n + 1]       = v1;
                outf[(size_t)(m + 8) * Dc + n]     = v2;
                outf[(size_t)(m + 8) * Dc + n + 1] = v3;
            } else {
                // Transposed V: pair adjacent key rows via shfl with lane^4 (g^1)
                float p0 = __shfl_xor_sync(0xffffffffu, v0, 4);
                float p1 = __shfl_xor_sync(0xffffffffu, v1, 4);
                float p2 = __shfl_xor_sync(0xffffffffu, v2, 4);
                float p3 = __shfl_xor_sync(0xffffffffu, v3, 4);
                if (!(g & 1)) {
                    int b = m >> 11, s = m & 2047;
                    int h = n >> 6, hd = n & 63;
                    size_t rb = ((size_t)(b * Hc + h)) * 64;
                    int kp = s >> 1;
                    unsigned hh, ll;
                    split_pair(v0, p0, hh, ll);
                    ohi[(rb + hd) * 1024 + kp] = hh;     olo[(rb + hd) * 1024 + kp] = ll;
                    split_pair(v1, p1, hh, ll);
                    ohi[(rb + hd + 1) * 1024 + kp] = hh; olo[(rb + hd + 1) * 1024 + kp] = ll;
                    split_pair(v2, p2, hh, ll);
                    ohi[(rb + hd) * 1024 + kp + 4] = hh;     olo[(rb + hd) * 1024 + kp + 4] = ll;
                    split_pair(v3, p3, hh, ll);
                    ohi[(rb + hd + 1) * 1024 + kp + 4] = hh; olo[(rb + hd + 1) * 1024 + kp + 4] = ll;
                }
            }
        }
    }
}

// ---------------------------------------------------------------------------
// Tensor-core flash attention, cp.async double-buffered K/V (V pre-transposed).
// Smem: Qhi/Qlo [128][36]; 2 stages x (Khi,Klo,Vhi,Vlo)[64][36].
// ---------------------------------------------------------------------------
#define AT_STAGE_U32 (4*64*36)
#define ATTN3_SMEM_U32 (2*128*36 + 2*AT_STAGE_U32)
#define ATTN3_SMEM_BYTES (ATTN3_SMEM_U32 * 4)   // 110592

__global__ __launch_bounds__(256, 2)
void attn_mma_kernel(const unsigned* __restrict__ Qhg, const unsigned* __restrict__ Qlg,
                     const unsigned* __restrict__ Khg, const unsigned* __restrict__ Klg,
                     const unsigned* __restrict__ Vthg, const unsigned* __restrict__ Vtlg,
                     unsigned* __restrict__ Chi, unsigned* __restrict__ Clo)
{
    extern __shared__ unsigned smu[];
    unsigned* Qsh = smu;                    // [128][36]
    unsigned* Qsl = Qsh + 128 * 36;
    unsigned* stages = Qsl + 128 * 36;

    const int bh = blockIdx.y;
    const int qt = (int)(gridDim.x - 1 - blockIdx.x);
    const int q0 = qt * 128;
    const int t    = threadIdx.x;
    const int lane = t & 31;
    const int w    = t >> 5;
    const int g    = lane >> 2;
    const int tig  = lane & 3;

    const int agrp  = lane >> 3;
    const int l7    = lane & 7;
    const int a_row = l7 + ((agrp & 1) << 3);
    const int a_col = (agrp >> 1) << 2;
    const int b_row = l7 + ((agrp >> 1) << 3);
    const int b_col = (agrp & 1) << 2;

    const unsigned* Qbh = Qhg + (size_t)bh * Sc * 32;
    const unsigned* Qbl = Qlg + (size_t)bh * Sc * 32;
    const unsigned* Kbh = Khg + (size_t)bh * Sc * 32;
    const unsigned* Kbl = Klg + (size_t)bh * Sc * 32;
    const unsigned* Vbh = Vthg + (size_t)bh * 64 * 1024;
    const unsigned* Vbl = Vtlg + (size_t)bh * 64 * 1024;

    // Q stage (pure copy, already scaled+split)
#pragma unroll
    for (int j = 0; j < 4; ++j) {
        int id = t + j * 256;
        int r = id >> 3, c4 = (id & 7) << 2;
        *reinterpret_cast<uint4*>(&Qsh[r * 36 + c4]) =
            *reinterpret_cast<const uint4*>(&Qbh[(size_t)(q0 + r) * 32 + c4]);
        *reinterpret_cast<uint4*>(&Qsl[r * 36 + c4]) =
            *reinterpret_cast<const uint4*>(&Qbl[(size_t)(q0 + r) * 32 + c4]);
    }

    auto stage_fn = [&](int st, int kt) {
        unsigned* Kh = stages + st * AT_STAGE_U32;
        unsigned* Kl = Kh + 64 * 36;
        unsigned* Vh = Kl + 64 * 36;
        unsigned* Vl = Vh + 64 * 36;
        const int k0 = kt * 64, kp0 = kt * 32;
#pragma unroll
        for (int j = 0; j < 2; ++j) {
            int id = t + j * 256;
            int r = id >> 3, c4 = (id & 7) << 2;
            cp16(Kh + r * 36 + c4, Kbh + (size_t)(k0 + r) * 32 + c4);
            cp16(Kl + r * 36 + c4, Kbl + (size_t)(k0 + r) * 32 + c4);
            cp16(Vh + r * 36 + c4, Vbh + (size_t)r * 1024 + kp0 + c4);
            cp16(Vl + r * 36 + c4, Vbl + (size_t)r * 1024 + kp0 + c4);
        }
        asm volatile("cp.async.commit_group;\n" ::: "memory");
    };

    float m_i[2] = {-1e30f, -1e30f};
    float l_i[2] = {0.0f, 0.0f};
    float o[8][4];
#pragma unroll
    for (int f = 0; f < 8; ++f)
#pragma unroll
        for (int e = 0; e < 4; ++e) o[f][e] = 0.0f;

    const int row0 = q0 + w * 16 + g;
    const int nkt = 2 * qt + 2;

    stage_fn(0, 0);

    for (int kt = 0; kt < nkt; ++kt) {
        const int k0 = kt * 64;
        __syncthreads();   // buffer (kt+1)&1 free (its readers from kt-1 are done)
        if (kt + 1 < nkt) {
            stage_fn((kt + 1) & 1, kt + 1);
            asm volatile("cp.async.wait_group 1;\n" ::: "memory");
        } else {
            asm volatile("cp.async.wait_group 0;\n" ::: "memory");
        }
        __syncthreads();

        if (q0 + w * 16 + 15 < k0) continue;

        const unsigned* Ksh = stages + (kt & 1) * AT_STAGE_U32;
        const unsigned* Ksl = Ksh + 64 * 36;
        const unsigned* Vsh = Ksl + 64 * 36;
        const unsigned* Vsl = Vsh + 64 * 36;

        // ---- S = Q K^T ----
        float s[8][4];
#pragma unroll
        for (int nf = 0; nf < 8; ++nf)
#pragma unroll
            for (int e = 0; e < 4; ++e) s[nf][e] = 0.0f;

#pragma unroll
        for (int ks = 0; ks < 4; ++ks) {
            unsigned aqh[4], aql[4];
            const int qoff = (w * 16 + a_row) * 36 + 8 * ks + a_col;
            ldsm4(aqh, Qsh + qoff);
            ldsm4(aql, Qsl + qoff);
            unsigned khi[4][4], klo[4][4];
#pragma unroll
            for (int np = 0; np < 4; ++np) {
                const int koff = (np * 16 + b_row) * 36 + 8 * ks + b_col;
                ldsm4(khi[np], Ksh + koff);
                ldsm4(klo[np], Ksl + koff);
            }
#pragma unroll
            for (int nf = 0; nf < 8; ++nf) {
                const unsigned* kh2 = &khi[nf >> 1][(nf & 1) * 2];
                const unsigned* kl2 = &klo[nf >> 1][(nf & 1) * 2];
                mma16816(s[nf], aqh, kh2);
                mma16816(s[nf], aqh, kl2);
                mma16816(s[nf], aql, kh2);
            }
        }

        // ---- causal mask ----
        if (k0 + 63 > q0 + w * 16) {
#pragma unroll
            for (int nf = 0; nf < 8; ++nf) {
                int key = k0 + 8 * nf + 2 * tig;
                if (key     > row0)     s[nf][0] = -1e30f;
                if (key + 1 > row0)     s[nf][1] = -1e30f;
                if (key     > row0 + 8) s[nf][2] = -1e30f;
                if (key + 1 > row0 + 8) s[nf][3] = -1e30f;
            }
        }

        // ---- online softmax ----
        float mx0 = -1e30f, mx1 = -1e30f;
#pragma unroll
        for (int nf = 0; nf < 8; ++nf) {
            mx0 = fmaxf(mx0, fmaxf(s[nf][0], s[nf][1]));
            mx1 = fmaxf(mx1, fmaxf(s[nf][2], s[nf][3]));
        }
        mx0 = fmaxf(mx0, __shfl_xor_sync(0xffffffffu, mx0, 1));
        mx0 = fmaxf(mx0, __shfl_xor_sync(0xffffffffu, mx0, 2));
        mx1 = fmaxf(mx1, __shfl_xor_sync(0xffffffffu, mx1, 1));
        mx1 = fmaxf(mx1, __shfl_xor_sync(0xffffffffu, mx1, 2));

        float mn0 = fmaxf(m_i[0], mx0);
        float mn1 = fmaxf(m_i[1], mx1);
        float cs0 = __expf(m_i[0] - mn0);
        float cs1 = __expf(m_i[1] - mn1);
        m_i[0] = mn0; m_i[1] = mn1;

        unsigned phi[8][2], plo[8][2];
        float sum0 = 0.0f, sum1 = 0.0f;
#pragma unroll
        for (int nf = 0; nf < 8; ++nf) {
            float p0 = __expf(s[nf][0] - mn0);
            float p1 = __expf(s[nf][1] - mn0);
            float p2 = __expf(s[nf][2] - mn1);
            float p3 = __expf(s[nf][3] - mn1);
            sum0 += p0 + p1;
            sum1 += p2 + p3;
            split_pair(p0, p1, phi[nf][0], plo[nf][0]);
            split_pair(p2, p3, phi[nf][1], plo[nf][1]);
        }
        sum0 += __shfl_xor_sync(0xffffffffu, sum0, 1);
        sum0 += __shfl_xor_sync(0xffffffffu, sum0, 2);
        sum1 += __shfl_xor_sync(0xffffffffu, sum1, 1);
        sum1 += __shfl_xor_sync(0xffffffffu, sum1, 2);
        l_i[0] = l_i[0] * cs0 + sum0;
        l_i[1] = l_i[1] * cs1 + sum1;

#pragma unroll
        for (int f = 0; f < 8; ++f) {
            o[f][0] *= cs0; o[f][1] *= cs0;
            o[f][2] *= cs1; o[f][3] *= cs1;
        }

        // ---- O += P V ----
#pragma unroll
        for (int ks = 0; ks < 4; ++ks) {
            unsigned pah[4] = { phi[2 * ks][0], phi[2 * ks][1], phi[2 * ks + 1][0], phi[2 * ks + 1][1] };
            unsigned pal[4] = { plo[2 * ks][0], plo[2 * ks][1], plo[2 * ks + 1][0], plo[2 * ks + 1][1] };
            unsigned vhi[4][4], vlo[4][4];
#pragma unroll
            for (int np = 0; np < 4; ++np) {
                const int voff = (np * 16 + b_row) * 36 + 8 * ks + b_col;
                ldsm4(vhi[np], Vsh + voff);
                ldsm4(vlo[np], Vsl + voff);
            }
#pragma unroll
            for (int nf = 0; nf < 8; ++nf) {
                const unsigned* vh2 = &vhi[nf >> 1][(nf & 1) * 2];
                const unsigned* vl2 = &vlo[nf >> 1][(nf & 1) * 2];
                mma16816(o[nf], pah, vh2);
                mma16816(o[nf], pah, vl2);
                mma16816(o[nf], pal, vh2);
            }
        }
    }

    // ---- epilogue: normalize, split, write split ctx ----
    const float inv0 = 1.0f / l_i[0];
    const float inv1 = 1.0f / l_i[1];
    const int b = bh >> 4;
    const int h = bh & 15;
#pragma unroll
    for (int nf = 0; nf < 8; ++nf) {
        int col = 8 * nf + 2 * tig;
        unsigned hh, ll;
        split_pair(o[nf][0] * inv0, o[nf][1] * inv0, hh, ll);
        size_t p0 = ((size_t)b * Sc + row0) * 512 + h * 32 + (col >> 1);
        Chi[p0] = hh; Clo[p0] = ll;
        split_pair(o[nf][2] * inv1, o[nf][3] * inv1, hh, ll);
        size_t p1 = ((size_t)b * Sc + row0 + 8) * 512 + h * 32 + (col >> 1);
        Chi[p1] = hh; Clo[p1] = ll;
    }
}

// ---------------------------------------------------------------------------
// Launch
// ---------------------------------------------------------------------------
#define SYMADDR(p, s) do { void* _tmp; cudaGetSymbolAddress(&_tmp, s); p = (unsigned*)_tmp; } while (0)

extern "C" void kernel_launch(void* const* d_in, const int* in_sizes, int n_in,
                              void* d_out, int out_size)
{
    const float* q  = (const float*)d_in[0];
    const float* k  = (const float*)d_in[1];
    const float* v  = (const float*)d_in[2];
    const float* Wq = (const float*)d_in[4];
    const float* bq = (const float*)d_in[5];
    const float* Wk = (const float*)d_in[6];
    const float* bk = (const float*)d_in[7];
    const float* Wv = (const float*)d_in[8];
    const float* bv = (const float*)d_in[9];
    const float* Wo = (const float*)d_in[10];
    const float* bo = (const float*)d_in[11];
    float* out = (float*)d_out;

    unsigned *wqh,*wql,*wkh,*wkl,*wvh,*wvl,*woh,*wol;
    unsigned *xqh,*xql,*xkh,*xkl,*xvh,*xvl;
    unsigned *qh,*ql,*kh,*kl,*vth,*vtl,*ch,*cl;
    SYMADDR(wqh, g_Wqhi); SYMADDR(wql, g_Wqlo);
    SYMADDR(wkh, g_Wkhi); SYMADDR(wkl, g_Wklo);
    SYMADDR(wvh, g_Wvhi); SYMADDR(wvl, g_Wvlo);
    SYMADDR(woh, g_Wohi); SYMADDR(wol, g_Wolo);
    SYMADDR(xqh, g_Xqhi); SYMADDR(xql, g_Xqlo);
    SYMADDR(xkh, g_Xkhi); SYMADDR(xkl, g_Xklo);
    SYMADDR(xvh, g_Xvhi); SYMADDR(xvl, g_Xvlo);
    SYMADDR(qh, g_Qhi);   SYMADDR(ql, g_Qlo);
    SYMADDR(kh, g_Khi);   SYMADDR(kl, g_Klo);
    SYMADDR(vth, g_Vthi); SYMADDR(vtl, g_Vtlo);
    SYMADDR(ch, g_Chi);   SYMADDR(cl, g_Clo);

    cudaFuncSetAttribute(gemm_split_kernel<0>, cudaFuncAttributeMaxDynamicSharedMemorySize, GEMM_SMEM);
    cudaFuncSetAttribute(gemm_split_kernel<1>, cudaFuncAttributeMaxDynamicSharedMemorySize, GEMM_SMEM);
    cudaFuncSetAttribute(gemm_split_kernel<2>, cudaFuncAttributeMaxDynamicSharedMemorySize, GEMM_SMEM);
    cudaFuncSetAttribute(attn_mma_kernel, cudaFuncAttributeMaxDynamicSharedMemorySize, ATTN3_SMEM_BYTES);

    // Pre-split weights (4 matrices, one launch) and inputs (3 matrices, one launch)
    split4_kernel<<<dim3(1024, 4), 256>>>(
        (const float4*)Wq, (const float4*)Wk, (const float4*)Wv, (const float4*)Wo,
        (uint2*)wqh, (uint2*)wkh, (uint2*)wvh, (uint2*)woh,
        (uint2*)wql, (uint2*)wkl, (uint2*)wvl, (uint2*)wol);
    split4_kernel<<<dim3(8192, 3), 256>>>(
        (const float4*)q, (const float4*)k, (const float4*)v, (const float4*)v,
        (uint2*)xqh, (uint2*)xkh, (uint2*)xvh, (uint2*)xvh,
        (uint2*)xql, (uint2*)xkl, (uint2*)xvl, (uint2*)xvl);

    dim3 gg(Dc / 128, Mrows / 128);   // (8, 64)
    gemm_split_kernel<0><<<gg, 256, GEMM_SMEM>>>(xqh, xql, wqh, wql, bq, 0.125f, nullptr, qh, ql);
    gemm_split_kernel<0><<<gg, 256, GEMM_SMEM>>>(xkh, xkl, wkh, wkl, bk, 1.0f,   nullptr, kh, kl);
    gemm_split_kernel<2><<<gg, 256, GEMM_SMEM>>>(xvh, xvl, wvh, wvl, bv, 1.0f,   nullptr, vth, vtl);

    dim3 ga(Sc / 128, Bc * Hc);       // (16, 64)
    attn_mma_kernel<<<ga, 256, ATTN3_SMEM_BYTES>>>(qh, ql, kh, kl, vth, vtl, ch, cl);

    gemm_split_kernel<1><<<gg, 256, GEMM_SMEM>>>(ch, cl, woh, wol, bo, 1.0f, out, nullptr, nullptr);
}

// round 9
// speedup vs baseline: 2.1858x; 1.0843x over previous
#include <cuda_runtime.h>
#include <cuda_bf16.h>

// Problem constants
#define Bc 4
#define Sc 2048
#define Dc 1024
#define Hc 16
#define Mrows (Bc*Sc)   // 8192

#define SCALE_Q 0.18033688010819965f   // 0.125 * log2(e)

// ---------------------------------------------------------------------------
// Device scratch: pre-split bf16 hi/lo (u32 = packed pair of bf16)
// ---------------------------------------------------------------------------
__device__ unsigned g_Wqhi[1024*512], g_Wqlo[1024*512];
__device__ unsigned g_Wkhi[1024*512], g_Wklo[1024*512];
__device__ unsigned g_Wvhi[1024*512], g_Wvlo[1024*512];
__device__ unsigned g_Wohi[1024*512], g_Wolo[1024*512];
__device__ unsigned g_Xqhi[(size_t)Mrows*512], g_Xqlo[(size_t)Mrows*512];
__device__ unsigned g_Xkhi[(size_t)Mrows*512], g_Xklo[(size_t)Mrows*512];
__device__ unsigned g_Xvhi[(size_t)Mrows*512], g_Xvlo[(size_t)Mrows*512];
// Q/K head layout [B,H,S,32]
__device__ unsigned g_Qhi[(size_t)Mrows*512], g_Qlo[(size_t)Mrows*512];
__device__ unsigned g_Khi[(size_t)Mrows*512], g_Klo[(size_t)Mrows*512];
// V transposed head layout [B,H,64(hd),1024(key-pair)]
__device__ unsigned g_Vthi[(size_t)Mrows*512], g_Vtlo[(size_t)Mrows*512];
// split ctx [B,S,512]
__device__ unsigned g_Chi[(size_t)Mrows*512], g_Clo[(size_t)Mrows*512];

// ---------------------------------------------------------------------------
// Helpers
// ---------------------------------------------------------------------------
__device__ __forceinline__ void split_pair(float x0, float x1,
                                           unsigned& hi, unsigned& lo)
{
    __nv_bfloat16 h0 = __float2bfloat16_rn(x0);
    __nv_bfloat16 h1 = __float2bfloat16_rn(x1);
    float r0 = x0 - __bfloat162float(h0);
    float r1 = x1 - __bfloat162float(h1);
    __nv_bfloat16 l0 = __float2bfloat16_rn(r0);
    __nv_bfloat16 l1 = __float2bfloat16_rn(r1);
    hi = ((unsigned)__bfloat16_as_ushort(h1) << 16) | __bfloat16_as_ushort(h0);
    lo = ((unsigned)__bfloat16_as_ushort(l1) << 16) | __bfloat16_as_ushort(l0);
}

__device__ __forceinline__ void mma16816(float c[4], const unsigned a[4],
                                         const unsigned b[2])
{
    asm volatile(
        "mma.sync.aligned.m16n8k16.row.col.f32.bf16.bf16.f32 "
        "{%0,%1,%2,%3}, {%4,%5,%6,%7}, {%8,%9}, {%0,%1,%2,%3};\n"
        : "+f"(c[0]), "+f"(c[1]), "+f"(c[2]), "+f"(c[3])
        : "r"(a[0]), "r"(a[1]), "r"(a[2]), "r"(a[3]),
          "r"(b[0]), "r"(b[1]));
}

__device__ __forceinline__ void ldsm4(unsigned r[4], const unsigned* p)
{
    unsigned a = (unsigned)__cvta_generic_to_shared(p);
    asm volatile("ldmatrix.sync.aligned.m8n8.x4.shared.b16 {%0,%1,%2,%3}, [%4];\n"
                 : "=r"(r[0]), "=r"(r[1]), "=r"(r[2]), "=r"(r[3]) : "r"(a));
}

__device__ __forceinline__ void cp16(void* smem, const void* g)
{
    unsigned sa = (unsigned)__cvta_generic_to_shared(smem);
    asm volatile("cp.async.cg.shared.global [%0], [%1], 16;\n"
                 :: "r"(sa), "l"(g) : "memory");
}

// ---------------------------------------------------------------------------
// Batched split converter
// ---------------------------------------------------------------------------
__global__ __launch_bounds__(256)
void split4_kernel(const float4* __restrict__ i0, const float4* __restrict__ i1,
                   const float4* __restrict__ i2, const float4* __restrict__ i3,
                   uint2* __restrict__ h0, uint2* __restrict__ h1,
                   uint2* __restrict__ h2, uint2* __restrict__ h3,
                   uint2* __restrict__ l0, uint2* __restrict__ l1,
                   uint2* __restrict__ l2, uint2* __restrict__ l3)
{
    const float4* in; uint2 *hi, *lo;
    switch (blockIdx.y) {
        case 0:  in = i0; hi = h0; lo = l0; break;
        case 1:  in = i1; hi = h1; lo = l1; break;
        case 2:  in = i2; hi = h2; lo = l2; break;
        default: in = i3; hi = h3; lo = l3; break;
    }
    int i = blockIdx.x * 256 + threadIdx.x;
    float4 f = in[i];
    unsigned a0, b0, a1, b1;
    split_pair(f.x, f.y, a0, b0);
    split_pair(f.z, f.w, a1, b1);
    hi[i] = make_uint2(a0, a1);
    lo[i] = make_uint2(b0, b1);
}

// ---------------------------------------------------------------------------
// Shared GEMM mainloop: c[4][4][4] += X[m0:,kt] W[n0:,kt]^T over K=1024.
// cp.async double-buffered, ldmatrix fragments, pass-major bf16x3 MMA order.
// ---------------------------------------------------------------------------
#define KPAD 20
#define HALF_U32 (128*KPAD)
#define STAGE_U32 (4*HALF_U32)
#define GEMM_SMEM (2*STAGE_U32*4)   // 81920 bytes

__device__ __forceinline__ void gemm_mainloop(
    const unsigned* __restrict__ Xhi, const unsigned* __restrict__ Xlo,
    const unsigned* __restrict__ Whi, const unsigned* __restrict__ Wlo,
    int m0, int n0, unsigned* sg, float c[4][4][4])
{
    const int t    = threadIdx.x;
    const int lane = t & 31;
    const int wid  = t >> 5;
    const int wm   = wid >> 2;
    const int wn   = wid & 3;

    const int agrp  = lane >> 3;
    const int l7    = lane & 7;
    const int a_row = l7 + ((agrp & 1) << 3);
    const int a_col = (agrp >> 1) << 2;
    const int b_row = l7 + ((agrp >> 1) << 3);
    const int b_col = (agrp & 1) << 2;

    auto issue = [&](int stage, int kt) {
        unsigned* base = sg + stage * STAGE_U32;
#pragma unroll
        for (int j = 0; j < 8; ++j) {
            int id   = t + j * 256;
            int half = id >> 9;
            int rem  = id & 511;
            int row  = rem >> 2;
            int c4   = (rem & 3) << 2;
            const unsigned* src;
            if      (half == 0) src = Xhi + (size_t)(m0 + row) * 512 + kt * 16 + c4;
            else if (half == 1) src = Xlo + (size_t)(m0 + row) * 512 + kt * 16 + c4;
            else if (half == 2) src = Whi + (size_t)(n0 + row) * 512 + kt * 16 + c4;
            else                src = Wlo + (size_t)(n0 + row) * 512 + kt * 16 + c4;
            cp16(base + half * HALF_U32 + row * KPAD + c4, src);
        }
        asm volatile("cp.async.commit_group;\n" ::: "memory");
    };

    issue(0, 0);

    const int NT = 32;
    for (int kt = 0; kt < NT; ++kt) {
        if (kt + 1 < NT) {
            issue((kt + 1) & 1, kt + 1);
            asm volatile("cp.async.wait_group 1;\n" ::: "memory");
        } else {
            asm volatile("cp.async.wait_group 0;\n" ::: "memory");
        }
        __syncthreads();

        const unsigned* Ah = sg + (kt & 1) * STAGE_U32;
        const unsigned* Al = Ah + HALF_U32;
        const unsigned* Bh = Ah + 2 * HALF_U32;
        const unsigned* Bl = Ah + 3 * HALF_U32;

#pragma unroll
        for (int ks = 0; ks < 2; ++ks) {
            const int pb = ks * 8;
            unsigned ahi[4][4], alo[4][4], bhi[2][4], blo[2][4];
#pragma unroll
            for (int mf = 0; mf < 4; ++mf) {
                const int r = (wm * 64 + mf * 16 + a_row) * KPAD + pb + a_col;
                ldsm4(ahi[mf], Ah + r);
                ldsm4(alo[mf], Al + r);
            }
#pragma unroll
            for (int np = 0; np < 2; ++np) {
                const int r = (wn * 32 + np * 16 + b_row) * KPAD + pb + b_col;
                ldsm4(bhi[np], Bh + r);
                ldsm4(blo[np], Bl + r);
            }
            // Pass-major order: dependent MMAs on the same accumulator are
            // 16 independent MMAs apart (hides HMMA latency).
#pragma unroll
            for (int mf = 0; mf < 4; ++mf)
#pragma unroll
                for (int nf = 0; nf < 4; ++nf)
                    mma16816(c[mf][nf], ahi[mf], &bhi[nf >> 1][(nf & 1) * 2]);
#pragma unroll
            for (int mf = 0; mf < 4; ++mf)
#pragma unroll
                for (int nf = 0; nf < 4; ++nf)
                    mma16816(c[mf][nf], ahi[mf], &blo[nf >> 1][(nf & 1) * 2]);
#pragma unroll
            for (int mf = 0; mf < 4; ++mf)
#pragma unroll
                for (int nf = 0; nf < 4; ++nf)
                    mma16816(c[mf][nf], alo[mf], &bhi[nf >> 1][(nf & 1) * 2]);
        }
        __syncthreads();
    }
}

// ---------------------------------------------------------------------------
// Merged Q/K/V projection GEMM: blockIdx.z selects input/weight/output.
// z=0: Q (scaled by SCALE_Q), z=1: K, z=2: V (transposed split output).
// ---------------------------------------------------------------------------
__global__ __launch_bounds__(256, 2)
void gemm_qkv_kernel(const unsigned* __restrict__ xqh, const unsigned* __restrict__ xql,
                     const unsigned* __restrict__ xkh, const unsigned* __restrict__ xkl,
                     const unsigned* __restrict__ xvh, const unsigned* __restrict__ xvl,
                     const unsigned* __restrict__ wqh, const unsigned* __restrict__ wql,
                     const unsigned* __restrict__ wkh, const unsigned* __restrict__ wkl,
                     const unsigned* __restrict__ wvh, const unsigned* __restrict__ wvl,
                     const float* __restrict__ bq, const float* __restrict__ bk,
                     const float* __restrict__ bv,
                     unsigned* __restrict__ qh, unsigned* __restrict__ ql,
                     unsigned* __restrict__ kh, unsigned* __restrict__ kl,
                     unsigned* __restrict__ vth, unsigned* __restrict__ vtl)
{
    extern __shared__ unsigned sg[];

    const int z = blockIdx.z;
    const unsigned *Xhi, *Xlo, *Whi, *Wlo;
    const float* bias;
    unsigned *ohi, *olo;
    float scale;
    if (z == 0) { Xhi = xqh; Xlo = xql; Whi = wqh; Wlo = wql; bias = bq;
                  ohi = qh; olo = ql; scale = SCALE_Q; }
    else if (z == 1) { Xhi = xkh; Xlo = xkl; Whi = wkh; Wlo = wkl; bias = bk;
                  ohi = kh; olo = kl; scale = 1.0f; }
    else { Xhi = xvh; Xlo = xvl; Whi = wvh; Wlo = wvl; bias = bv;
                  ohi = vth; olo = vtl; scale = 1.0f; }

    const int t    = threadIdx.x;
    const int lane = t & 31;
    const int wid  = t >> 5;
    const int wm   = wid >> 2;
    const int wn   = wid & 3;
    const int g    = lane >> 2;
    const int tig  = lane & 3;
    const int m0 = blockIdx.y * 128;
    const int n0 = blockIdx.x * 128;

    float c[4][4][4];
#pragma unroll
    for (int i = 0; i < 4; ++i)
#pragma unroll
        for (int j = 0; j < 4; ++j)
#pragma unroll
            for (int e = 0; e < 4; ++e) c[i][j][e] = 0.0f;

    gemm_mainloop(Xhi, Xlo, Whi, Wlo, m0, n0, sg, c);

#pragma unroll
    for (int mf = 0; mf < 4; ++mf) {
#pragma unroll
        for (int nf = 0; nf < 4; ++nf) {
            int m = m0 + wm * 64 + mf * 16 + g;
            int n = n0 + wn * 32 + nf * 8 + tig * 2;
            float v0 = (c[mf][nf][0] + bias[n]) * scale;
            float v1 = (c[mf][nf][1] + bias[n + 1]) * scale;
            float v2 = (c[mf][nf][2] + bias[n]) * scale;
            float v3 = (c[mf][nf][3] + bias[n + 1]) * scale;
            if (z < 2) {
                int b = m >> 11, s = m & 2047;
                int h = n >> 6, hd = n & 63;
                unsigned hh, ll;
                split_pair(v0, v1, hh, ll);
                size_t p0 = (((size_t)(b * Hc + h)) * Sc + s) * 32 + (hd >> 1);
                ohi[p0] = hh; olo[p0] = ll;
                split_pair(v2, v3, hh, ll);
                size_t p1 = (((size_t)(b * Hc + h)) * Sc + (s + 8)) * 32 + (hd >> 1);
                ohi[p1] = hh; olo[p1] = ll;
            } else {
                float p0 = __shfl_xor_sync(0xffffffffu, v0, 4);
                float p1 = __shfl_xor_sync(0xffffffffu, v1, 4);
                float p2 = __shfl_xor_sync(0xffffffffu, v2, 4);
                float p3 = __shfl_xor_sync(0xffffffffu, v3, 4);
                if (!(g & 1)) {
                    int b = m >> 11, s = m & 2047;
                    int h = n >> 6, hd = n & 63;
                    size_t rb = ((size_t)(b * Hc + h)) * 64;
                    int kp = s >> 1;
                    unsigned hh, ll;
                    split_pair(v0, p0, hh, ll);
                    ohi[(rb + hd) * 1024 + kp] = hh;     olo[(rb + hd) * 1024 + kp] = ll;
                    split_pair(v1, p1, hh, ll);
                    ohi[(rb + hd + 1) * 1024 + kp] = hh; olo[(rb + hd + 1) * 1024 + kp] = ll;
                    split_pair(v2, p2, hh, ll);
                    ohi[(rb + hd) * 1024 + kp + 4] = hh;     olo[(rb + hd) * 1024 + kp + 4] = ll;
                    split_pair(v3, p3, hh, ll);
                    ohi[(rb + hd + 1) * 1024 + kp + 4] = hh; olo[(rb + hd + 1) * 1024 + kp + 4] = ll;
                }
            }
        }
    }
}

// ---------------------------------------------------------------------------
// Output GEMM: ctx(split) @ Wo^T + bo -> fp32 out
// ---------------------------------------------------------------------------
__global__ __launch_bounds__(256, 2)
void gemm_out_kernel(const unsigned* __restrict__ Xhi, const unsigned* __restrict__ Xlo,
                     const unsigned* __restrict__ Whi, const unsigned* __restrict__ Wlo,
                     const float* __restrict__ bias, float* __restrict__ outf)
{
    extern __shared__ unsigned sg[];

    const int t    = threadIdx.x;
    const int lane = t & 31;
    const int wid  = t >> 5;
    const int wm   = wid >> 2;
    const int wn   = wid & 3;
    const int g    = lane >> 2;
    const int tig  = lane & 3;
    const int m0 = blockIdx.y * 128;
    const int n0 = blockIdx.x * 128;

    float c[4][4][4];
#pragma unroll
    for (int i = 0; i < 4; ++i)
#pragma unroll
        for (int j = 0; j < 4; ++j)
#pragma unroll
            for (int e = 0; e < 4; ++e) c[i][j][e] = 0.0f;

    gemm_mainloop(Xhi, Xlo, Whi, Wlo, m0, n0, sg, c);

#pragma unroll
    for (int mf = 0; mf < 4; ++mf) {
#pragma unroll
        for (int nf = 0; nf < 4; ++nf) {
            int m = m0 + wm * 64 + mf * 16 + g;
            int n = n0 + wn * 32 + nf * 8 + tig * 2;
            outf[(size_t)m * Dc + n]           = c[mf][nf][0] + bias[n];
            outf[(size_t)m * Dc + n + 1]       = c[mf][nf][1] + bias[n + 1];
            outf[(size_t)(m + 8) * Dc + n]     = c[mf][nf][2] + bias[n];
            outf[(size_t)(m + 8) * Dc + n + 1] = c[mf][nf][3] + bias[n + 1];
        }
    }
}

// ---------------------------------------------------------------------------
// Tensor-core flash attention: exp2-domain softmax (Q pre-scaled by log2e/8),
// cp.async double-buffered K/V (V pre-transposed), pass-major MMA order.
// ---------------------------------------------------------------------------
#define AT_STAGE_U32 (4*64*36)
#define ATTN3_SMEM_U32 (2*128*36 + 2*AT_STAGE_U32)
#define ATTN3_SMEM_BYTES (ATTN3_SMEM_U32 * 4)   // 110592

__global__ __launch_bounds__(256, 2)
void attn_mma_kernel(const unsigned* __restrict__ Qhg, const unsigned* __restrict__ Qlg,
                     const unsigned* __restrict__ Khg, const unsigned* __restrict__ Klg,
                     const unsigned* __restrict__ Vthg, const unsigned* __restrict__ Vtlg,
                     unsigned* __restrict__ Chi, unsigned* __restrict__ Clo)
{
    extern __shared__ unsigned smu[];
    unsigned* Qsh = smu;                    // [128][36]
    unsigned* Qsl = Qsh + 128 * 36;
    unsigned* stages = Qsl + 128 * 36;

    const int bh = blockIdx.y;
    const int qt = (int)(gridDim.x - 1 - blockIdx.x);
    const int q0 = qt * 128;
    const int t    = threadIdx.x;
    const int lane = t & 31;
    const int w    = t >> 5;
    const int g    = lane >> 2;
    const int tig  = lane & 3;

    const int agrp  = lane >> 3;
    const int l7    = lane & 7;
    const int a_row = l7 + ((agrp & 1) << 3);
    const int a_col = (agrp >> 1) << 2;
    const int b_row = l7 + ((agrp >> 1) << 3);
    const int b_col = (agrp & 1) << 2;

    const unsigned* Qbh = Qhg + (size_t)bh * Sc * 32;
    const unsigned* Qbl = Qlg + (size_t)bh * Sc * 32;
    const unsigned* Kbh = Khg + (size_t)bh * Sc * 32;
    const unsigned* Kbl = Klg + (size_t)bh * Sc * 32;
    const unsigned* Vbh = Vthg + (size_t)bh * 64 * 1024;
    const unsigned* Vbl = Vtlg + (size_t)bh * 64 * 1024;

    // Q stage via cp.async (own group; drained by the first wait_group 1)
#pragma unroll
    for (int j = 0; j < 4; ++j) {
        int id = t + j * 256;
        int r = id >> 3, c4 = (id & 7) << 2;
        cp16(&Qsh[r * 36 + c4], &Qbh[(size_t)(q0 + r) * 32 + c4]);
        cp16(&Qsl[r * 36 + c4], &Qbl[(size_t)(q0 + r) * 32 + c4]);
    }
    asm volatile("cp.async.commit_group;\n" ::: "memory");

    auto stage_fn = [&](int st, int kt) {
        unsigned* Kh = stages + st * AT_STAGE_U32;
        unsigned* Kl = Kh + 64 * 36;
        unsigned* Vh = Kl + 64 * 36;
        unsigned* Vl = Vh + 64 * 36;
        const int k0 = kt * 64, kp0 = kt * 32;
#pragma unroll
        for (int j = 0; j < 2; ++j) {
            int id = t + j * 256;
            int r = id >> 3, c4 = (id & 7) << 2;
            cp16(Kh + r * 36 + c4, Kbh + (size_t)(k0 + r) * 32 + c4);
            cp16(Kl + r * 36 + c4, Kbl + (size_t)(k0 + r) * 32 + c4);
            cp16(Vh + r * 36 + c4, Vbh + (size_t)r * 1024 + kp0 + c4);
            cp16(Vl + r * 36 + c4, Vbl + (size_t)r * 1024 + kp0 + c4);
        }
        asm volatile("cp.async.commit_group;\n" ::: "memory");
    };

    float m_i[2] = {-1e30f, -1e30f};
    float l_i[2] = {0.0f, 0.0f};
    float o[8][4];
#pragma unroll
    for (int f = 0; f < 8; ++f)
#pragma unroll
        for (int e = 0; e < 4; ++e) o[f][e] = 0.0f;

    const int row0 = q0 + w * 16 + g;
    const int nkt = 2 * qt + 2;

    stage_fn(0, 0);

    for (int kt = 0; kt < nkt; ++kt) {
        const int k0 = kt * 64;
        __syncthreads();
        if (kt + 1 < nkt) {
            stage_fn((kt + 1) & 1, kt + 1);
            asm volatile("cp.async.wait_group 1;\n" ::: "memory");
        } else {
            asm volatile("cp.async.wait_group 0;\n" ::: "memory");
        }
        __syncthreads();

        if (q0 + w * 16 + 15 < k0) continue;

        const unsigned* Ksh = stages + (kt & 1) * AT_STAGE_U32;
        const unsigned* Ksl = Ksh + 64 * 36;
        const unsigned* Vsh = Ksl + 64 * 36;
        const unsigned* Vsl = Vsh + 64 * 36;

        // ---- S = Q K^T (pass-major) ----
        float s[8][4];
#pragma unroll
        for (int nf = 0; nf < 8; ++nf)
#pragma unroll
            for (int e = 0; e < 4; ++e) s[nf][e] = 0.0f;

#pragma unroll
        for (int ks = 0; ks < 4; ++ks) {
            unsigned aqh[4], aql[4];
            const int qoff = (w * 16 + a_row) * 36 + 8 * ks + a_col;
            ldsm4(aqh, Qsh + qoff);
            ldsm4(aql, Qsl + qoff);
            unsigned khi[4][4], klo[4][4];
#pragma unroll
            for (int np = 0; np < 4; ++np) {
                const int koff = (np * 16 + b_row) * 36 + 8 * ks + b_col;
                ldsm4(khi[np], Ksh + koff);
                ldsm4(klo[np], Ksl + koff);
            }
#pragma unroll
            for (int nf = 0; nf < 8; ++nf)
                mma16816(s[nf], aqh, &khi[nf >> 1][(nf & 1) * 2]);
#pragma unroll
            for (int nf = 0; nf < 8; ++nf)
                mma16816(s[nf], aqh, &klo[nf >> 1][(nf & 1) * 2]);
#pragma unroll
            for (int nf = 0; nf < 8; ++nf)
                mma16816(s[nf], aql, &khi[nf >> 1][(nf & 1) * 2]);
        }

        // ---- causal mask ----
        if (k0 + 63 > q0 + w * 16) {
#pragma unroll
            for (int nf = 0; nf < 8; ++nf) {
                int key = k0 + 8 * nf + 2 * tig;
                if (key     > row0)     s[nf][0] = -1e30f;
                if (key + 1 > row0)     s[nf][1] = -1e30f;
                if (key     > row0 + 8) s[nf][2] = -1e30f;
                if (key + 1 > row0 + 8) s[nf][3] = -1e30f;
            }
        }

        // ---- online softmax (base-2 domain) ----
        float mx0 = -1e30f, mx1 = -1e30f;
#pragma unroll
        for (int nf = 0; nf < 8; ++nf) {
            mx0 = fmaxf(mx0, fmaxf(s[nf][0], s[nf][1]));
            mx1 = fmaxf(mx1, fmaxf(s[nf][2], s[nf][3]));
        }
        mx0 = fmaxf(mx0, __shfl_xor_sync(0xffffffffu, mx0, 1));
        mx0 = fmaxf(mx0, __shfl_xor_sync(0xffffffffu, mx0, 2));
        mx1 = fmaxf(mx1, __shfl_xor_sync(0xffffffffu, mx1, 1));
        mx1 = fmaxf(mx1, __shfl_xor_sync(0xffffffffu, mx1, 2));

        float mn0 = fmaxf(m_i[0], mx0);
        float mn1 = fmaxf(m_i[1], mx1);
        float cs0 = exp2f(m_i[0] - mn0);
        float cs1 = exp2f(m_i[1] - mn1);
        m_i[0] = mn0; m_i[1] = mn1;

        unsigned phi[8][2], plo[8][2];
        float sum0 = 0.0f, sum1 = 0.0f;
#pragma unroll
        for (int nf = 0; nf < 8; ++nf) {
            float p0 = exp2f(s[nf][0] - mn0);
            float p1 = exp2f(s[nf][1] - mn0);
            float p2 = exp2f(s[nf][2] - mn1);
            float p3 = exp2f(s[nf][3] - mn1);
            sum0 += p0 + p1;
            sum1 += p2 + p3;
            split_pair(p0, p1, phi[nf][0], plo[nf][0]);
            split_pair(p2, p3, phi[nf][1], plo[nf][1]);
        }
        sum0 += __shfl_xor_sync(0xffffffffu, sum0, 1);
        sum0 += __shfl_xor_sync(0xffffffffu, sum0, 2);
        sum1 += __shfl_xor_sync(0xffffffffu, sum1, 1);
        sum1 += __shfl_xor_sync(0xffffffffu, sum1, 2);
        l_i[0] = l_i[0] * cs0 + sum0;
        l_i[1] = l_i[1] * cs1 + sum1;

#pragma unroll
        for (int f = 0; f < 8; ++f) {
            o[f][0] *= cs0; o[f][1] *= cs0;
            o[f][2] *= cs1; o[f][3] *= cs1;
        }

        // ---- O += P V (pass-major) ----
#pragma unroll
        for (int ks = 0; ks < 4; ++ks) {
            unsigned pah[4] = { phi[2 * ks][0], phi[2 * ks][1], phi[2 * ks + 1][0], phi[2 * ks + 1][1] };
            unsigned pal[4] = { plo[2 * ks][0], plo[2 * ks][1], plo[2 * ks + 1][0], plo[2 * ks + 1][1] };
            unsigned vhi[4][4], vlo[4][4];
#pragma unroll
            for (int np = 0; np < 4; ++np) {
                const int voff = (np * 16 + b_row) * 36 + 8 * ks + b_col;
                ldsm4(vhi[np], Vsh + voff);
                ldsm4(vlo[np], Vsl + voff);
            }
#pragma unroll
            for (int nf = 0; nf < 8; ++nf)
                mma16816(o[nf], pah, &vhi[nf >> 1][(nf & 1) * 2]);
#pragma unroll
            for (int nf = 0; nf < 8; ++nf)
                mma16816(o[nf], pah, &vlo[nf >> 1][(nf & 1) * 2]);
#pragma unroll
            for (int nf = 0; nf < 8; ++nf)
                mma16816(o[nf], pal, &vhi[nf >> 1][(nf & 1) * 2]);
        }
    }

    // ---- epilogue: normalize, split, write split ctx ----
    const float inv0 = 1.0f / l_i[0];
    const float inv1 = 1.0f / l_i[1];
    const int b = bh >> 4;
    const int h = bh & 15;
#pragma unroll
    for (int nf = 0; nf < 8; ++nf) {
        int col = 8 * nf + 2 * tig;
        unsigned hh, ll;
        split_pair(o[nf][0] * inv0, o[nf][1] * inv0, hh, ll);
        size_t p0 = ((size_t)b * Sc + row0) * 512 + h * 32 + (col >> 1);
        Chi[p0] = hh; Clo[p0] = ll;
        split_pair(o[nf][2] * inv1, o[nf][3] * inv1, hh, ll);
        size_t p1 = ((size_t)b * Sc + row0 + 8) * 512 + h * 32 + (col >> 1);
        Chi[p1] = hh; Clo[p1] = ll;
    }
}

// ---------------------------------------------------------------------------
// Launch
// ---------------------------------------------------------------------------
#define SYMADDR(p, s) do { void* _tmp; cudaGetSymbolAddress(&_tmp, s); p = (unsigned*)_tmp; } while (0)

extern "C" void kernel_launch(void* const* d_in, const int* in_sizes, int n_in,
                              void* d_out, int out_size)
{
    const float* q  = (const float*)d_in[0];
    const float* k  = (const float*)d_in[1];
    const float* v  = (const float*)d_in[2];
    const float* Wq = (const float*)d_in[4];
    const float* bq = (const float*)d_in[5];
    const float* Wk = (const float*)d_in[6];
    const float* bk = (const float*)d_in[7];
    const float* Wv = (const float*)d_in[8];
    const float* bv = (const float*)d_in[9];
    const float* Wo = (const float*)d_in[10];
    const float* bo = (const float*)d_in[11];
    float* out = (float*)d_out;

    unsigned *wqh,*wql,*wkh,*wkl,*wvh,*wvl,*woh,*wol;
    unsigned *xqh,*xql,*xkh,*xkl,*xvh,*xvl;
    unsigned *qh,*ql,*kh,*kl,*vth,*vtl,*ch,*cl;
    SYMADDR(wqh, g_Wqhi); SYMADDR(wql, g_Wqlo);
    SYMADDR(wkh, g_Wkhi); SYMADDR(wkl, g_Wklo);
    SYMADDR(wvh, g_Wvhi); SYMADDR(wvl, g_Wvlo);
    SYMADDR(woh, g_Wohi); SYMADDR(wol, g_Wolo);
    SYMADDR(xqh, g_Xqhi); SYMADDR(xql, g_Xqlo);
    SYMADDR(xkh, g_Xkhi); SYMADDR(xkl, g_Xklo);
    SYMADDR(xvh, g_Xvhi); SYMADDR(xvl, g_Xvlo);
    SYMADDR(qh, g_Qhi);   SYMADDR(ql, g_Qlo);
    SYMADDR(kh, g_Khi);   SYMADDR(kl, g_Klo);
    SYMADDR(vth, g_Vthi); SYMADDR(vtl, g_Vtlo);
    SYMADDR(ch, g_Chi);   SYMADDR(cl, g_Clo);

    cudaFuncSetAttribute(gemm_qkv_kernel, cudaFuncAttributeMaxDynamicSharedMemorySize, GEMM_SMEM);
    cudaFuncSetAttribute(gemm_out_kernel, cudaFuncAttributeMaxDynamicSharedMemorySize, GEMM_SMEM);
    cudaFuncSetAttribute(attn_mma_kernel, cudaFuncAttributeMaxDynamicSharedMemorySize, ATTN3_SMEM_BYTES);

    split4_kernel<<<dim3(1024, 4), 256>>>(
        (const float4*)Wq, (const float4*)Wk, (const float4*)Wv, (const float4*)Wo,
        (uint2*)wqh, (uint2*)wkh, (uint2*)wvh, (uint2*)woh,
        (uint2*)wql, (uint2*)wkl, (uint2*)wvl, (uint2*)wol);
    split4_kernel<<<dim3(8192, 3), 256>>>(
        (const float4*)q, (const float4*)k, (const float4*)v, (const float4*)v,
        (uint2*)xqh, (uint2*)xkh, (uint2*)xvh, (uint2*)xvh,
        (uint2*)xql, (uint2*)xkl, (uint2*)xvl, (uint2*)xvl);

    dim3 gg3(Dc / 128, Mrows / 128, 3);   // (8, 64, 3)
    gemm_qkv_kernel<<<gg3, 256, GEMM_SMEM>>>(
        xqh, xql, xkh, xkl, xvh, xvl,
        wqh, wql, wkh, wkl, wvh, wvl,
        bq, bk, bv,
        qh, ql, kh, kl, vth, vtl);

    dim3 ga(Sc / 128, Bc * Hc);           // (16, 64)
    attn_mma_kernel<<<ga, 256, ATTN3_SMEM_BYTES>>>(qh, ql, kh, kl, vth, vtl, ch, cl);

    dim3 gg(Dc / 128, Mrows / 128);       // (8, 64)
    gemm_out_kernel<<<gg, 256, GEMM_SMEM>>>(ch, cl, woh, wol, bo, out);
}

// round 10
// speedup vs baseline: 2.1871x; 1.0006x over previous
#include <cuda_runtime.h>
#include <cuda_bf16.h>

// Problem constants
#define Bc 4
#define Sc 2048
#define Dc 1024
#define Hc 16
#define Mrows (Bc*Sc)   // 8192

#define SCALE_Q 0.18033688010819965f   // 0.125 * log2(e)

// ---------------------------------------------------------------------------
// Device scratch: pre-split bf16 hi/lo (u32 = packed pair of bf16)
// ---------------------------------------------------------------------------
__device__ unsigned g_Wqhi[1024*512], g_Wqlo[1024*512];
__device__ unsigned g_Wkhi[1024*512], g_Wklo[1024*512];
__device__ unsigned g_Wvhi[1024*512], g_Wvlo[1024*512];
__device__ unsigned g_Wohi[1024*512], g_Wolo[1024*512];
__device__ unsigned g_Xqhi[(size_t)Mrows*512], g_Xqlo[(size_t)Mrows*512];
__device__ unsigned g_Xkhi[(size_t)Mrows*512], g_Xklo[(size_t)Mrows*512];
__device__ unsigned g_Xvhi[(size_t)Mrows*512], g_Xvlo[(size_t)Mrows*512];
// Q/K head layout [B,H,S,32]
__device__ unsigned g_Qhi[(size_t)Mrows*512], g_Qlo[(size_t)Mrows*512];
__device__ unsigned g_Khi[(size_t)Mrows*512], g_Klo[(size_t)Mrows*512];
// V transposed head layout [B,H,64(hd),1024(key-pair)]
__device__ unsigned g_Vthi[(size_t)Mrows*512], g_Vtlo[(size_t)Mrows*512];
// split ctx [B,S,512]
__device__ unsigned g_Chi[(size_t)Mrows*512], g_Clo[(size_t)Mrows*512];

// ---------------------------------------------------------------------------
// Helpers
// ---------------------------------------------------------------------------
__device__ __forceinline__ void split_pair(float x0, float x1,
                                           unsigned& hi, unsigned& lo)
{
    __nv_bfloat16 h0 = __float2bfloat16_rn(x0);
    __nv_bfloat16 h1 = __float2bfloat16_rn(x1);
    float r0 = x0 - __bfloat162float(h0);
    float r1 = x1 - __bfloat162float(h1);
    __nv_bfloat16 l0 = __float2bfloat16_rn(r0);
    __nv_bfloat16 l1 = __float2bfloat16_rn(r1);
    hi = ((unsigned)__bfloat16_as_ushort(h1) << 16) | __bfloat16_as_ushort(h0);
    lo = ((unsigned)__bfloat16_as_ushort(l1) << 16) | __bfloat16_as_ushort(l0);
}

__device__ __forceinline__ void mma16816(float c[4], const unsigned a[4],
                                         const unsigned b[2])
{
    asm volatile(
        "mma.sync.aligned.m16n8k16.row.col.f32.bf16.bf16.f32 "
        "{%0,%1,%2,%3}, {%4,%5,%6,%7}, {%8,%9}, {%0,%1,%2,%3};\n"
        : "+f"(c[0]), "+f"(c[1]), "+f"(c[2]), "+f"(c[3])
        : "r"(a[0]), "r"(a[1]), "r"(a[2]), "r"(a[3]),
          "r"(b[0]), "r"(b[1]));
}

__device__ __forceinline__ void ldsm4(unsigned r[4], const unsigned* p)
{
    unsigned a = (unsigned)__cvta_generic_to_shared(p);
    asm volatile("ldmatrix.sync.aligned.m8n8.x4.shared.b16 {%0,%1,%2,%3}, [%4];\n"
                 : "=r"(r[0]), "=r"(r[1]), "=r"(r[2]), "=r"(r[3]) : "r"(a));
}

__device__ __forceinline__ void cp16(void* smem, const void* g)
{
    unsigned sa = (unsigned)__cvta_generic_to_shared(smem);
    asm volatile("cp.async.cg.shared.global [%0], [%1], 16;\n"
                 :: "r"(sa), "l"(g) : "memory");
}

// ---------------------------------------------------------------------------
// Batched split converter
// ---------------------------------------------------------------------------
__global__ __launch_bounds__(256)
void split4_kernel(const float4* __restrict__ i0, const float4* __restrict__ i1,
                   const float4* __restrict__ i2, const float4* __restrict__ i3,
                   uint2* __restrict__ h0, uint2* __restrict__ h1,
                   uint2* __restrict__ h2, uint2* __restrict__ h3,
                   uint2* __restrict__ l0, uint2* __restrict__ l1,
                   uint2* __restrict__ l2, uint2* __restrict__ l3)
{
    const float4* in; uint2 *hi, *lo;
    switch (blockIdx.y) {
        case 0:  in = i0; hi = h0; lo = l0; break;
        case 1:  in = i1; hi = h1; lo = l1; break;
        case 2:  in = i2; hi = h2; lo = l2; break;
        default: in = i3; hi = h3; lo = l3; break;
    }
    int i = blockIdx.x * 256 + threadIdx.x;
    float4 f = in[i];
    unsigned a0, b0, a1, b1;
    split_pair(f.x, f.y, a0, b0);
    split_pair(f.z, f.w, a1, b1);
    hi[i] = make_uint2(a0, a1);
    lo[i] = make_uint2(b0, b1);
}

// ---------------------------------------------------------------------------
// Shared GEMM mainloop: c[4][4][4] += X[m0:,kt] W[n0:,kt]^T over K=1024.
// cp.async double-buffered, ldmatrix fragments, pass-major bf16x3 MMA order.
// ---------------------------------------------------------------------------
#define KPAD 20
#define HALF_U32 (128*KPAD)
#define STAGE_U32 (4*HALF_U32)
#define GEMM_SMEM (2*STAGE_U32*4)   // 81920 bytes

__device__ __forceinline__ void gemm_mainloop(
    const unsigned* __restrict__ Xhi, const unsigned* __restrict__ Xlo,
    const unsigned* __restrict__ Whi, const unsigned* __restrict__ Wlo,
    int m0, int n0, unsigned* sg, float c[4][4][4])
{
    const int t    = threadIdx.x;
    const int lane = t & 31;
    const int wid  = t >> 5;
    const int wm   = wid >> 2;
    const int wn   = wid & 3;

    const int agrp  = lane >> 3;
    const int l7    = lane & 7;
    const int a_row = l7 + ((agrp & 1) << 3);
    const int a_col = (agrp >> 1) << 2;
    const int b_row = l7 + ((agrp >> 1) << 3);
    const int b_col = (agrp & 1) << 2;

    auto issue = [&](int stage, int kt) {
        unsigned* base = sg + stage * STAGE_U32;
#pragma unroll
        for (int j = 0; j < 8; ++j) {
            int id   = t + j * 256;
            int half = id >> 9;
            int rem  = id & 511;
            int row  = rem >> 2;
            int c4   = (rem & 3) << 2;
            const unsigned* src;
            if      (half == 0) src = Xhi + (size_t)(m0 + row) * 512 + kt * 16 + c4;
            else if (half == 1) src = Xlo + (size_t)(m0 + row) * 512 + kt * 16 + c4;
            else if (half == 2) src = Whi + (size_t)(n0 + row) * 512 + kt * 16 + c4;
            else                src = Wlo + (size_t)(n0 + row) * 512 + kt * 16 + c4;
            cp16(base + half * HALF_U32 + row * KPAD + c4, src);
        }
        asm volatile("cp.async.commit_group;\n" ::: "memory");
    };

    issue(0, 0);

    const int NT = 32;
    for (int kt = 0; kt < NT; ++kt) {
        if (kt + 1 < NT) {
            issue((kt + 1) & 1, kt + 1);
            asm volatile("cp.async.wait_group 1;\n" ::: "memory");
        } else {
            asm volatile("cp.async.wait_group 0;\n" ::: "memory");
        }
        __syncthreads();

        const unsigned* Ah = sg + (kt & 1) * STAGE_U32;
        const unsigned* Al = Ah + HALF_U32;
        const unsigned* Bh = Ah + 2 * HALF_U32;
        const unsigned* Bl = Ah + 3 * HALF_U32;

#pragma unroll
        for (int ks = 0; ks < 2; ++ks) {
            const int pb = ks * 8;
            unsigned ahi[4][4], alo[4][4], bhi[2][4], blo[2][4];
#pragma unroll
            for (int mf = 0; mf < 4; ++mf) {
                const int r = (wm * 64 + mf * 16 + a_row) * KPAD + pb + a_col;
                ldsm4(ahi[mf], Ah + r);
                ldsm4(alo[mf], Al + r);
            }
#pragma unroll
            for (int np = 0; np < 2; ++np) {
                const int r = (wn * 32 + np * 16 + b_row) * KPAD + pb + b_col;
                ldsm4(bhi[np], Bh + r);
                ldsm4(blo[np], Bl + r);
            }
            // Pass-major order: dependent MMAs on the same accumulator are
            // 16 independent MMAs apart (hides HMMA latency).
#pragma unroll
            for (int mf = 0; mf < 4; ++mf)
#pragma unroll
                for (int nf = 0; nf < 4; ++nf)
                    mma16816(c[mf][nf], ahi[mf], &bhi[nf >> 1][(nf & 1) * 2]);
#pragma unroll
            for (int mf = 0; mf < 4; ++mf)
#pragma unroll
                for (int nf = 0; nf < 4; ++nf)
                    mma16816(c[mf][nf], ahi[mf], &blo[nf >> 1][(nf & 1) * 2]);
#pragma unroll
            for (int mf = 0; mf < 4; ++mf)
#pragma unroll
                for (int nf = 0; nf < 4; ++nf)
                    mma16816(c[mf][nf], alo[mf], &bhi[nf >> 1][(nf & 1) * 2]);
        }
        __syncthreads();
    }
}

// ---------------------------------------------------------------------------
// Merged Q/K/V projection GEMM: blockIdx.z selects input/weight/output.
// z=0: Q (scaled by SCALE_Q), z=1: K, z=2: V (transposed split output).
// ---------------------------------------------------------------------------
__global__ __launch_bounds__(256, 2)
void gemm_qkv_kernel(const unsigned* __restrict__ xqh, const unsigned* __restrict__ xql,
                     const unsigned* __restrict__ xkh, const unsigned* __restrict__ xkl,
                     const unsigned* __restrict__ xvh, const unsigned* __restrict__ xvl,
                     const unsigned* __restrict__ wqh, const unsigned* __restrict__ wql,
                     const unsigned* __restrict__ wkh, const unsigned* __restrict__ wkl,
                     const unsigned* __restrict__ wvh, const unsigned* __restrict__ wvl,
                     const float* __restrict__ bq, const float* __restrict__ bk,
                     const float* __restrict__ bv,
                     unsigned* __restrict__ qh, unsigned* __restrict__ ql,
                     unsigned* __restrict__ kh, unsigned* __restrict__ kl,
                     unsigned* __restrict__ vth, unsigned* __restrict__ vtl)
{
    extern __shared__ unsigned sg[];

    const int z = blockIdx.z;
    const unsigned *Xhi, *Xlo, *Whi, *Wlo;
    const float* bias;
    unsigned *ohi, *olo;
    float scale;
    if (z == 0) { Xhi = xqh; Xlo = xql; Whi = wqh; Wlo = wql; bias = bq;
                  ohi = qh; olo = ql; scale = SCALE_Q; }
    else if (z == 1) { Xhi = xkh; Xlo = xkl; Whi = wkh; Wlo = wkl; bias = bk;
                  ohi = kh; olo = kl; scale = 1.0f; }
    else { Xhi = xvh; Xlo = xvl; Whi = wvh; Wlo = wvl; bias = bv;
                  ohi = vth; olo = vtl; scale = 1.0f; }

    const int t    = threadIdx.x;
    const int lane = t & 31;
    const int wid  = t >> 5;
    const int wm   = wid >> 2;
    const int wn   = wid & 3;
    const int g    = lane >> 2;
    const int tig  = lane & 3;
    const int m0 = blockIdx.y * 128;
    const int n0 = blockIdx.x * 128;

    float c[4][4][4];
#pragma unroll
    for (int i = 0; i < 4; ++i)
#pragma unroll
        for (int j = 0; j < 4; ++j)
#pragma unroll
            for (int e = 0; e < 4; ++e) c[i][j][e] = 0.0f;

    gemm_mainloop(Xhi, Xlo, Whi, Wlo, m0, n0, sg, c);

#pragma unroll
    for (int mf = 0; mf < 4; ++mf) {
#pragma unroll
        for (int nf = 0; nf < 4; ++nf) {
            int m = m0 + wm * 64 + mf * 16 + g;
            int n = n0 + wn * 32 + nf * 8 + tig * 2;
            float v0 = (c[mf][nf][0] + bias[n]) * scale;
            float v1 = (c[mf][nf][1] + bias[n + 1]) * scale;
            float v2 = (c[mf][nf][2] + bias[n]) * scale;
            float v3 = (c[mf][nf][3] + bias[n + 1]) * scale;
            if (z < 2) {
                int b = m >> 11, s = m & 2047;
                int h = n >> 6, hd = n & 63;
                unsigned hh, ll;
                split_pair(v0, v1, hh, ll);
                size_t p0 = (((size_t)(b * Hc + h)) * Sc + s) * 32 + (hd >> 1);
                ohi[p0] = hh; olo[p0] = ll;
                split_pair(v2, v3, hh, ll);
                size_t p1 = (((size_t)(b * Hc + h)) * Sc + (s + 8)) * 32 + (hd >> 1);
                ohi[p1] = hh; olo[p1] = ll;
            } else {
                float p0 = __shfl_xor_sync(0xffffffffu, v0, 4);
                float p1 = __shfl_xor_sync(0xffffffffu, v1, 4);
                float p2 = __shfl_xor_sync(0xffffffffu, v2, 4);
                float p3 = __shfl_xor_sync(0xffffffffu, v3, 4);
                if (!(g & 1)) {
                    int b = m >> 11, s = m & 2047;
                    int h = n >> 6, hd = n & 63;
                    size_t rb = ((size_t)(b * Hc + h)) * 64;
                    int kp = s >> 1;
                    unsigned hh, ll;
                    split_pair(v0, p0, hh, ll);
                    ohi[(rb + hd) * 1024 + kp] = hh;     olo[(rb + hd) * 1024 + kp] = ll;
                    split_pair(v1, p1, hh, ll);
                    ohi[(rb + hd + 1) * 1024 + kp] = hh; olo[(rb + hd + 1) * 1024 + kp] = ll;
                    split_pair(v2, p2, hh, ll);
                    ohi[(rb + hd) * 1024 + kp + 4] = hh;     olo[(rb + hd) * 1024 + kp + 4] = ll;
                    split_pair(v3, p3, hh, ll);
                    ohi[(rb + hd + 1) * 1024 + kp + 4] = hh; olo[(rb + hd + 1) * 1024 + kp + 4] = ll;
                }
            }
        }
    }
}

// ---------------------------------------------------------------------------
// Output GEMM: ctx(split) @ Wo^T + bo -> fp32 out
// ---------------------------------------------------------------------------
__global__ __launch_bounds__(256, 2)
void gemm_out_kernel(const unsigned* __restrict__ Xhi, const unsigned* __restrict__ Xlo,
                     const unsigned* __restrict__ Whi, const unsigned* __restrict__ Wlo,
                     const float* __restrict__ bias, float* __restrict__ outf)
{
    extern __shared__ unsigned sg[];

    const int t    = threadIdx.x;
    const int lane = t & 31;
    const int wid  = t >> 5;
    const int wm   = wid >> 2;
    const int wn   = wid & 3;
    const int g    = lane >> 2;
    const int tig  = lane & 3;
    const int m0 = blockIdx.y * 128;
    const int n0 = blockIdx.x * 128;

    float c[4][4][4];
#pragma unroll
    for (int i = 0; i < 4; ++i)
#pragma unroll
        for (int j = 0; j < 4; ++j)
#pragma unroll
            for (int e = 0; e < 4; ++e) c[i][j][e] = 0.0f;

    gemm_mainloop(Xhi, Xlo, Whi, Wlo, m0, n0, sg, c);

#pragma unroll
    for (int mf = 0; mf < 4; ++mf) {
#pragma unroll
        for (int nf = 0; nf < 4; ++nf) {
            int m = m0 + wm * 64 + mf * 16 + g;
            int n = n0 + wn * 32 + nf * 8 + tig * 2;
            outf[(size_t)m * Dc + n]           = c[mf][nf][0] + bias[n];
            outf[(size_t)m * Dc + n + 1]       = c[mf][nf][1] + bias[n + 1];
            outf[(size_t)(m + 8) * Dc + n]     = c[mf][nf][2] + bias[n];
            outf[(size_t)(m + 8) * Dc + n + 1] = c[mf][nf][3] + bias[n + 1];
        }
    }
}

// ---------------------------------------------------------------------------
// Tensor-core flash attention: exp2-domain softmax (Q pre-scaled by log2e/8),
// cp.async double-buffered K/V (V pre-transposed), pass-major MMA order.
// ---------------------------------------------------------------------------
#define AT_STAGE_U32 (4*64*36)
#define ATTN3_SMEM_U32 (2*128*36 + 2*AT_STAGE_U32)
#define ATTN3_SMEM_BYTES (ATTN3_SMEM_U32 * 4)   // 110592

__global__ __launch_bounds__(256, 2)
void attn_mma_kernel(const unsigned* __restrict__ Qhg, const unsigned* __restrict__ Qlg,
                     const unsigned* __restrict__ Khg, const unsigned* __restrict__ Klg,
                     const unsigned* __restrict__ Vthg, const unsigned* __restrict__ Vtlg,
                     unsigned* __restrict__ Chi, unsigned* __restrict__ Clo)
{
    extern __shared__ unsigned smu[];
    unsigned* Qsh = smu;                    // [128][36]
    unsigned* Qsl = Qsh + 128 * 36;
    unsigned* stages = Qsl + 128 * 36;

    const int bh = blockIdx.y;
    const int qt = (int)(gridDim.x - 1 - blockIdx.x);
    const int q0 = qt * 128;
    const int t    = threadIdx.x;
    const int lane = t & 31;
    const int w    = t >> 5;
    const int g    = lane >> 2;
    const int tig  = lane & 3;

    const int agrp  = lane >> 3;
    const int l7    = lane & 7;
    const int a_row = l7 + ((agrp & 1) << 3);
    const int a_col = (agrp >> 1) << 2;
    const int b_row = l7 + ((agrp >> 1) << 3);
    const int b_col = (agrp & 1) << 2;

    const unsigned* Qbh = Qhg + (size_t)bh * Sc * 32;
    const unsigned* Qbl = Qlg + (size_t)bh * Sc * 32;
    const unsigned* Kbh = Khg + (size_t)bh * Sc * 32;
    const unsigned* Kbl = Klg + (size_t)bh * Sc * 32;
    const unsigned* Vbh = Vthg + (size_t)bh * 64 * 1024;
    const unsigned* Vbl = Vtlg + (size_t)bh * 64 * 1024;

    // Q stage via cp.async (own group; drained by the first wait_group 1)
#pragma unroll
    for (int j = 0; j < 4; ++j) {
        int id = t + j * 256;
        int r = id >> 3, c4 = (id & 7) << 2;
        cp16(&Qsh[r * 36 + c4], &Qbh[(size_t)(q0 + r) * 32 + c4]);
        cp16(&Qsl[r * 36 + c4], &Qbl[(size_t)(q0 + r) * 32 + c4]);
    }
    asm volatile("cp.async.commit_group;\n" ::: "memory");

    auto stage_fn = [&](int st, int kt) {
        unsigned* Kh = stages + st * AT_STAGE_U32;
        unsigned* Kl = Kh + 64 * 36;
        unsigned* Vh = Kl + 64 * 36;
        unsigned* Vl = Vh + 64 * 36;
        const int k0 = kt * 64, kp0 = kt * 32;
#pragma unroll
        for (int j = 0; j < 2; ++j) {
            int id = t + j * 256;
            int r = id >> 3, c4 = (id & 7) << 2;
            cp16(Kh + r * 36 + c4, Kbh + (size_t)(k0 + r) * 32 + c4);
            cp16(Kl + r * 36 + c4, Kbl + (size_t)(k0 + r) * 32 + c4);
            cp16(Vh + r * 36 + c4, Vbh + (size_t)r * 1024 + kp0 + c4);
            cp16(Vl + r * 36 + c4, Vbl + (size_t)r * 1024 + kp0 + c4);
        }
        asm volatile("cp.async.commit_group;\n" ::: "memory");
    };

    float m_i[2] = {-1e30f, -1e30f};
    float l_i[2] = {0.0f, 0.0f};
    float o[8][4];
#pragma unroll
    for (int f = 0; f < 8; ++f)
#pragma unroll
        for (int e = 0; e < 4; ++e) o[f][e] = 0.0f;

    const int row0 = q0 + w * 16 + g;
    const int nkt = 2 * qt + 2;

    stage_fn(0, 0);

    for (int kt = 0; kt < nkt; ++kt) {
        const int k0 = kt * 64;
        __syncthreads();
        if (kt + 1 < nkt) {
            stage_fn((kt + 1) & 1, kt + 1);
            asm volatile("cp.async.wait_group 1;\n" ::: "memory");
        } else {
            asm volatile("cp.async.wait_group 0;\n" ::: "memory");
        }
        __syncthreads();

        if (q0 + w * 16 + 15 < k0) continue;

        const unsigned* Ksh = stages + (kt & 1) * AT_STAGE_U32;
        const unsigned* Ksl = Ksh + 64 * 36;
        const unsigned* Vsh = Ksl + 64 * 36;
        const unsigned* Vsl = Vsh + 64 * 36;

        // ---- S = Q K^T (pass-major) ----
        float s[8][4];
#pragma unroll
        for (int nf = 0; nf < 8; ++nf)
#pragma unroll
            for (int e = 0; e < 4; ++e) s[nf][e] = 0.0f;

#pragma unroll
        for (int ks = 0; ks < 4; ++ks) {
            unsigned aqh[4], aql[4];
            const int qoff = (w * 16 + a_row) * 36 + 8 * ks + a_col;
            ldsm4(aqh, Qsh + qoff);
            ldsm4(aql, Qsl + qoff);
            unsigned khi[4][4], klo[4][4];
#pragma unroll
            for (int np = 0; np < 4; ++np) {
                const int koff = (np * 16 + b_row) * 36 + 8 * ks + b_col;
                ldsm4(khi[np], Ksh + koff);
                ldsm4(klo[np], Ksl + koff);
            }
#pragma unroll
            for (int nf = 0; nf < 8; ++nf)
                mma16816(s[nf], aqh, &khi[nf >> 1][(nf & 1) * 2]);
#pragma unroll
            for (int nf = 0; nf < 8; ++nf)
                mma16816(s[nf], aqh, &klo[nf >> 1][(nf & 1) * 2]);
#pragma unroll
            for (int nf = 0; nf < 8; ++nf)
                mma16816(s[nf], aql, &khi[nf >> 1][(nf & 1) * 2]);
        }

        // ---- causal mask ----
        if (k0 + 63 > q0 + w * 16) {
#pragma unroll
            for (int nf = 0; nf < 8; ++nf) {
                int key = k0 + 8 * nf + 2 * tig;
                if (key     > row0)     s[nf][0] = -1e30f;
                if (key + 1 > row0)     s[nf][1] = -1e30f;
                if (key     > row0 + 8) s[nf][2] = -1e30f;
                if (key + 1 > row0 + 8) s[nf][3] = -1e30f;
            }
        }

        // ---- online softmax (base-2 domain) ----
        float mx0 = -1e30f, mx1 = -1e30f;
#pragma unroll
        for (int nf = 0; nf < 8; ++nf) {
            mx0 = fmaxf(mx0, fmaxf(s[nf][0], s[nf][1]));
            mx1 = fmaxf(mx1, fmaxf(s[nf][2], s[nf][3]));
        }
        mx0 = fmaxf(mx0, __shfl_xor_sync(0xffffffffu, mx0, 1));
        mx0 = fmaxf(mx0, __shfl_xor_sync(0xffffffffu, mx0, 2));
        mx1 = fmaxf(mx1, __shfl_xor_sync(0xffffffffu, mx1, 1));
        mx1 = fmaxf(mx1, __shfl_xor_sync(0xffffffffu, mx1, 2));

        float mn0 = fmaxf(m_i[0], mx0);
        float mn1 = fmaxf(m_i[1], mx1);
        float cs0 = exp2f(m_i[0] - mn0);
        float cs1 = exp2f(m_i[1] - mn1);
        m_i[0] = mn0; m_i[1] = mn1;

        unsigned phi[8][2], plo[8][2];
        float sum0 = 0.0f, sum1 = 0.0f;
#pragma unroll
        for (int nf = 0; nf < 8; ++nf) {
            float p0 = exp2f(s[nf][0] - mn0);
            float p1 = exp2f(s[nf][1] - mn0);
            float p2 = exp2f(s[nf][2] - mn1);
            float p3 = exp2f(s[nf][3] - mn1);
            sum0 += p0 + p1;
            sum1 += p2 + p3;
            split_pair(p0, p1, phi[nf][0], plo[nf][0]);
            split_pair(p2, p3, phi[nf][1], plo[nf][1]);
        }
        sum0 += __shfl_xor_sync(0xffffffffu, sum0, 1);
        sum0 += __shfl_xor_sync(0xffffffffu, sum0, 2);
        sum1 += __shfl_xor_sync(0xffffffffu, sum1, 1);
        sum1 += __shfl_xor_sync(0xffffffffu, sum1, 2);
        l_i[0] = l_i[0] * cs0 + sum0;
        l_i[1] = l_i[1] * cs1 + sum1;

#pragma unroll
        for (int f = 0; f < 8; ++f) {
            o[f][0] *= cs0; o[f][1] *= cs0;
            o[f][2] *= cs1; o[f][3] *= cs1;
        }

        // ---- O += P V (pass-major) ----
#pragma unroll
        for (int ks = 0; ks < 4; ++ks) {
            unsigned pah[4] = { phi[2 * ks][0], phi[2 * ks][1], phi[2 * ks + 1][0], phi[2 * ks + 1][1] };
            unsigned pal[4] = { plo[2 * ks][0], plo[2 * ks][1], plo[2 * ks + 1][0], plo[2 * ks + 1][1] };
            unsigned vhi[4][4], vlo[4][4];
#pragma unroll
            for (int np = 0; np < 4; ++np) {
                const int voff = (np * 16 + b_row) * 36 + 8 * ks + b_col;
                ldsm4(vhi[np], Vsh + voff);
                ldsm4(vlo[np], Vsl + voff);
            }
#pragma unroll
            for (int nf = 0; nf < 8; ++nf)
                mma16816(o[nf], pah, &vhi[nf >> 1][(nf & 1) * 2]);
#pragma unroll
            for (int nf = 0; nf < 8; ++nf)
                mma16816(o[nf], pah, &vlo[nf >> 1][(nf & 1) * 2]);
#pragma unroll
            for (int nf = 0; nf < 8; ++nf)
                mma16816(o[nf], pal, &vhi[nf >> 1][(nf & 1) * 2]);
        }
    }

    // ---- epilogue: normalize, split, write split ctx ----
    const float inv0 = 1.0f / l_i[0];
    const float inv1 = 1.0f / l_i[1];
    const int b = bh >> 4;
    const int h = bh & 15;
#pragma unroll
    for (int nf = 0; nf < 8; ++nf) {
        int col = 8 * nf + 2 * tig;
        unsigned hh, ll;
        split_pair(o[nf][0] * inv0, o[nf][1] * inv0, hh, ll);
        size_t p0 = ((size_t)b * Sc + row0) * 512 + h * 32 + (col >> 1);
        Chi[p0] = hh; Clo[p0] = ll;
        split_pair(o[nf][2] * inv1, o[nf][3] * inv1, hh, ll);
        size_t p1 = ((size_t)b * Sc + row0 + 8) * 512 + h * 32 + (col >> 1);
        Chi[p1] = hh; Clo[p1] = ll;
    }
}

// ---------------------------------------------------------------------------
// Launch
// ---------------------------------------------------------------------------
#define SYMADDR(p, s) do { void* _tmp; cudaGetSymbolAddress(&_tmp, s); p = (unsigned*)_tmp; } while (0)

extern "C" void kernel_launch(void* const* d_in, const int* in_sizes, int n_in,
                              void* d_out, int out_size)
{
    const float* q  = (const float*)d_in[0];
    const float* k  = (const float*)d_in[1];
    const float* v  = (const float*)d_in[2];
    const float* Wq = (const float*)d_in[4];
    const float* bq = (const float*)d_in[5];
    const float* Wk = (const float*)d_in[6];
    const float* bk = (const float*)d_in[7];
    const float* Wv = (const float*)d_in[8];
    const float* bv = (const float*)d_in[9];
    const float* Wo = (const float*)d_in[10];
    const float* bo = (const float*)d_in[11];
    float* out = (float*)d_out;

    unsigned *wqh,*wql,*wkh,*wkl,*wvh,*wvl,*woh,*wol;
    unsigned *xqh,*xql,*xkh,*xkl,*xvh,*xvl;
    unsigned *qh,*ql,*kh,*kl,*vth,*vtl,*ch,*cl;
    SYMADDR(wqh, g_Wqhi); SYMADDR(wql, g_Wqlo);
    SYMADDR(wkh, g_Wkhi); SYMADDR(wkl, g_Wklo);
    SYMADDR(wvh, g_Wvhi); SYMADDR(wvl, g_Wvlo);
    SYMADDR(woh, g_Wohi); SYMADDR(wol, g_Wolo);
    SYMADDR(xqh, g_Xqhi); SYMADDR(xql, g_Xqlo);
    SYMADDR(xkh, g_Xkhi); SYMADDR(xkl, g_Xklo);
    SYMADDR(xvh, g_Xvhi); SYMADDR(xvl, g_Xvlo);
    SYMADDR(qh, g_Qhi);   SYMADDR(ql, g_Qlo);
    SYMADDR(kh, g_Khi);   SYMADDR(kl, g_Klo);
    SYMADDR(vth, g_Vthi); SYMADDR(vtl, g_Vtlo);
    SYMADDR(ch, g_Chi);   SYMADDR(cl, g_Clo);

    cudaFuncSetAttribute(gemm_qkv_kernel, cudaFuncAttributeMaxDynamicSharedMemorySize, GEMM_SMEM);
    cudaFuncSetAttribute(gemm_out_kernel, cudaFuncAttributeMaxDynamicSharedMemorySize, GEMM_SMEM);
    cudaFuncSetAttribute(attn_mma_kernel, cudaFuncAttributeMaxDynamicSharedMemorySize, ATTN3_SMEM_BYTES);

    split4_kernel<<<dim3(1024, 4), 256>>>(
        (const float4*)Wq, (const float4*)Wk, (const float4*)Wv, (const float4*)Wo,
        (uint2*)wqh, (uint2*)wkh, (uint2*)wvh, (uint2*)woh,
        (uint2*)wql, (uint2*)wkl, (uint2*)wvl, (uint2*)wol);
    split4_kernel<<<dim3(8192, 3), 256>>>(
        (const float4*)q, (const float4*)k, (const float4*)v, (const float4*)v,
        (uint2*)xqh, (uint2*)xkh, (uint2*)xvh, (uint2*)xvh,
        (uint2*)xql, (uint2*)xkl, (uint2*)xvl, (uint2*)xvl);

    dim3 gg3(Dc / 128, Mrows / 128, 3);   // (8, 64, 3)
    gemm_qkv_kernel<<<gg3, 256, GEMM_SMEM>>>(
        xqh, xql, xkh, xkl, xvh, xvl,
        wqh, wql, wkh, wkl, wvh, wvl,
        bq, bk, bv,
        qh, ql, kh, kl, vth, vtl);

    dim3 ga(Sc / 128, Bc * Hc);           // (16, 64)
    attn_mma_kernel<<<ga, 256, ATTN3_SMEM_BYTES>>>(qh, ql, kh, kl, vth, vtl, ch, cl);

    dim3 gg(Dc / 128, Mrows / 128);       // (8, 64)
    gemm_out_kernel<<<gg, 256, GEMM_SMEM>>>(ch, cl, woh, wol, bo, out);
}

// round 11
// speedup vs baseline: 2.3252x; 1.0631x over previous
#include <cuda_runtime.h>
#include <cuda_bf16.h>
#include <cuda_fp16.h>

// Problem constants
#define Bc 4
#define Sc 2048
#define Dc 1024
#define Hc 16
#define Mrows (Bc*Sc)   // 8192

#define SCALE_Q 0.18033688010819965f   // 0.125 * log2(e)

// ---------------------------------------------------------------------------
// Device scratch: pre-split bf16 hi/lo (u32 = packed pair of bf16)
// ---------------------------------------------------------------------------
__device__ unsigned g_Wqhi[1024*512], g_Wqlo[1024*512];
__device__ unsigned g_Wkhi[1024*512], g_Wklo[1024*512];
__device__ unsigned g_Wvhi[1024*512], g_Wvlo[1024*512];
__device__ unsigned g_Wohi[1024*512], g_Wolo[1024*512];
__device__ unsigned g_Xqhi[(size_t)Mrows*512], g_Xqlo[(size_t)Mrows*512];
__device__ unsigned g_Xkhi[(size_t)Mrows*512], g_Xklo[(size_t)Mrows*512];
__device__ unsigned g_Xvhi[(size_t)Mrows*512], g_Xvlo[(size_t)Mrows*512];
// Q/K head layout [B,H,S,32] (bf16 split)
__device__ unsigned g_Qhi[(size_t)Mrows*512], g_Qlo[(size_t)Mrows*512];
__device__ unsigned g_Khi[(size_t)Mrows*512], g_Klo[(size_t)Mrows*512];
// V transposed head layout [B,H,64(hd),1024(key-pair)] -- fp16 split
__device__ unsigned g_Vthi[(size_t)Mrows*512], g_Vtlo[(size_t)Mrows*512];
// split ctx [B,S,512] (bf16 split)
__device__ unsigned g_Chi[(size_t)Mrows*512], g_Clo[(size_t)Mrows*512];

// ---------------------------------------------------------------------------
// Helpers
// ---------------------------------------------------------------------------
__device__ __forceinline__ void split_pair(float x0, float x1,
                                           unsigned& hi, unsigned& lo)
{
    // cheap split: 1 packed cvt, bit-exact bf16->f32 via shift, residual cvt
    __nv_bfloat162 h2 = __floats2bfloat162_rn(x0, x1);   // .x=x0 (low 16b)
    unsigned hu = *reinterpret_cast<unsigned*>(&h2);
    float h0 = __uint_as_float(hu << 16);
    float h1 = __uint_as_float(hu & 0xffff0000u);
    __nv_bfloat162 l2 = __floats2bfloat162_rn(x0 - h0, x1 - h1);
    hi = hu;
    lo = *reinterpret_cast<unsigned*>(&l2);
}

__device__ __forceinline__ void split_pair_f16(float x0, float x1,
                                               unsigned& hi, unsigned& lo)
{
    __half2 h2 = __floats2half2_rn(x0, x1);   // .x=x0 (low 16b)
    float2 hf = __half22float2(h2);
    __half2 l2 = __floats2half2_rn(x0 - hf.x, x1 - hf.y);
    hi = *reinterpret_cast<unsigned*>(&h2);
    lo = *reinterpret_cast<unsigned*>(&l2);
}

__device__ __forceinline__ void mma16816(float c[4], const unsigned a[4],
                                         const unsigned b[2])
{
    asm volatile(
        "mma.sync.aligned.m16n8k16.row.col.f32.bf16.bf16.f32 "
        "{%0,%1,%2,%3}, {%4,%5,%6,%7}, {%8,%9}, {%0,%1,%2,%3};\n"
        : "+f"(c[0]), "+f"(c[1]), "+f"(c[2]), "+f"(c[3])
        : "r"(a[0]), "r"(a[1]), "r"(a[2]), "r"(a[3]),
          "r"(b[0]), "r"(b[1]));
}

__device__ __forceinline__ void mma16816f16(float c[4], const unsigned a[4],
                                            const unsigned b[2])
{
    asm volatile(
        "mma.sync.aligned.m16n8k16.row.col.f32.f16.f16.f32 "
        "{%0,%1,%2,%3}, {%4,%5,%6,%7}, {%8,%9}, {%0,%1,%2,%3};\n"
        : "+f"(c[0]), "+f"(c[1]), "+f"(c[2]), "+f"(c[3])
        : "r"(a[0]), "r"(a[1]), "r"(a[2]), "r"(a[3]),
          "r"(b[0]), "r"(b[1]));
}

__device__ __forceinline__ void ldsm4(unsigned r[4], const unsigned* p)
{
    unsigned a = (unsigned)__cvta_generic_to_shared(p);
    asm volatile("ldmatrix.sync.aligned.m8n8.x4.shared.b16 {%0,%1,%2,%3}, [%4];\n"
                 : "=r"(r[0]), "=r"(r[1]), "=r"(r[2]), "=r"(r[3]) : "r"(a));
}

__device__ __forceinline__ void cp16(void* smem, const void* g)
{
    unsigned sa = (unsigned)__cvta_generic_to_shared(smem);
    asm volatile("cp.async.cg.shared.global [%0], [%1], 16;\n"
                 :: "r"(sa), "l"(g) : "memory");
}

// ---------------------------------------------------------------------------
// Batched split converter
// ---------------------------------------------------------------------------
__global__ __launch_bounds__(256)
void split4_kernel(const float4* __restrict__ i0, const float4* __restrict__ i1,
                   const float4* __restrict__ i2, const float4* __restrict__ i3,
                   uint2* __restrict__ h0, uint2* __restrict__ h1,
                   uint2* __restrict__ h2, uint2* __restrict__ h3,
                   uint2* __restrict__ l0, uint2* __restrict__ l1,
                   uint2* __restrict__ l2, uint2* __restrict__ l3)
{
    const float4* in; uint2 *hi, *lo;
    switch (blockIdx.y) {
        case 0:  in = i0; hi = h0; lo = l0; break;
        case 1:  in = i1; hi = h1; lo = l1; break;
        case 2:  in = i2; hi = h2; lo = l2; break;
        default: in = i3; hi = h3; lo = l3; break;
    }
    int i = blockIdx.x * 256 + threadIdx.x;
    float4 f = in[i];
    unsigned a0, b0, a1, b1;
    split_pair(f.x, f.y, a0, b0);
    split_pair(f.z, f.w, a1, b1);
    hi[i] = make_uint2(a0, a1);
    lo[i] = make_uint2(b0, b1);
}

// ---------------------------------------------------------------------------
// Shared GEMM mainloop (unchanged from R10)
// ---------------------------------------------------------------------------
#define KPAD 20
#define HALF_U32 (128*KPAD)
#define STAGE_U32 (4*HALF_U32)
#define GEMM_SMEM (2*STAGE_U32*4)   // 81920 bytes

__device__ __forceinline__ void gemm_mainloop(
    const unsigned* __restrict__ Xhi, const unsigned* __restrict__ Xlo,
    const unsigned* __restrict__ Whi, const unsigned* __restrict__ Wlo,
    int m0, int n0, unsigned* sg, float c[4][4][4])
{
    const int t    = threadIdx.x;
    const int lane = t & 31;
    const int wid  = t >> 5;
    const int wm   = wid >> 2;
    const int wn   = wid & 3;

    const int agrp  = lane >> 3;
    const int l7    = lane & 7;
    const int a_row = l7 + ((agrp & 1) << 3);
    const int a_col = (agrp >> 1) << 2;
    const int b_row = l7 + ((agrp >> 1) << 3);
    const int b_col = (agrp & 1) << 2;

    auto issue = [&](int stage, int kt) {
        unsigned* base = sg + stage * STAGE_U32;
#pragma unroll
        for (int j = 0; j < 8; ++j) {
            int id   = t + j * 256;
            int half = id >> 9;
            int rem  = id & 511;
            int row  = rem >> 2;
            int c4   = (rem & 3) << 2;
            const unsigned* src;
            if      (half == 0) src = Xhi + (size_t)(m0 + row) * 512 + kt * 16 + c4;
            else if (half == 1) src = Xlo + (size_t)(m0 + row) * 512 + kt * 16 + c4;
            else if (half == 2) src = Whi + (size_t)(n0 + row) * 512 + kt * 16 + c4;
            else                src = Wlo + (size_t)(n0 + row) * 512 + kt * 16 + c4;
            cp16(base + half * HALF_U32 + row * KPAD + c4, src);
        }
        asm volatile("cp.async.commit_group;\n" ::: "memory");
    };

    issue(0, 0);

    const int NT = 32;
    for (int kt = 0; kt < NT; ++kt) {
        if (kt + 1 < NT) {
            issue((kt + 1) & 1, kt + 1);
            asm volatile("cp.async.wait_group 1;\n" ::: "memory");
        } else {
            asm volatile("cp.async.wait_group 0;\n" ::: "memory");
        }
        __syncthreads();

        const unsigned* Ah = sg + (kt & 1) * STAGE_U32;
        const unsigned* Al = Ah + HALF_U32;
        const unsigned* Bh = Ah + 2 * HALF_U32;
        const unsigned* Bl = Ah + 3 * HALF_U32;

#pragma unroll
        for (int ks = 0; ks < 2; ++ks) {
            const int pb = ks * 8;
            unsigned ahi[4][4], alo[4][4], bhi[2][4], blo[2][4];
#pragma unroll
            for (int mf = 0; mf < 4; ++mf) {
                const int r = (wm * 64 + mf * 16 + a_row) * KPAD + pb + a_col;
                ldsm4(ahi[mf], Ah + r);
                ldsm4(alo[mf], Al + r);
            }
#pragma unroll
            for (int np = 0; np < 2; ++np) {
                const int r = (wn * 32 + np * 16 + b_row) * KPAD + pb + b_col;
                ldsm4(bhi[np], Bh + r);
                ldsm4(blo[np], Bl + r);
            }
#pragma unroll
            for (int mf = 0; mf < 4; ++mf)
#pragma unroll
                for (int nf = 0; nf < 4; ++nf)
                    mma16816(c[mf][nf], ahi[mf], &bhi[nf >> 1][(nf & 1) * 2]);
#pragma unroll
            for (int mf = 0; mf < 4; ++mf)
#pragma unroll
                for (int nf = 0; nf < 4; ++nf)
                    mma16816(c[mf][nf], ahi[mf], &blo[nf >> 1][(nf & 1) * 2]);
#pragma unroll
            for (int mf = 0; mf < 4; ++mf)
#pragma unroll
                for (int nf = 0; nf < 4; ++nf)
                    mma16816(c[mf][nf], alo[mf], &bhi[nf >> 1][(nf & 1) * 2]);
        }
        __syncthreads();
    }
}

// ---------------------------------------------------------------------------
// Merged Q/K/V projection GEMM: z=0 Q (bf16 split, scaled), z=1 K (bf16 split),
// z=2 V (transposed FP16 split output).
// ---------------------------------------------------------------------------
__global__ __launch_bounds__(256, 2)
void gemm_qkv_kernel(const unsigned* __restrict__ xqh, const unsigned* __restrict__ xql,
                     const unsigned* __restrict__ xkh, const unsigned* __restrict__ xkl,
                     const unsigned* __restrict__ xvh, const unsigned* __restrict__ xvl,
                     const unsigned* __restrict__ wqh, const unsigned* __restrict__ wql,
                     const unsigned* __restrict__ wkh, const unsigned* __restrict__ wkl,
                     const unsigned* __restrict__ wvh, const unsigned* __restrict__ wvl,
                     const float* __restrict__ bq, const float* __restrict__ bk,
                     const float* __restrict__ bv,
                     unsigned* __restrict__ qh, unsigned* __restrict__ ql,
                     unsigned* __restrict__ kh, unsigned* __restrict__ kl,
                     unsigned* __restrict__ vth, unsigned* __restrict__ vtl)
{
    extern __shared__ unsigned sg[];

    const int z = blockIdx.z;
    const unsigned *Xhi, *Xlo, *Whi, *Wlo;
    const float* bias;
    unsigned *ohi, *olo;
    float scale;
    if (z == 0) { Xhi = xqh; Xlo = xql; Whi = wqh; Wlo = wql; bias = bq;
                  ohi = qh; olo = ql; scale = SCALE_Q; }
    else if (z == 1) { Xhi = xkh; Xlo = xkl; Whi = wkh; Wlo = wkl; bias = bk;
                  ohi = kh; olo = kl; scale = 1.0f; }
    else { Xhi = xvh; Xlo = xvl; Whi = wvh; Wlo = wvl; bias = bv;
                  ohi = vth; olo = vtl; scale = 1.0f; }

    const int t    = threadIdx.x;
    const int lane = t & 31;
    const int wid  = t >> 5;
    const int wm   = wid >> 2;
    const int wn   = wid & 3;
    const int g    = lane >> 2;
    const int tig  = lane & 3;
    const int m0 = blockIdx.y * 128;
    const int n0 = blockIdx.x * 128;

    float c[4][4][4];
#pragma unroll
    for (int i = 0; i < 4; ++i)
#pragma unroll
        for (int j = 0; j < 4; ++j)
#pragma unroll
            for (int e = 0; e < 4; ++e) c[i][j][e] = 0.0f;

    gemm_mainloop(Xhi, Xlo, Whi, Wlo, m0, n0, sg, c);

#pragma unroll
    for (int mf = 0; mf < 4; ++mf) {
#pragma unroll
        for (int nf = 0; nf < 4; ++nf) {
            int m = m0 + wm * 64 + mf * 16 + g;
            int n = n0 + wn * 32 + nf * 8 + tig * 2;
            float v0 = (c[mf][nf][0] + bias[n]) * scale;
            float v1 = (c[mf][nf][1] + bias[n + 1]) * scale;
            float v2 = (c[mf][nf][2] + bias[n]) * scale;
            float v3 = (c[mf][nf][3] + bias[n + 1]) * scale;
            if (z < 2) {
                int b = m >> 11, s = m & 2047;
                int h = n >> 6, hd = n & 63;
                unsigned hh, ll;
                split_pair(v0, v1, hh, ll);
                size_t p0 = (((size_t)(b * Hc + h)) * Sc + s) * 32 + (hd >> 1);
                ohi[p0] = hh; olo[p0] = ll;
                split_pair(v2, v3, hh, ll);
                size_t p1 = (((size_t)(b * Hc + h)) * Sc + (s + 8)) * 32 + (hd >> 1);
                ohi[p1] = hh; olo[p1] = ll;
            } else {
                float p0 = __shfl_xor_sync(0xffffffffu, v0, 4);
                float p1 = __shfl_xor_sync(0xffffffffu, v1, 4);
                float p2 = __shfl_xor_sync(0xffffffffu, v2, 4);
                float p3 = __shfl_xor_sync(0xffffffffu, v3, 4);
                if (!(g & 1)) {
                    int b = m >> 11, s = m & 2047;
                    int h = n >> 6, hd = n & 63;
                    size_t rb = ((size_t)(b * Hc + h)) * 64;
                    int kp = s >> 1;
                    unsigned hh, ll;
                    split_pair_f16(v0, p0, hh, ll);
                    vth[(rb + hd) * 1024 + kp] = hh;     vtl[(rb + hd) * 1024 + kp] = ll;
                    split_pair_f16(v1, p1, hh, ll);
                    vth[(rb + hd + 1) * 1024 + kp] = hh; vtl[(rb + hd + 1) * 1024 + kp] = ll;
                    split_pair_f16(v2, p2, hh, ll);
                    vth[(rb + hd) * 1024 + kp + 4] = hh;     vtl[(rb + hd) * 1024 + kp + 4] = ll;
                    split_pair_f16(v3, p3, hh, ll);
                    vth[(rb + hd + 1) * 1024 + kp + 4] = hh; vtl[(rb + hd + 1) * 1024 + kp + 4] = ll;
                }
            }
        }
    }
}

// ---------------------------------------------------------------------------
// Output GEMM: ctx(split) @ Wo^T + bo -> fp32 out
// ---------------------------------------------------------------------------
__global__ __launch_bounds__(256, 2)
void gemm_out_kernel(const unsigned* __restrict__ Xhi, const unsigned* __restrict__ Xlo,
                     const unsigned* __restrict__ Whi, const unsigned* __restrict__ Wlo,
                     const float* __restrict__ bias, float* __restrict__ outf)
{
    extern __shared__ unsigned sg[];

    const int t    = threadIdx.x;
    const int lane = t & 31;
    const int wid  = t >> 5;
    const int wm   = wid >> 2;
    const int wn   = wid & 3;
    const int g    = lane >> 2;
    const int tig  = lane & 3;
    const int m0 = blockIdx.y * 128;
    const int n0 = blockIdx.x * 128;

    float c[4][4][4];
#pragma unroll
    for (int i = 0; i < 4; ++i)
#pragma unroll
        for (int j = 0; j < 4; ++j)
#pragma unroll
            for (int e = 0; e < 4; ++e) c[i][j][e] = 0.0f;

    gemm_mainloop(Xhi, Xlo, Whi, Wlo, m0, n0, sg, c);

#pragma unroll
    for (int mf = 0; mf < 4; ++mf) {
#pragma unroll
        for (int nf = 0; nf < 4; ++nf) {
            int m = m0 + wm * 64 + mf * 16 + g;
            int n = n0 + wn * 32 + nf * 8 + tig * 2;
            outf[(size_t)m * Dc + n]           = c[mf][nf][0] + bias[n];
            outf[(size_t)m * Dc + n + 1]       = c[mf][nf][1] + bias[n + 1];
            outf[(size_t)(m + 8) * Dc + n]     = c[mf][nf][2] + bias[n];
            outf[(size_t)(m + 8) * Dc + n + 1] = c[mf][nf][3] + bias[n + 1];
        }
    }
}

// ---------------------------------------------------------------------------
// Tensor-core flash attention: exp2-domain softmax, fp16 P (single value),
// fp16 hi/lo V (2-pass PV), bf16x3 QK, cp.async double-buffered K/V.
// ---------------------------------------------------------------------------
#define AT_STAGE_U32 (4*64*36)
#define ATTN3_SMEM_U32 (2*128*36 + 2*AT_STAGE_U32)
#define ATTN3_SMEM_BYTES (ATTN3_SMEM_U32 * 4)   // 110592

__global__ __launch_bounds__(256, 2)
void attn_mma_kernel(const unsigned* __restrict__ Qhg, const unsigned* __restrict__ Qlg,
                     const unsigned* __restrict__ Khg, const unsigned* __restrict__ Klg,
                     const unsigned* __restrict__ Vthg, const unsigned* __restrict__ Vtlg,
                     unsigned* __restrict__ Chi, unsigned* __restrict__ Clo)
{
    extern __shared__ unsigned smu[];
    unsigned* Qsh = smu;                    // [128][36]
    unsigned* Qsl = Qsh + 128 * 36;
    unsigned* stages = Qsl + 128 * 36;

    const int bh = blockIdx.y;
    const int qt = (int)(gridDim.x - 1 - blockIdx.x);
    const int q0 = qt * 128;
    const int t    = threadIdx.x;
    const int lane = t & 31;
    const int w    = t >> 5;
    const int g    = lane >> 2;
    const int tig  = lane & 3;

    const int agrp  = lane >> 3;
    const int l7    = lane & 7;
    const int a_row = l7 + ((agrp & 1) << 3);
    const int a_col = (agrp >> 1) << 2;
    const int b_row = l7 + ((agrp >> 1) << 3);
    const int b_col = (agrp & 1) << 2;

    const unsigned* Qbh = Qhg + (size_t)bh * Sc * 32;
    const unsigned* Qbl = Qlg + (size_t)bh * Sc * 32;
    const unsigned* Kbh = Khg + (size_t)bh * Sc * 32;
    const unsigned* Kbl = Klg + (size_t)bh * Sc * 32;
    const unsigned* Vbh = Vthg + (size_t)bh * 64 * 1024;
    const unsigned* Vbl = Vtlg + (size_t)bh * 64 * 1024;

    // Q stage via cp.async
#pragma unroll
    for (int j = 0; j < 4; ++j) {
        int id = t + j * 256;
        int r = id >> 3, c4 = (id & 7) << 2;
        cp16(&Qsh[r * 36 + c4], &Qbh[(size_t)(q0 + r) * 32 + c4]);
        cp16(&Qsl[r * 36 + c4], &Qbl[(size_t)(q0 + r) * 32 + c4]);
    }
    asm volatile("cp.async.commit_group;\n" ::: "memory");

    auto stage_fn = [&](int st, int kt) {
        unsigned* Kh = stages + st * AT_STAGE_U32;
        unsigned* Kl = Kh + 64 * 36;
        unsigned* Vh = Kl + 64 * 36;
        unsigned* Vl = Vh + 64 * 36;
        const int k0 = kt * 64, kp0 = kt * 32;
#pragma unroll
        for (int j = 0; j < 2; ++j) {
            int id = t + j * 256;
            int r = id >> 3, c4 = (id & 7) << 2;
            cp16(Kh + r * 36 + c4, Kbh + (size_t)(k0 + r) * 32 + c4);
            cp16(Kl + r * 36 + c4, Kbl + (size_t)(k0 + r) * 32 + c4);
            cp16(Vh + r * 36 + c4, Vbh + (size_t)r * 1024 + kp0 + c4);
            cp16(Vl + r * 36 + c4, Vbl + (size_t)r * 1024 + kp0 + c4);
        }
        asm volatile("cp.async.commit_group;\n" ::: "memory");
    };

    float m_i[2] = {-1e30f, -1e30f};
    float l_i[2] = {0.0f, 0.0f};
    float o[8][4];
#pragma unroll
    for (int f = 0; f < 8; ++f)
#pragma unroll
        for (int e = 0; e < 4; ++e) o[f][e] = 0.0f;

    const int row0 = q0 + w * 16 + g;
    const int nkt = 2 * qt + 2;

    stage_fn(0, 0);

    for (int kt = 0; kt < nkt; ++kt) {
        const int k0 = kt * 64;
        __syncthreads();
        if (kt + 1 < nkt) {
            stage_fn((kt + 1) & 1, kt + 1);
            asm volatile("cp.async.wait_group 1;\n" ::: "memory");
        } else {
            asm volatile("cp.async.wait_group 0;\n" ::: "memory");
        }
        __syncthreads();

        if (q0 + w * 16 + 15 < k0) continue;

        const unsigned* Ksh = stages + (kt & 1) * AT_STAGE_U32;
        const unsigned* Ksl = Ksh + 64 * 36;
        const unsigned* Vsh = Ksl + 64 * 36;
        const unsigned* Vsl = Vsh + 64 * 36;

        // ---- S = Q K^T (bf16x3, pass-major) ----
        float s[8][4];
#pragma unroll
        for (int nf = 0; nf < 8; ++nf)
#pragma unroll
            for (int e = 0; e < 4; ++e) s[nf][e] = 0.0f;

#pragma unroll
        for (int ks = 0; ks < 4; ++ks) {
            unsigned aqh[4], aql[4];
            const int qoff = (w * 16 + a_row) * 36 + 8 * ks + a_col;
            ldsm4(aqh, Qsh + qoff);
            ldsm4(aql, Qsl + qoff);
            unsigned khi[4][4], klo[4][4];
#pragma unroll
            for (int np = 0; np < 4; ++np) {
                const int koff = (np * 16 + b_row) * 36 + 8 * ks + b_col;
                ldsm4(khi[np], Ksh + koff);
                ldsm4(klo[np], Ksl + koff);
            }
#pragma unroll
            for (int nf = 0; nf < 8; ++nf)
                mma16816(s[nf], aqh, &khi[nf >> 1][(nf & 1) * 2]);
#pragma unroll
            for (int nf = 0; nf < 8; ++nf)
                mma16816(s[nf], aqh, &klo[nf >> 1][(nf & 1) * 2]);
#pragma unroll
            for (int nf = 0; nf < 8; ++nf)
                mma16816(s[nf], aql, &khi[nf >> 1][(nf & 1) * 2]);
        }

        // ---- causal mask ----
        if (k0 + 63 > q0 + w * 16) {
#pragma unroll
            for (int nf = 0; nf < 8; ++nf) {
                int key = k0 + 8 * nf + 2 * tig;
                if (key     > row0)     s[nf][0] = -1e30f;
                if (key + 1 > row0)     s[nf][1] = -1e30f;
                if (key     > row0 + 8) s[nf][2] = -1e30f;
                if (key + 1 > row0 + 8) s[nf][3] = -1e30f;
            }
        }

        // ---- online softmax (base-2 domain) ----
        float mx0 = -1e30f, mx1 = -1e30f;
#pragma unroll
        for (int nf = 0; nf < 8; ++nf) {
            mx0 = fmaxf(mx0, fmaxf(s[nf][0], s[nf][1]));
            mx1 = fmaxf(mx1, fmaxf(s[nf][2], s[nf][3]));
        }
        mx0 = fmaxf(mx0, __shfl_xor_sync(0xffffffffu, mx0, 1));
        mx0 = fmaxf(mx0, __shfl_xor_sync(0xffffffffu, mx0, 2));
        mx1 = fmaxf(mx1, __shfl_xor_sync(0xffffffffu, mx1, 1));
        mx1 = fmaxf(mx1, __shfl_xor_sync(0xffffffffu, mx1, 2));

        float mn0 = fmaxf(m_i[0], mx0);
        float mn1 = fmaxf(m_i[1], mx1);
        float cs0 = exp2f(m_i[0] - mn0);
        float cs1 = exp2f(m_i[1] - mn1);
        m_i[0] = mn0; m_i[1] = mn1;

        // P as single fp16 (packed pairs along the key dim)
        unsigned pf[8][2];
        float sum0 = 0.0f, sum1 = 0.0f;
#pragma unroll
        for (int nf = 0; nf < 8; ++nf) {
            float p0 = exp2f(s[nf][0] - mn0);
            float p1 = exp2f(s[nf][1] - mn0);
            float p2 = exp2f(s[nf][2] - mn1);
            float p3 = exp2f(s[nf][3] - mn1);
            sum0 += p0 + p1;
            sum1 += p2 + p3;
            __half2 h01 = __floats2half2_rn(p0, p1);
            __half2 h23 = __floats2half2_rn(p2, p3);
            pf[nf][0] = *reinterpret_cast<unsigned*>(&h01);
            pf[nf][1] = *reinterpret_cast<unsigned*>(&h23);
        }
        sum0 += __shfl_xor_sync(0xffffffffu, sum0, 1);
        sum0 += __shfl_xor_sync(0xffffffffu, sum0, 2);
        sum1 += __shfl_xor_sync(0xffffffffu, sum1, 1);
        sum1 += __shfl_xor_sync(0xffffffffu, sum1, 2);
        l_i[0] = l_i[0] * cs0 + sum0;
        l_i[1] = l_i[1] * cs1 + sum1;

#pragma unroll
        for (int f = 0; f < 8; ++f) {
            o[f][0] *= cs0; o[f][1] *= cs0;
            o[f][2] *= cs1; o[f][3] *= cs1;
        }

        // ---- O += P V (fp16, 2-pass: p*vh + p*vl) ----
#pragma unroll
        for (int ks = 0; ks < 4; ++ks) {
            unsigned pa[4] = { pf[2 * ks][0], pf[2 * ks][1],
                               pf[2 * ks + 1][0], pf[2 * ks + 1][1] };
            unsigned vhi[4][4], vlo[4][4];
#pragma unroll
            for (int np = 0; np < 4; ++np) {
                const int voff = (np * 16 + b_row) * 36 + 8 * ks + b_col;
                ldsm4(vhi[np], Vsh + voff);
                ldsm4(vlo[np], Vsl + voff);
            }
#pragma unroll
            for (int nf = 0; nf < 8; ++nf)
                mma16816f16(o[nf], pa, &vhi[nf >> 1][(nf & 1) * 2]);
#pragma unroll
            for (int nf = 0; nf < 8; ++nf)
                mma16816f16(o[nf], pa, &vlo[nf >> 1][(nf & 1) * 2]);
        }
    }

    // ---- epilogue: normalize, split (bf16), write split ctx ----
    const float inv0 = 1.0f / l_i[0];
    const float inv1 = 1.0f / l_i[1];
    const int b = bh >> 4;
    const int h = bh & 15;
#pragma unroll
    for (int nf = 0; nf < 8; ++nf) {
        int col = 8 * nf + 2 * tig;
        unsigned hh, ll;
        split_pair(o[nf][0] * inv0, o[nf][1] * inv0, hh, ll);
        size_t p0 = ((size_t)b * Sc + row0) * 512 + h * 32 + (col >> 1);
        Chi[p0] = hh; Clo[p0] = ll;
        split_pair(o[nf][2] * inv1, o[nf][3] * inv1, hh, ll);
        size_t p1 = ((size_t)b * Sc + row0 + 8) * 512 + h * 32 + (col >> 1);
        Chi[p1] = hh; Clo[p1] = ll;
    }
}

// ---------------------------------------------------------------------------
// Launch
// ---------------------------------------------------------------------------
#define SYMADDR(p, s) do { void* _tmp; cudaGetSymbolAddress(&_tmp, s); p = (unsigned*)_tmp; } while (0)

extern "C" void kernel_launch(void* const* d_in, const int* in_sizes, int n_in,
                              void* d_out, int out_size)
{
    const float* q  = (const float*)d_in[0];
    const float* k  = (const float*)d_in[1];
    const float* v  = (const float*)d_in[2];
    const float* Wq = (const float*)d_in[4];
    const float* bq = (const float*)d_in[5];
    const float* Wk = (const float*)d_in[6];
    const float* bk = (const float*)d_in[7];
    const float* Wv = (const float*)d_in[8];
    const float* bv = (const float*)d_in[9];
    const float* Wo = (const float*)d_in[10];
    const float* bo = (const float*)d_in[11];
    float* out = (float*)d_out;

    unsigned *wqh,*wql,*wkh,*wkl,*wvh,*wvl,*woh,*wol;
    unsigned *xqh,*xql,*xkh,*xkl,*xvh,*xvl;
    unsigned *qh,*ql,*kh,*kl,*vth,*vtl,*ch,*cl;
    SYMADDR(wqh, g_Wqhi); SYMADDR(wql, g_Wqlo);
    SYMADDR(wkh, g_Wkhi); SYMADDR(wkl, g_Wklo);
    SYMADDR(wvh, g_Wvhi); SYMADDR(wvl, g_Wvlo);
    SYMADDR(woh, g_Wohi); SYMADDR(wol, g_Wolo);
    SYMADDR(xqh, g_Xqhi); SYMADDR(xql, g_Xqlo);
    SYMADDR(xkh, g_Xkhi); SYMADDR(xkl, g_Xklo);
    SYMADDR(xvh, g_Xvhi); SYMADDR(xvl, g_Xvlo);
    SYMADDR(qh, g_Qhi);   SYMADDR(ql, g_Qlo);
    SYMADDR(kh, g_Khi);   SYMADDR(kl, g_Klo);
    SYMADDR(vth, g_Vthi); SYMADDR(vtl, g_Vtlo);
    SYMADDR(ch, g_Chi);   SYMADDR(cl, g_Clo);

    cudaFuncSetAttribute(gemm_qkv_kernel, cudaFuncAttributeMaxDynamicSharedMemorySize, GEMM_SMEM);
    cudaFuncSetAttribute(gemm_out_kernel, cudaFuncAttributeMaxDynamicSharedMemorySize, GEMM_SMEM);
    cudaFuncSetAttribute(attn_mma_kernel, cudaFuncAttributeMaxDynamicSharedMemorySize, ATTN3_SMEM_BYTES);

    split4_kernel<<<dim3(1024, 4), 256>>>(
        (const float4*)Wq, (const float4*)Wk, (const float4*)Wv, (const float4*)Wo,
        (uint2*)wqh, (uint2*)wkh, (uint2*)wvh, (uint2*)woh,
        (uint2*)wql, (uint2*)wkl, (uint2*)wvl, (uint2*)wol);
    split4_kernel<<<dim3(8192, 3), 256>>>(
        (const float4*)q, (const float4*)k, (const float4*)v, (const float4*)v,
        (uint2*)xqh, (uint2*)xkh, (uint2*)xvh, (uint2*)xvh,
        (uint2*)xql, (uint2*)xkl, (uint2*)xvl, (uint2*)xvl);

    dim3 gg3(Dc / 128, Mrows / 128, 3);   // (8, 64, 3)
    gemm_qkv_kernel<<<gg3, 256, GEMM_SMEM>>>(
        xqh, xql, xkh, xkl, xvh, xvl,
        wqh, wql, wkh, wkl, wvh, wvl,
        bq, bk, bv,
        qh, ql, kh, kl, vth, vtl);

    dim3 ga(Sc / 128, Bc * Hc);           // (16, 64)
    attn_mma_kernel<<<ga, 256, ATTN3_SMEM_BYTES>>>(qh, ql, kh, kl, vth, vtl, ch, cl);

    dim3 gg(Dc / 128, Mrows / 128);       // (8, 64)
    gemm_out_kernel<<<gg, 256, GEMM_SMEM>>>(ch, cl, woh, wol, bo, out);
}

// round 12
// speedup vs baseline: 2.8407x; 1.2217x over previous
#include <cuda_runtime.h>
#include <cuda_bf16.h>
#include <cuda_fp16.h>

// Problem constants
#define Bc 4
#define Sc 2048
#define Dc 1024
#define Hc 16
#define Mrows (Bc*Sc)   // 8192

#define SCALE_Q 0.18033688010819965f   // 0.125 * log2(e)

// ---------------------------------------------------------------------------
// Device scratch (u32 = packed pair of 16-bit values)
// Weights + inputs: fp16 split (GEMMs use hi of W only)
// ---------------------------------------------------------------------------
__device__ unsigned g_Wqhi[1024*512], g_Wqlo[1024*512];
__device__ unsigned g_Wkhi[1024*512], g_Wklo[1024*512];
__device__ unsigned g_Wvhi[1024*512], g_Wvlo[1024*512];
__device__ unsigned g_Wohi[1024*512], g_Wolo[1024*512];
__device__ unsigned g_Xqhi[(size_t)Mrows*512], g_Xqlo[(size_t)Mrows*512];
__device__ unsigned g_Xkhi[(size_t)Mrows*512], g_Xklo[(size_t)Mrows*512];
__device__ unsigned g_Xvhi[(size_t)Mrows*512], g_Xvlo[(size_t)Mrows*512];
// Q/K head layout [B,H,S,32] (bf16 split -- attention QK is bf16x3)
__device__ unsigned g_Qhi[(size_t)Mrows*512], g_Qlo[(size_t)Mrows*512];
__device__ unsigned g_Khi[(size_t)Mrows*512], g_Klo[(size_t)Mrows*512];
// V transposed head layout [B,H,64(hd),1024(key-pair)] -- fp16 split
__device__ unsigned g_Vthi[(size_t)Mrows*512], g_Vtlo[(size_t)Mrows*512];
// ctx [B,S,512] -- fp16 split (O-GEMM input)
__device__ unsigned g_Chi[(size_t)Mrows*512], g_Clo[(size_t)Mrows*512];

// ---------------------------------------------------------------------------
// Helpers
// ---------------------------------------------------------------------------
__device__ __forceinline__ void split_pair(float x0, float x1,
                                           unsigned& hi, unsigned& lo)
{
    __nv_bfloat162 h2 = __floats2bfloat162_rn(x0, x1);
    unsigned hu = *reinterpret_cast<unsigned*>(&h2);
    float h0 = __uint_as_float(hu << 16);
    float h1 = __uint_as_float(hu & 0xffff0000u);
    __nv_bfloat162 l2 = __floats2bfloat162_rn(x0 - h0, x1 - h1);
    hi = hu;
    lo = *reinterpret_cast<unsigned*>(&l2);
}

__device__ __forceinline__ void split_pair_f16(float x0, float x1,
                                               unsigned& hi, unsigned& lo)
{
    __half2 h2 = __floats2half2_rn(x0, x1);
    float2 hf = __half22float2(h2);
    __half2 l2 = __floats2half2_rn(x0 - hf.x, x1 - hf.y);
    hi = *reinterpret_cast<unsigned*>(&h2);
    lo = *reinterpret_cast<unsigned*>(&l2);
}

__device__ __forceinline__ void mma16816(float c[4], const unsigned a[4],
                                         const unsigned b[2])
{
    asm volatile(
        "mma.sync.aligned.m16n8k16.row.col.f32.bf16.bf16.f32 "
        "{%0,%1,%2,%3}, {%4,%5,%6,%7}, {%8,%9}, {%0,%1,%2,%3};\n"
        : "+f"(c[0]), "+f"(c[1]), "+f"(c[2]), "+f"(c[3])
        : "r"(a[0]), "r"(a[1]), "r"(a[2]), "r"(a[3]),
          "r"(b[0]), "r"(b[1]));
}

__device__ __forceinline__ void mma16816f16(float c[4], const unsigned a[4],
                                            const unsigned b[2])
{
    asm volatile(
        "mma.sync.aligned.m16n8k16.row.col.f32.f16.f16.f32 "
        "{%0,%1,%2,%3}, {%4,%5,%6,%7}, {%8,%9}, {%0,%1,%2,%3};\n"
        : "+f"(c[0]), "+f"(c[1]), "+f"(c[2]), "+f"(c[3])
        : "r"(a[0]), "r"(a[1]), "r"(a[2]), "r"(a[3]),
          "r"(b[0]), "r"(b[1]));
}

__device__ __forceinline__ void ldsm4(unsigned r[4], const unsigned* p)
{
    unsigned a = (unsigned)__cvta_generic_to_shared(p);
    asm volatile("ldmatrix.sync.aligned.m8n8.x4.shared.b16 {%0,%1,%2,%3}, [%4];\n"
                 : "=r"(r[0]), "=r"(r[1]), "=r"(r[2]), "=r"(r[3]) : "r"(a));
}

__device__ __forceinline__ void cp16(void* smem, const void* g)
{
    unsigned sa = (unsigned)__cvta_generic_to_shared(smem);
    asm volatile("cp.async.cg.shared.global [%0], [%1], 16;\n"
                 :: "r"(sa), "l"(g) : "memory");
}

// ---------------------------------------------------------------------------
// Batched split converter (fp16 hi/lo)
// ---------------------------------------------------------------------------
__global__ __launch_bounds__(256)
void split4_kernel(const float4* __restrict__ i0, const float4* __restrict__ i1,
                   const float4* __restrict__ i2, const float4* __restrict__ i3,
                   uint2* __restrict__ h0, uint2* __restrict__ h1,
                   uint2* __restrict__ h2, uint2* __restrict__ h3,
                   uint2* __restrict__ l0, uint2* __restrict__ l1,
                   uint2* __restrict__ l2, uint2* __restrict__ l3)
{
    const float4* in; uint2 *hi, *lo;
    switch (blockIdx.y) {
        case 0:  in = i0; hi = h0; lo = l0; break;
        case 1:  in = i1; hi = h1; lo = l1; break;
        case 2:  in = i2; hi = h2; lo = l2; break;
        default: in = i3; hi = h3; lo = l3; break;
    }
    int i = blockIdx.x * 256 + threadIdx.x;
    float4 f = in[i];
    unsigned a0, b0, a1, b1;
    split_pair_f16(f.x, f.y, a0, b0);
    split_pair_f16(f.z, f.w, a1, b1);
    hi[i] = make_uint2(a0, a1);
    lo[i] = make_uint2(b0, b1);
}

// ---------------------------------------------------------------------------
// Shared GEMM mainloop: fp16 2-pass (X split hi/lo, W hi only).
// Stages 3 tiles (Xh, Xl, Wh) per k-tile, cp.async double-buffered.
// ---------------------------------------------------------------------------
#define KPAD 20
#define HALF_U32 (128*KPAD)
#define STAGE_U32 (3*HALF_U32)
#define GEMM_SMEM (2*STAGE_U32*4)   // 61440 bytes

__device__ __forceinline__ void gemm_mainloop(
    const unsigned* __restrict__ Xhi, const unsigned* __restrict__ Xlo,
    const unsigned* __restrict__ Whi,
    int m0, int n0, unsigned* sg, float c[4][4][4])
{
    const int t    = threadIdx.x;
    const int lane = t & 31;
    const int wid  = t >> 5;
    const int wm   = wid >> 2;
    const int wn   = wid & 3;

    const int agrp  = lane >> 3;
    const int l7    = lane & 7;
    const int a_row = l7 + ((agrp & 1) << 3);
    const int a_col = (agrp >> 1) << 2;
    const int b_row = l7 + ((agrp >> 1) << 3);
    const int b_col = (agrp & 1) << 2;

    auto issue = [&](int stage, int kt) {
        unsigned* base = sg + stage * STAGE_U32;
#pragma unroll
        for (int j = 0; j < 6; ++j) {
            int id   = t + j * 256;          // 0..1535
            int half = id >> 9;              // 0..2
            int rem  = id & 511;
            int row  = rem >> 2;
            int c4   = (rem & 3) << 2;
            const unsigned* src;
            if      (half == 0) src = Xhi + (size_t)(m0 + row) * 512 + kt * 16 + c4;
            else if (half == 1) src = Xlo + (size_t)(m0 + row) * 512 + kt * 16 + c4;
            else                src = Whi + (size_t)(n0 + row) * 512 + kt * 16 + c4;
            cp16(base + half * HALF_U32 + row * KPAD + c4, src);
        }
        asm volatile("cp.async.commit_group;\n" ::: "memory");
    };

    issue(0, 0);

    const int NT = 32;
    for (int kt = 0; kt < NT; ++kt) {
        if (kt + 1 < NT) {
            issue((kt + 1) & 1, kt + 1);
            asm volatile("cp.async.wait_group 1;\n" ::: "memory");
        } else {
            asm volatile("cp.async.wait_group 0;\n" ::: "memory");
        }
        __syncthreads();

        const unsigned* Ah = sg + (kt & 1) * STAGE_U32;
        const unsigned* Al = Ah + HALF_U32;
        const unsigned* Bh = Ah + 2 * HALF_U32;

#pragma unroll
        for (int ks = 0; ks < 2; ++ks) {
            const int pb = ks * 8;
            unsigned ahi[4][4], alo[4][4], bhi[2][4];
#pragma unroll
            for (int mf = 0; mf < 4; ++mf) {
                const int r = (wm * 64 + mf * 16 + a_row) * KPAD + pb + a_col;
                ldsm4(ahi[mf], Ah + r);
                ldsm4(alo[mf], Al + r);
            }
#pragma unroll
            for (int np = 0; np < 2; ++np) {
                const int r = (wn * 32 + np * 16 + b_row) * KPAD + pb + b_col;
                ldsm4(bhi[np], Bh + r);
            }
            // Pass-major 2-pass fp16
#pragma unroll
            for (int mf = 0; mf < 4; ++mf)
#pragma unroll
                for (int nf = 0; nf < 4; ++nf)
                    mma16816f16(c[mf][nf], ahi[mf], &bhi[nf >> 1][(nf & 1) * 2]);
#pragma unroll
            for (int mf = 0; mf < 4; ++mf)
#pragma unroll
                for (int nf = 0; nf < 4; ++nf)
                    mma16816f16(c[mf][nf], alo[mf], &bhi[nf >> 1][(nf & 1) * 2]);
        }
        __syncthreads();
    }
}

// ---------------------------------------------------------------------------
// Merged Q/K/V projection GEMM: z=0 Q (bf16 split out, scaled), z=1 K (bf16
// split out), z=2 V (transposed fp16 split out).
// ---------------------------------------------------------------------------
__global__ __launch_bounds__(256, 2)
void gemm_qkv_kernel(const unsigned* __restrict__ xqh, const unsigned* __restrict__ xql,
                     const unsigned* __restrict__ xkh, const unsigned* __restrict__ xkl,
                     const unsigned* __restrict__ xvh, const unsigned* __restrict__ xvl,
                     const unsigned* __restrict__ wqh,
                     const unsigned* __restrict__ wkh,
                     const unsigned* __restrict__ wvh,
                     const float* __restrict__ bq, const float* __restrict__ bk,
                     const float* __restrict__ bv,
                     unsigned* __restrict__ qh, unsigned* __restrict__ ql,
                     unsigned* __restrict__ kh, unsigned* __restrict__ kl,
                     unsigned* __restrict__ vth, unsigned* __restrict__ vtl)
{
    extern __shared__ unsigned sg[];

    const int z = blockIdx.z;
    const unsigned *Xhi, *Xlo, *Whi;
    const float* bias;
    unsigned *ohi, *olo;
    float scale;
    if (z == 0) { Xhi = xqh; Xlo = xql; Whi = wqh; bias = bq;
                  ohi = qh; olo = ql; scale = SCALE_Q; }
    else if (z == 1) { Xhi = xkh; Xlo = xkl; Whi = wkh; bias = bk;
                  ohi = kh; olo = kl; scale = 1.0f; }
    else { Xhi = xvh; Xlo = xvl; Whi = wvh; bias = bv;
                  ohi = vth; olo = vtl; scale = 1.0f; }

    const int t    = threadIdx.x;
    const int lane = t & 31;
    const int wid  = t >> 5;
    const int wm   = wid >> 2;
    const int wn   = wid & 3;
    const int g    = lane >> 2;
    const int tig  = lane & 3;
    const int m0 = blockIdx.y * 128;
    const int n0 = blockIdx.x * 128;

    float c[4][4][4];
#pragma unroll
    for (int i = 0; i < 4; ++i)
#pragma unroll
        for (int j = 0; j < 4; ++j)
#pragma unroll
            for (int e = 0; e < 4; ++e) c[i][j][e] = 0.0f;

    gemm_mainloop(Xhi, Xlo, Whi, m0, n0, sg, c);

#pragma unroll
    for (int mf = 0; mf < 4; ++mf) {
#pragma unroll
        for (int nf = 0; nf < 4; ++nf) {
            int m = m0 + wm * 64 + mf * 16 + g;
            int n = n0 + wn * 32 + nf * 8 + tig * 2;
            float v0 = (c[mf][nf][0] + bias[n]) * scale;
            float v1 = (c[mf][nf][1] + bias[n + 1]) * scale;
            float v2 = (c[mf][nf][2] + bias[n]) * scale;
            float v3 = (c[mf][nf][3] + bias[n + 1]) * scale;
            if (z < 2) {
                int b = m >> 11, s = m & 2047;
                int h = n >> 6, hd = n & 63;
                unsigned hh, ll;
                split_pair(v0, v1, hh, ll);
                size_t p0 = (((size_t)(b * Hc + h)) * Sc + s) * 32 + (hd >> 1);
                ohi[p0] = hh; olo[p0] = ll;
                split_pair(v2, v3, hh, ll);
                size_t p1 = (((size_t)(b * Hc + h)) * Sc + (s + 8)) * 32 + (hd >> 1);
                ohi[p1] = hh; olo[p1] = ll;
            } else {
                float p0 = __shfl_xor_sync(0xffffffffu, v0, 4);
                float p1 = __shfl_xor_sync(0xffffffffu, v1, 4);
                float p2 = __shfl_xor_sync(0xffffffffu, v2, 4);
                float p3 = __shfl_xor_sync(0xffffffffu, v3, 4);
                if (!(g & 1)) {
                    int b = m >> 11, s = m & 2047;
                    int h = n >> 6, hd = n & 63;
                    size_t rb = ((size_t)(b * Hc + h)) * 64;
                    int kp = s >> 1;
                    unsigned hh, ll;
                    split_pair_f16(v0, p0, hh, ll);
                    ohi[(rb + hd) * 1024 + kp] = hh;     olo[(rb + hd) * 1024 + kp] = ll;
                    split_pair_f16(v1, p1, hh, ll);
                    ohi[(rb + hd + 1) * 1024 + kp] = hh; olo[(rb + hd + 1) * 1024 + kp] = ll;
                    split_pair_f16(v2, p2, hh, ll);
                    ohi[(rb + hd) * 1024 + kp + 4] = hh;     olo[(rb + hd) * 1024 + kp + 4] = ll;
                    split_pair_f16(v3, p3, hh, ll);
                    ohi[(rb + hd + 1) * 1024 + kp + 4] = hh; olo[(rb + hd + 1) * 1024 + kp + 4] = ll;
                }
            }
        }
    }
}

// ---------------------------------------------------------------------------
// Output GEMM: ctx(fp16 split) @ Wo(hi)^T + bo -> fp32 out
// ---------------------------------------------------------------------------
__global__ __launch_bounds__(256, 2)
void gemm_out_kernel(const unsigned* __restrict__ Xhi, const unsigned* __restrict__ Xlo,
                     const unsigned* __restrict__ Whi,
                     const float* __restrict__ bias, float* __restrict__ outf)
{
    extern __shared__ unsigned sg[];

    const int t    = threadIdx.x;
    const int lane = t & 31;
    const int wid  = t >> 5;
    const int wm   = wid >> 2;
    const int wn   = wid & 3;
    const int g    = lane >> 2;
    const int tig  = lane & 3;
    const int m0 = blockIdx.y * 128;
    const int n0 = blockIdx.x * 128;

    float c[4][4][4];
#pragma unroll
    for (int i = 0; i < 4; ++i)
#pragma unroll
        for (int j = 0; j < 4; ++j)
#pragma unroll
            for (int e = 0; e < 4; ++e) c[i][j][e] = 0.0f;

    gemm_mainloop(Xhi, Xlo, Whi, m0, n0, sg, c);

#pragma unroll
    for (int mf = 0; mf < 4; ++mf) {
#pragma unroll
        for (int nf = 0; nf < 4; ++nf) {
            int m = m0 + wm * 64 + mf * 16 + g;
            int n = n0 + wn * 32 + nf * 8 + tig * 2;
            outf[(size_t)m * Dc + n]           = c[mf][nf][0] + bias[n];
            outf[(size_t)m * Dc + n + 1]       = c[mf][nf][1] + bias[n + 1];
            outf[(size_t)(m + 8) * Dc + n]     = c[mf][nf][2] + bias[n];
            outf[(size_t)(m + 8) * Dc + n + 1] = c[mf][nf][3] + bias[n + 1];
        }
    }
}

// ---------------------------------------------------------------------------
// Tensor-core flash attention (bf16x3 QK, fp16 P + fp16-split V 2-pass PV),
// exp2-domain softmax, cp.async double-buffered K/V; ctx out = fp16 split.
// ---------------------------------------------------------------------------
#define AT_STAGE_U32 (4*64*36)
#define ATTN3_SMEM_U32 (2*128*36 + 2*AT_STAGE_U32)
#define ATTN3_SMEM_BYTES (ATTN3_SMEM_U32 * 4)   // 110592

__global__ __launch_bounds__(256, 2)
void attn_mma_kernel(const unsigned* __restrict__ Qhg, const unsigned* __restrict__ Qlg,
                     const unsigned* __restrict__ Khg, const unsigned* __restrict__ Klg,
                     const unsigned* __restrict__ Vthg, const unsigned* __restrict__ Vtlg,
                     unsigned* __restrict__ Chi, unsigned* __restrict__ Clo)
{
    extern __shared__ unsigned smu[];
    unsigned* Qsh = smu;                    // [128][36]
    unsigned* Qsl = Qsh + 128 * 36;
    unsigned* stages = Qsl + 128 * 36;

    const int bh = blockIdx.y;
    const int qt = (int)(gridDim.x - 1 - blockIdx.x);
    const int q0 = qt * 128;
    const int t    = threadIdx.x;
    const int lane = t & 31;
    const int w    = t >> 5;
    const int g    = lane >> 2;
    const int tig  = lane & 3;

    const int agrp  = lane >> 3;
    const int l7    = lane & 7;
    const int a_row = l7 + ((agrp & 1) << 3);
    const int a_col = (agrp >> 1) << 2;
    const int b_row = l7 + ((agrp >> 1) << 3);
    const int b_col = (agrp & 1) << 2;

    const unsigned* Qbh = Qhg + (size_t)bh * Sc * 32;
    const unsigned* Qbl = Qlg + (size_t)bh * Sc * 32;
    const unsigned* Kbh = Khg + (size_t)bh * Sc * 32;
    const unsigned* Kbl = Klg + (size_t)bh * Sc * 32;
    const unsigned* Vbh = Vthg + (size_t)bh * 64 * 1024;
    const unsigned* Vbl = Vtlg + (size_t)bh * 64 * 1024;

#pragma unroll
    for (int j = 0; j < 4; ++j) {
        int id = t + j * 256;
        int r = id >> 3, c4 = (id & 7) << 2;
        cp16(&Qsh[r * 36 + c4], &Qbh[(size_t)(q0 + r) * 32 + c4]);
        cp16(&Qsl[r * 36 + c4], &Qbl[(size_t)(q0 + r) * 32 + c4]);
    }
    asm volatile("cp.async.commit_group;\n" ::: "memory");

    auto stage_fn = [&](int st, int kt) {
        unsigned* Kh = stages + st * AT_STAGE_U32;
        unsigned* Kl = Kh + 64 * 36;
        unsigned* Vh = Kl + 64 * 36;
        unsigned* Vl = Vh + 64 * 36;
        const int k0 = kt * 64, kp0 = kt * 32;
#pragma unroll
        for (int j = 0; j < 2; ++j) {
            int id = t + j * 256;
            int r = id >> 3, c4 = (id & 7) << 2;
            cp16(Kh + r * 36 + c4, Kbh + (size_t)(k0 + r) * 32 + c4);
            cp16(Kl + r * 36 + c4, Kbl + (size_t)(k0 + r) * 32 + c4);
            cp16(Vh + r * 36 + c4, Vbh + (size_t)r * 1024 + kp0 + c4);
            cp16(Vl + r * 36 + c4, Vbl + (size_t)r * 1024 + kp0 + c4);
        }
        asm volatile("cp.async.commit_group;\n" ::: "memory");
    };

    float m_i[2] = {-1e30f, -1e30f};
    float l_i[2] = {0.0f, 0.0f};
    float o[8][4];
#pragma unroll
    for (int f = 0; f < 8; ++f)
#pragma unroll
        for (int e = 0; e < 4; ++e) o[f][e] = 0.0f;

    const int row0 = q0 + w * 16 + g;
    const int nkt = 2 * qt + 2;

    stage_fn(0, 0);

    for (int kt = 0; kt < nkt; ++kt) {
        const int k0 = kt * 64;
        __syncthreads();
        if (kt + 1 < nkt) {
            stage_fn((kt + 1) & 1, kt + 1);
            asm volatile("cp.async.wait_group 1;\n" ::: "memory");
        } else {
            asm volatile("cp.async.wait_group 0;\n" ::: "memory");
        }
        __syncthreads();

        if (q0 + w * 16 + 15 < k0) continue;

        const unsigned* Ksh = stages + (kt & 1) * AT_STAGE_U32;
        const unsigned* Ksl = Ksh + 64 * 36;
        const unsigned* Vsh = Ksl + 64 * 36;
        const unsigned* Vsl = Vsh + 64 * 36;

        // ---- S = Q K^T (bf16x3, pass-major) ----
        float s[8][4];
#pragma unroll
        for (int nf = 0; nf < 8; ++nf)
#pragma unroll
            for (int e = 0; e < 4; ++e) s[nf][e] = 0.0f;

#pragma unroll
        for (int ks = 0; ks < 4; ++ks) {
            unsigned aqh[4], aql[4];
            const int qoff = (w * 16 + a_row) * 36 + 8 * ks + a_col;
            ldsm4(aqh, Qsh + qoff);
            ldsm4(aql, Qsl + qoff);
            unsigned khi[4][4], klo[4][4];
#pragma unroll
            for (int np = 0; np < 4; ++np) {
                const int koff = (np * 16 + b_row) * 36 + 8 * ks + b_col;
                ldsm4(khi[np], Ksh + koff);
                ldsm4(klo[np], Ksl + koff);
            }
#pragma unroll
            for (int nf = 0; nf < 8; ++nf)
                mma16816(s[nf], aqh, &khi[nf >> 1][(nf & 1) * 2]);
#pragma unroll
            for (int nf = 0; nf < 8; ++nf)
                mma16816(s[nf], aqh, &klo[nf >> 1][(nf & 1) * 2]);
#pragma unroll
            for (int nf = 0; nf < 8; ++nf)
                mma16816(s[nf], aql, &khi[nf >> 1][(nf & 1) * 2]);
        }

        // ---- causal mask ----
        if (k0 + 63 > q0 + w * 16) {
#pragma unroll
            for (int nf = 0; nf < 8; ++nf) {
                int key = k0 + 8 * nf + 2 * tig;
                if (key     > row0)     s[nf][0] = -1e30f;
                if (key + 1 > row0)     s[nf][1] = -1e30f;
                if (key     > row0 + 8) s[nf][2] = -1e30f;
                if (key + 1 > row0 + 8) s[nf][3] = -1e30f;
            }
        }

        // ---- online softmax (base-2 domain) ----
        float mx0 = -1e30f, mx1 = -1e30f;
#pragma unroll
        for (int nf = 0; nf < 8; ++nf) {
            mx0 = fmaxf(mx0, fmaxf(s[nf][0], s[nf][1]));
            mx1 = fmaxf(mx1, fmaxf(s[nf][2], s[nf][3]));
        }
        mx0 = fmaxf(mx0, __shfl_xor_sync(0xffffffffu, mx0, 1));
        mx0 = fmaxf(mx0, __shfl_xor_sync(0xffffffffu, mx0, 2));
        mx1 = fmaxf(mx1, __shfl_xor_sync(0xffffffffu, mx1, 1));
        mx1 = fmaxf(mx1, __shfl_xor_sync(0xffffffffu, mx1, 2));

        float mn0 = fmaxf(m_i[0], mx0);
        float mn1 = fmaxf(m_i[1], mx1);
        float cs0 = exp2f(m_i[0] - mn0);
        float cs1 = exp2f(m_i[1] - mn1);
        m_i[0] = mn0; m_i[1] = mn1;

        unsigned pf[8][2];
        float sum0 = 0.0f, sum1 = 0.0f;
#pragma unroll
        for (int nf = 0; nf < 8; ++nf) {
            float p0 = exp2f(s[nf][0] - mn0);
            float p1 = exp2f(s[nf][1] - mn0);
            float p2 = exp2f(s[nf][2] - mn1);
            float p3 = exp2f(s[nf][3] - mn1);
            sum0 += p0 + p1;
            sum1 += p2 + p3;
            __half2 h01 = __floats2half2_rn(p0, p1);
            __half2 h23 = __floats2half2_rn(p2, p3);
            pf[nf][0] = *reinterpret_cast<unsigned*>(&h01);
            pf[nf][1] = *reinterpret_cast<unsigned*>(&h23);
        }
        sum0 += __shfl_xor_sync(0xffffffffu, sum0, 1);
        sum0 += __shfl_xor_sync(0xffffffffu, sum0, 2);
        sum1 += __shfl_xor_sync(0xffffffffu, sum1, 1);
        sum1 += __shfl_xor_sync(0xffffffffu, sum1, 2);
        l_i[0] = l_i[0] * cs0 + sum0;
        l_i[1] = l_i[1] * cs1 + sum1;

#pragma unroll
        for (int f = 0; f < 8; ++f) {
            o[f][0] *= cs0; o[f][1] *= cs0;
            o[f][2] *= cs1; o[f][3] *= cs1;
        }

        // ---- O += P V (fp16, 2-pass) ----
#pragma unroll
        for (int ks = 0; ks < 4; ++ks) {
            unsigned pa[4] = { pf[2 * ks][0], pf[2 * ks][1],
                               pf[2 * ks + 1][0], pf[2 * ks + 1][1] };
            unsigned vhi[4][4], vlo[4][4];
#pragma unroll
            for (int np = 0; np < 4; ++np) {
                const int voff = (np * 16 + b_row) * 36 + 8 * ks + b_col;
                ldsm4(vhi[np], Vsh + voff);
                ldsm4(vlo[np], Vsl + voff);
            }
#pragma unroll
            for (int nf = 0; nf < 8; ++nf)
                mma16816f16(o[nf], pa, &vhi[nf >> 1][(nf & 1) * 2]);
#pragma unroll
            for (int nf = 0; nf < 8; ++nf)
                mma16816f16(o[nf], pa, &vlo[nf >> 1][(nf & 1) * 2]);
        }
    }

    // ---- epilogue: normalize, fp16 split, write ctx ----
    const float inv0 = 1.0f / l_i[0];
    const float inv1 = 1.0f / l_i[1];
    const int b = bh >> 4;
    const int h = bh & 15;
#pragma unroll
    for (int nf = 0; nf < 8; ++nf) {
        int col = 8 * nf + 2 * tig;
        unsigned hh, ll;
        split_pair_f16(o[nf][0] * inv0, o[nf][1] * inv0, hh, ll);
        size_t p0 = ((size_t)b * Sc + row0) * 512 + h * 32 + (col >> 1);
        Chi[p0] = hh; Clo[p0] = ll;
        split_pair_f16(o[nf][2] * inv1, o[nf][3] * inv1, hh, ll);
        size_t p1 = ((size_t)b * Sc + row0 + 8) * 512 + h * 32 + (col >> 1);
        Chi[p1] = hh; Clo[p1] = ll;
    }
}

// ---------------------------------------------------------------------------
// Launch
// ---------------------------------------------------------------------------
#define SYMADDR(p, s) do { void* _tmp; cudaGetSymbolAddress(&_tmp, s); p = (unsigned*)_tmp; } while (0)

extern "C" void kernel_launch(void* const* d_in, const int* in_sizes, int n_in,
                              void* d_out, int out_size)
{
    const float* q  = (const float*)d_in[0];
    const float* k  = (const float*)d_in[1];
    const float* v  = (const float*)d_in[2];
    const float* Wq = (const float*)d_in[4];
    const float* bq = (const float*)d_in[5];
    const float* Wk = (const float*)d_in[6];
    const float* bk = (const float*)d_in[7];
    const float* Wv = (const float*)d_in[8];
    const float* bv = (const float*)d_in[9];
    const float* Wo = (const float*)d_in[10];
    const float* bo = (const float*)d_in[11];
    float* out = (float*)d_out;

    unsigned *wqh,*wql,*wkh,*wkl,*wvh,*wvl,*woh,*wol;
    unsigned *xqh,*xql,*xkh,*xkl,*xvh,*xvl;
    unsigned *qh,*ql,*kh,*kl,*vth,*vtl,*ch,*cl;
    SYMADDR(wqh, g_Wqhi); SYMADDR(wql, g_Wqlo);
    SYMADDR(wkh, g_Wkhi); SYMADDR(wkl, g_Wklo);
    SYMADDR(wvh, g_Wvhi); SYMADDR(wvl, g_Wvlo);
    SYMADDR(woh, g_Wohi); SYMADDR(wol, g_Wolo);
    SYMADDR(xqh, g_Xqhi); SYMADDR(xql, g_Xqlo);
    SYMADDR(xkh, g_Xkhi); SYMADDR(xkl, g_Xklo);
    SYMADDR(xvh, g_Xvhi); SYMADDR(xvl, g_Xvlo);
    SYMADDR(qh, g_Qhi);   SYMADDR(ql, g_Qlo);
    SYMADDR(kh, g_Khi);   SYMADDR(kl, g_Klo);
    SYMADDR(vth, g_Vthi); SYMADDR(vtl, g_Vtlo);
    SYMADDR(ch, g_Chi);   SYMADDR(cl, g_Clo);

    cudaFuncSetAttribute(gemm_qkv_kernel, cudaFuncAttributeMaxDynamicSharedMemorySize, GEMM_SMEM);
    cudaFuncSetAttribute(gemm_out_kernel, cudaFuncAttributeMaxDynamicSharedMemorySize, GEMM_SMEM);
    cudaFuncSetAttribute(attn_mma_kernel, cudaFuncAttributeMaxDynamicSharedMemorySize, ATTN3_SMEM_BYTES);

    split4_kernel<<<dim3(1024, 4), 256>>>(
        (const float4*)Wq, (const float4*)Wk, (const float4*)Wv, (const float4*)Wo,
        (uint2*)wqh, (uint2*)wkh, (uint2*)wvh, (uint2*)woh,
        (uint2*)wql, (uint2*)wkl, (uint2*)wvl, (uint2*)wol);
    split4_kernel<<<dim3(8192, 3), 256>>>(
        (const float4*)q, (const float4*)k, (const float4*)v, (const float4*)v,
        (uint2*)xqh, (uint2*)xkh, (uint2*)xvh, (uint2*)xvh,
        (uint2*)xql, (uint2*)xkl, (uint2*)xvl, (uint2*)xvl);

    dim3 gg3(Dc / 128, Mrows / 128, 3);   // (8, 64, 3)
    gemm_qkv_kernel<<<gg3, 256, GEMM_SMEM>>>(
        xqh, xql, xkh, xkl, xvh, xvl,
        wqh, wkh, wvh,
        bq, bk, bv,
        qh, ql, kh, kl, vth, vtl);

    dim3 ga(Sc / 128, Bc * Hc);           // (16, 64)
    attn_mma_kernel<<<ga, 256, ATTN3_SMEM_BYTES>>>(qh, ql, kh, kl, vth, vtl, ch, cl);

    dim3 gg(Dc / 128, Mrows / 128);       // (8, 64)
    gemm_out_kernel<<<gg, 256, GEMM_SMEM>>>(ch, cl, woh, bo, out);
}

// round 13
// speedup vs baseline: 3.0651x; 1.0790x over previous
#include <cuda_runtime.h>
#include <cuda_bf16.h>
#include <cuda_fp16.h>

// Problem constants
#define Bc 4
#define Sc 2048
#define Dc 1024
#define Hc 16
#define Mrows (Bc*Sc)   // 8192

#define SCALE_Q 0.18033688010819965f   // 0.125 * log2(e)

// ---------------------------------------------------------------------------
// Device scratch (u32 = packed pair of 16-bit values), all fp16 planes
// ---------------------------------------------------------------------------
__device__ unsigned g_Wqhi[1024*512], g_Wqlo[1024*512];
__device__ unsigned g_Wkhi[1024*512], g_Wklo[1024*512];
__device__ unsigned g_Wvhi[1024*512], g_Wvlo[1024*512];
__device__ unsigned g_Wohi[1024*512], g_Wolo[1024*512];
__device__ unsigned g_Xqhi[(size_t)Mrows*512], g_Xqlo[(size_t)Mrows*512];
__device__ unsigned g_Xkhi[(size_t)Mrows*512], g_Xklo[(size_t)Mrows*512];
__device__ unsigned g_Xvhi[(size_t)Mrows*512], g_Xvlo[(size_t)Mrows*512];
// Q head layout [B,H,S,32] fp16 split; K single fp16 plane
__device__ unsigned g_Qhi[(size_t)Mrows*512], g_Qlo[(size_t)Mrows*512];
__device__ unsigned g_Khi[(size_t)Mrows*512];
// V transposed head layout [B,H,64(hd),1024(key-pair)] fp16 split
__device__ unsigned g_Vthi[(size_t)Mrows*512], g_Vtlo[(size_t)Mrows*512];
// ctx [B,S,512] fp16 split
__device__ unsigned g_Chi[(size_t)Mrows*512], g_Clo[(size_t)Mrows*512];

// ---------------------------------------------------------------------------
// Helpers
// ---------------------------------------------------------------------------
__device__ __forceinline__ void split_pair_f16(float x0, float x1,
                                               unsigned& hi, unsigned& lo)
{
    __half2 h2 = __floats2half2_rn(x0, x1);
    float2 hf = __half22float2(h2);
    __half2 l2 = __floats2half2_rn(x0 - hf.x, x1 - hf.y);
    hi = *reinterpret_cast<unsigned*>(&h2);
    lo = *reinterpret_cast<unsigned*>(&l2);
}

__device__ __forceinline__ void mma16816f16(float c[4], const unsigned a[4],
                                            const unsigned b[2])
{
    asm volatile(
        "mma.sync.aligned.m16n8k16.row.col.f32.f16.f16.f32 "
        "{%0,%1,%2,%3}, {%4,%5,%6,%7}, {%8,%9}, {%0,%1,%2,%3};\n"
        : "+f"(c[0]), "+f"(c[1]), "+f"(c[2]), "+f"(c[3])
        : "r"(a[0]), "r"(a[1]), "r"(a[2]), "r"(a[3]),
          "r"(b[0]), "r"(b[1]));
}

__device__ __forceinline__ void ldsm4(unsigned r[4], const unsigned* p)
{
    unsigned a = (unsigned)__cvta_generic_to_shared(p);
    asm volatile("ldmatrix.sync.aligned.m8n8.x4.shared.b16 {%0,%1,%2,%3}, [%4];\n"
                 : "=r"(r[0]), "=r"(r[1]), "=r"(r[2]), "=r"(r[3]) : "r"(a));
}

__device__ __forceinline__ void cp16(void* smem, const void* g)
{
    unsigned sa = (unsigned)__cvta_generic_to_shared(smem);
    asm volatile("cp.async.cg.shared.global [%0], [%1], 16;\n"
                 :: "r"(sa), "l"(g) : "memory");
}

// ---------------------------------------------------------------------------
// Batched split converter (fp16 hi/lo)
// ---------------------------------------------------------------------------
__global__ __launch_bounds__(256)
void split4_kernel(const float4* __restrict__ i0, const float4* __restrict__ i1,
                   const float4* __restrict__ i2, const float4* __restrict__ i3,
                   uint2* __restrict__ h0, uint2* __restrict__ h1,
                   uint2* __restrict__ h2, uint2* __restrict__ h3,
                   uint2* __restrict__ l0, uint2* __restrict__ l1,
                   uint2* __restrict__ l2, uint2* __restrict__ l3)
{
    const float4* in; uint2 *hi, *lo;
    switch (blockIdx.y) {
        case 0:  in = i0; hi = h0; lo = l0; break;
        case 1:  in = i1; hi = h1; lo = l1; break;
        case 2:  in = i2; hi = h2; lo = l2; break;
        default: in = i3; hi = h3; lo = l3; break;
    }
    int i = blockIdx.x * 256 + threadIdx.x;
    float4 f = in[i];
    unsigned a0, b0, a1, b1;
    split_pair_f16(f.x, f.y, a0, b0);
    split_pair_f16(f.z, f.w, a1, b1);
    hi[i] = make_uint2(a0, a1);
    lo[i] = make_uint2(b0, b1);
}

// ---------------------------------------------------------------------------
// Shared GEMM mainloop: fp16 2-pass (X split hi/lo, W hi only).
// ---------------------------------------------------------------------------
#define KPAD 20
#define HALF_U32 (128*KPAD)
#define STAGE_U32 (3*HALF_U32)
#define GEMM_SMEM (2*STAGE_U32*4)   // 61440 bytes

__device__ __forceinline__ void gemm_mainloop(
    const unsigned* __restrict__ Xhi, const unsigned* __restrict__ Xlo,
    const unsigned* __restrict__ Whi,
    int m0, int n0, unsigned* sg, float c[4][4][4])
{
    const int t    = threadIdx.x;
    const int lane = t & 31;
    const int wid  = t >> 5;
    const int wm   = wid >> 2;
    const int wn   = wid & 3;

    const int agrp  = lane >> 3;
    const int l7    = lane & 7;
    const int a_row = l7 + ((agrp & 1) << 3);
    const int a_col = (agrp >> 1) << 2;
    const int b_row = l7 + ((agrp >> 1) << 3);
    const int b_col = (agrp & 1) << 2;

    auto issue = [&](int stage, int kt) {
        unsigned* base = sg + stage * STAGE_U32;
#pragma unroll
        for (int j = 0; j < 6; ++j) {
            int id   = t + j * 256;
            int half = id >> 9;
            int rem  = id & 511;
            int row  = rem >> 2;
            int c4   = (rem & 3) << 2;
            const unsigned* src;
            if      (half == 0) src = Xhi + (size_t)(m0 + row) * 512 + kt * 16 + c4;
            else if (half == 1) src = Xlo + (size_t)(m0 + row) * 512 + kt * 16 + c4;
            else                src = Whi + (size_t)(n0 + row) * 512 + kt * 16 + c4;
            cp16(base + half * HALF_U32 + row * KPAD + c4, src);
        }
        asm volatile("cp.async.commit_group;\n" ::: "memory");
    };

    issue(0, 0);

    const int NT = 32;
    for (int kt = 0; kt < NT; ++kt) {
        if (kt + 1 < NT) {
            issue((kt + 1) & 1, kt + 1);
            asm volatile("cp.async.wait_group 1;\n" ::: "memory");
        } else {
            asm volatile("cp.async.wait_group 0;\n" ::: "memory");
        }
        __syncthreads();

        const unsigned* Ah = sg + (kt & 1) * STAGE_U32;
        const unsigned* Al = Ah + HALF_U32;
        const unsigned* Bh = Ah + 2 * HALF_U32;

#pragma unroll
        for (int ks = 0; ks < 2; ++ks) {
            const int pb = ks * 8;
            unsigned ahi[4][4], alo[4][4], bhi[2][4];
#pragma unroll
            for (int mf = 0; mf < 4; ++mf) {
                const int r = (wm * 64 + mf * 16 + a_row) * KPAD + pb + a_col;
                ldsm4(ahi[mf], Ah + r);
                ldsm4(alo[mf], Al + r);
            }
#pragma unroll
            for (int np = 0; np < 2; ++np) {
                const int r = (wn * 32 + np * 16 + b_row) * KPAD + pb + b_col;
                ldsm4(bhi[np], Bh + r);
            }
#pragma unroll
            for (int mf = 0; mf < 4; ++mf)
#pragma unroll
                for (int nf = 0; nf < 4; ++nf)
                    mma16816f16(c[mf][nf], ahi[mf], &bhi[nf >> 1][(nf & 1) * 2]);
#pragma unroll
            for (int mf = 0; mf < 4; ++mf)
#pragma unroll
                for (int nf = 0; nf < 4; ++nf)
                    mma16816f16(c[mf][nf], alo[mf], &bhi[nf >> 1][(nf & 1) * 2]);
        }
        __syncthreads();
    }
}

// ---------------------------------------------------------------------------
// Merged Q/K/V projection GEMM: z=0 Q (fp16 split out, scaled),
// z=1 K (single fp16 out), z=2 V (transposed fp16 split out).
// ---------------------------------------------------------------------------
__global__ __launch_bounds__(256, 2)
void gemm_qkv_kernel(const unsigned* __restrict__ xqh, const unsigned* __restrict__ xql,
                     const unsigned* __restrict__ xkh, const unsigned* __restrict__ xkl,
                     const unsigned* __restrict__ xvh, const unsigned* __restrict__ xvl,
                     const unsigned* __restrict__ wqh,
                     const unsigned* __restrict__ wkh,
                     const unsigned* __restrict__ wvh,
                     const float* __restrict__ bq, const float* __restrict__ bk,
                     const float* __restrict__ bv,
                     unsigned* __restrict__ qh, unsigned* __restrict__ ql,
                     unsigned* __restrict__ kh,
                     unsigned* __restrict__ vth, unsigned* __restrict__ vtl)
{
    extern __shared__ unsigned sg[];

    const int z = blockIdx.z;
    const unsigned *Xhi, *Xlo, *Whi;
    const float* bias;
    float scale;
    if (z == 0) { Xhi = xqh; Xlo = xql; Whi = wqh; bias = bq; scale = SCALE_Q; }
    else if (z == 1) { Xhi = xkh; Xlo = xkl; Whi = wkh; bias = bk; scale = 1.0f; }
    else { Xhi = xvh; Xlo = xvl; Whi = wvh; bias = bv; scale = 1.0f; }

    const int t    = threadIdx.x;
    const int lane = t & 31;
    const int wid  = t >> 5;
    const int wm   = wid >> 2;
    const int wn   = wid & 3;
    const int g    = lane >> 2;
    const int tig  = lane & 3;
    const int m0 = blockIdx.y * 128;
    const int n0 = blockIdx.x * 128;

    float c[4][4][4];
#pragma unroll
    for (int i = 0; i < 4; ++i)
#pragma unroll
        for (int j = 0; j < 4; ++j)
#pragma unroll
            for (int e = 0; e < 4; ++e) c[i][j][e] = 0.0f;

    gemm_mainloop(Xhi, Xlo, Whi, m0, n0, sg, c);

#pragma unroll
    for (int mf = 0; mf < 4; ++mf) {
#pragma unroll
        for (int nf = 0; nf < 4; ++nf) {
            int m = m0 + wm * 64 + mf * 16 + g;
            int n = n0 + wn * 32 + nf * 8 + tig * 2;
            float v0 = (c[mf][nf][0] + bias[n]) * scale;
            float v1 = (c[mf][nf][1] + bias[n + 1]) * scale;
            float v2 = (c[mf][nf][2] + bias[n]) * scale;
            float v3 = (c[mf][nf][3] + bias[n + 1]) * scale;
            int b = m >> 11, s = m & 2047;
            int h = n >> 6, hd = n & 63;
            if (z == 0) {
                unsigned hh, ll;
                split_pair_f16(v0, v1, hh, ll);
                size_t p0 = (((size_t)(b * Hc + h)) * Sc + s) * 32 + (hd >> 1);
                qh[p0] = hh; ql[p0] = ll;
                split_pair_f16(v2, v3, hh, ll);
                size_t p1 = (((size_t)(b * Hc + h)) * Sc + (s + 8)) * 32 + (hd >> 1);
                qh[p1] = hh; ql[p1] = ll;
            } else if (z == 1) {
                __half2 h01 = __floats2half2_rn(v0, v1);
                __half2 h23 = __floats2half2_rn(v2, v3);
                size_t p0 = (((size_t)(b * Hc + h)) * Sc + s) * 32 + (hd >> 1);
                size_t p1 = (((size_t)(b * Hc + h)) * Sc + (s + 8)) * 32 + (hd >> 1);
                kh[p0] = *reinterpret_cast<unsigned*>(&h01);
                kh[p1] = *reinterpret_cast<unsigned*>(&h23);
            } else {
                float p0 = __shfl_xor_sync(0xffffffffu, v0, 4);
                float p1 = __shfl_xor_sync(0xffffffffu, v1, 4);
                float p2 = __shfl_xor_sync(0xffffffffu, v2, 4);
                float p3 = __shfl_xor_sync(0xffffffffu, v3, 4);
                if (!(g & 1)) {
                    size_t rb = ((size_t)(b * Hc + h)) * 64;
                    int kp = s >> 1;
                    unsigned hh, ll;
                    split_pair_f16(v0, p0, hh, ll);
                    vth[(rb + hd) * 1024 + kp] = hh;     vtl[(rb + hd) * 1024 + kp] = ll;
                    split_pair_f16(v1, p1, hh, ll);
                    vth[(rb + hd + 1) * 1024 + kp] = hh; vtl[(rb + hd + 1) * 1024 + kp] = ll;
                    split_pair_f16(v2, p2, hh, ll);
                    vth[(rb + hd) * 1024 + kp + 4] = hh;     vtl[(rb + hd) * 1024 + kp + 4] = ll;
                    split_pair_f16(v3, p3, hh, ll);
                    vth[(rb + hd + 1) * 1024 + kp + 4] = hh; vtl[(rb + hd + 1) * 1024 + kp + 4] = ll;
                }
            }
        }
    }
}

// ---------------------------------------------------------------------------
// Output GEMM: ctx(fp16 split) @ Wo(hi)^T + bo -> fp32 out
// ---------------------------------------------------------------------------
__global__ __launch_bounds__(256, 2)
void gemm_out_kernel(const unsigned* __restrict__ Xhi, const unsigned* __restrict__ Xlo,
                     const unsigned* __restrict__ Whi,
                     const float* __restrict__ bias, float* __restrict__ outf)
{
    extern __shared__ unsigned sg[];

    const int t    = threadIdx.x;
    const int lane = t & 31;
    const int wid  = t >> 5;
    const int wm   = wid >> 2;
    const int wn   = wid & 3;
    const int g    = lane >> 2;
    const int tig  = lane & 3;
    const int m0 = blockIdx.y * 128;
    const int n0 = blockIdx.x * 128;

    float c[4][4][4];
#pragma unroll
    for (int i = 0; i < 4; ++i)
#pragma unroll
        for (int j = 0; j < 4; ++j)
#pragma unroll
            for (int e = 0; e < 4; ++e) c[i][j][e] = 0.0f;

    gemm_mainloop(Xhi, Xlo, Whi, m0, n0, sg, c);

#pragma unroll
    for (int mf = 0; mf < 4; ++mf) {
#pragma unroll
        for (int nf = 0; nf < 4; ++nf) {
            int m = m0 + wm * 64 + mf * 16 + g;
            int n = n0 + wn * 32 + nf * 8 + tig * 2;
            outf[(size_t)m * Dc + n]           = c[mf][nf][0] + bias[n];
            outf[(size_t)m * Dc + n + 1]       = c[mf][nf][1] + bias[n + 1];
            outf[(size_t)(m + 8) * Dc + n]     = c[mf][nf][2] + bias[n];
            outf[(size_t)(m + 8) * Dc + n + 1] = c[mf][nf][3] + bias[n + 1];
        }
    }
}

// ---------------------------------------------------------------------------
// Flash attention: fp16 2-pass QK (Q split, K single), fp16 P + fp16-split V
// 2-pass PV, exp2 softmax, cp.async double-buffered (Kh,Vh,Vl per stage).
// ---------------------------------------------------------------------------
#define AT_STAGE_U32 (3*64*36)
#define ATTN4_SMEM_U32 (2*128*36 + 2*AT_STAGE_U32)
#define ATTN4_SMEM_BYTES (ATTN4_SMEM_U32 * 4)   // 92160

__global__ __launch_bounds__(256, 2)
void attn_mma_kernel(const unsigned* __restrict__ Qhg, const unsigned* __restrict__ Qlg,
                     const unsigned* __restrict__ Khg,
                     const unsigned* __restrict__ Vthg, const unsigned* __restrict__ Vtlg,
                     unsigned* __restrict__ Chi, unsigned* __restrict__ Clo)
{
    extern __shared__ unsigned smu[];
    unsigned* Qsh = smu;                    // [128][36]
    unsigned* Qsl = Qsh + 128 * 36;
    unsigned* stages = Qsl + 128 * 36;

    const int bh = blockIdx.y;
    const int qt = (int)(gridDim.x - 1 - blockIdx.x);
    const int q0 = qt * 128;
    const int t    = threadIdx.x;
    const int lane = t & 31;
    const int w    = t >> 5;
    const int g    = lane >> 2;
    const int tig  = lane & 3;

    const int agrp  = lane >> 3;
    const int l7    = lane & 7;
    const int a_row = l7 + ((agrp & 1) << 3);
    const int a_col = (agrp >> 1) << 2;
    const int b_row = l7 + ((agrp >> 1) << 3);
    const int b_col = (agrp & 1) << 2;

    const unsigned* Qbh = Qhg + (size_t)bh * Sc * 32;
    const unsigned* Qbl = Qlg + (size_t)bh * Sc * 32;
    const unsigned* Kbh = Khg + (size_t)bh * Sc * 32;
    const unsigned* Vbh = Vthg + (size_t)bh * 64 * 1024;
    const unsigned* Vbl = Vtlg + (size_t)bh * 64 * 1024;

#pragma unroll
    for (int j = 0; j < 4; ++j) {
        int id = t + j * 256;
        int r = id >> 3, c4 = (id & 7) << 2;
        cp16(&Qsh[r * 36 + c4], &Qbh[(size_t)(q0 + r) * 32 + c4]);
        cp16(&Qsl[r * 36 + c4], &Qbl[(size_t)(q0 + r) * 32 + c4]);
    }
    asm volatile("cp.async.commit_group;\n" ::: "memory");

    auto stage_fn = [&](int st, int kt) {
        unsigned* Kh = stages + st * AT_STAGE_U32;
        unsigned* Vh = Kh + 64 * 36;
        unsigned* Vl = Vh + 64 * 36;
        const int k0 = kt * 64, kp0 = kt * 32;
#pragma unroll
        for (int j = 0; j < 2; ++j) {
            int id = t + j * 256;
            int r = id >> 3, c4 = (id & 7) << 2;
            cp16(Kh + r * 36 + c4, Kbh + (size_t)(k0 + r) * 32 + c4);
            cp16(Vh + r * 36 + c4, Vbh + (size_t)r * 1024 + kp0 + c4);
            cp16(Vl + r * 36 + c4, Vbl + (size_t)r * 1024 + kp0 + c4);
        }
        asm volatile("cp.async.commit_group;\n" ::: "memory");
    };

    float m_i[2] = {-1e30f, -1e30f};
    float l_i[2] = {0.0f, 0.0f};
    float o[8][4];
#pragma unroll
    for (int f = 0; f < 8; ++f)
#pragma unroll
        for (int e = 0; e < 4; ++e) o[f][e] = 0.0f;

    const int row0 = q0 + w * 16 + g;
    const int nkt = 2 * qt + 2;

    stage_fn(0, 0);

    for (int kt = 0; kt < nkt; ++kt) {
        const int k0 = kt * 64;
        __syncthreads();
        if (kt + 1 < nkt) {
            stage_fn((kt + 1) & 1, kt + 1);
            asm volatile("cp.async.wait_group 1;\n" ::: "memory");
        } else {
            asm volatile("cp.async.wait_group 0;\n" ::: "memory");
        }
        __syncthreads();

        if (q0 + w * 16 + 15 < k0) continue;

        const unsigned* Ksh = stages + (kt & 1) * AT_STAGE_U32;
        const unsigned* Vsh = Ksh + 64 * 36;
        const unsigned* Vsl = Vsh + 64 * 36;

        // ---- S = Q K^T (fp16 2-pass: qh*kh + ql*kh) ----
        float s[8][4];
#pragma unroll
        for (int nf = 0; nf < 8; ++nf)
#pragma unroll
            for (int e = 0; e < 4; ++e) s[nf][e] = 0.0f;

#pragma unroll
        for (int ks = 0; ks < 4; ++ks) {
            unsigned aqh[4], aql[4];
            const int qoff = (w * 16 + a_row) * 36 + 8 * ks + a_col;
            ldsm4(aqh, Qsh + qoff);
            ldsm4(aql, Qsl + qoff);
            unsigned khi[4][4];
#pragma unroll
            for (int np = 0; np < 4; ++np) {
                const int koff = (np * 16 + b_row) * 36 + 8 * ks + b_col;
                ldsm4(khi[np], Ksh + koff);
            }
#pragma unroll
            for (int nf = 0; nf < 8; ++nf)
                mma16816f16(s[nf], aqh, &khi[nf >> 1][(nf & 1) * 2]);
#pragma unroll
            for (int nf = 0; nf < 8; ++nf)
                mma16816f16(s[nf], aql, &khi[nf >> 1][(nf & 1) * 2]);
        }

        // ---- causal mask ----
        if (k0 + 63 > q0 + w * 16) {
#pragma unroll
            for (int nf = 0; nf < 8; ++nf) {
                int key = k0 + 8 * nf + 2 * tig;
                if (key     > row0)     s[nf][0] = -1e30f;
                if (key + 1 > row0)     s[nf][1] = -1e30f;
                if (key     > row0 + 8) s[nf][2] = -1e30f;
                if (key + 1 > row0 + 8) s[nf][3] = -1e30f;
            }
        }

        // ---- online softmax (base-2 domain) ----
        float mx0 = -1e30f, mx1 = -1e30f;
#pragma unroll
        for (int nf = 0; nf < 8; ++nf) {
            mx0 = fmaxf(mx0, fmaxf(s[nf][0], s[nf][1]));
            mx1 = fmaxf(mx1, fmaxf(s[nf][2], s[nf][3]));
        }
        mx0 = fmaxf(mx0, __shfl_xor_sync(0xffffffffu, mx0, 1));
        mx0 = fmaxf(mx0, __shfl_xor_sync(0xffffffffu, mx0, 2));
        mx1 = fmaxf(mx1, __shfl_xor_sync(0xffffffffu, mx1, 1));
        mx1 = fmaxf(mx1, __shfl_xor_sync(0xffffffffu, mx1, 2));

        float mn0 = fmaxf(m_i[0], mx0);
        float mn1 = fmaxf(m_i[1], mx1);
        float cs0 = exp2f(m_i[0] - mn0);
        float cs1 = exp2f(m_i[1] - mn1);
        m_i[0] = mn0; m_i[1] = mn1;

        unsigned pf[8][2];
        float sum0 = 0.0f, sum1 = 0.0f;
#pragma unroll
        for (int nf = 0; nf < 8; ++nf) {
            float p0 = exp2f(s[nf][0] - mn0);
            float p1 = exp2f(s[nf][1] - mn0);
            float p2 = exp2f(s[nf][2] - mn1);
            float p3 = exp2f(s[nf][3] - mn1);
            sum0 += p0 + p1;
            sum1 += p2 + p3;
            __half2 h01 = __floats2half2_rn(p0, p1);
            __half2 h23 = __floats2half2_rn(p2, p3);
            pf[nf][0] = *reinterpret_cast<unsigned*>(&h01);
            pf[nf][1] = *reinterpret_cast<unsigned*>(&h23);
        }
        sum0 += __shfl_xor_sync(0xffffffffu, sum0, 1);
        sum0 += __shfl_xor_sync(0xffffffffu, sum0, 2);
        sum1 += __shfl_xor_sync(0xffffffffu, sum1, 1);
        sum1 += __shfl_xor_sync(0xffffffffu, sum1, 2);
        l_i[0] = l_i[0] * cs0 + sum0;
        l_i[1] = l_i[1] * cs1 + sum1;

#pragma unroll
        for (int f = 0; f < 8; ++f) {
            o[f][0] *= cs0; o[f][1] *= cs0;
            o[f][2] *= cs1; o[f][3] *= cs1;
        }

        // ---- O += P V (fp16, 2-pass) ----
#pragma unroll
        for (int ks = 0; ks < 4; ++ks) {
            unsigned pa[4] = { pf[2 * ks][0], pf[2 * ks][1],
                               pf[2 * ks + 1][0], pf[2 * ks + 1][1] };
            unsigned vhi[4][4], vlo[4][4];
#pragma unroll
            for (int np = 0; np < 4; ++np) {
                const int voff = (np * 16 + b_row) * 36 + 8 * ks + b_col;
                ldsm4(vhi[np], Vsh + voff);
                ldsm4(vlo[np], Vsl + voff);
            }
#pragma unroll
            for (int nf = 0; nf < 8; ++nf)
                mma16816f16(o[nf], pa, &vhi[nf >> 1][(nf & 1) * 2]);
#pragma unroll
            for (int nf = 0; nf < 8; ++nf)
                mma16816f16(o[nf], pa, &vlo[nf >> 1][(nf & 1) * 2]);
        }
    }

    // ---- epilogue: normalize, fp16 split, write ctx ----
    const float inv0 = 1.0f / l_i[0];
    const float inv1 = 1.0f / l_i[1];
    const int b = bh >> 4;
    const int h = bh & 15;
#pragma unroll
    for (int nf = 0; nf < 8; ++nf) {
        int col = 8 * nf + 2 * tig;
        unsigned hh, ll;
        split_pair_f16(o[nf][0] * inv0, o[nf][1] * inv0, hh, ll);
        size_t p0 = ((size_t)b * Sc + row0) * 512 + h * 32 + (col >> 1);
        Chi[p0] = hh; Clo[p0] = ll;
        split_pair_f16(o[nf][2] * inv1, o[nf][3] * inv1, hh, ll);
        size_t p1 = ((size_t)b * Sc + row0 + 8) * 512 + h * 32 + (col >> 1);
        Chi[p1] = hh; Clo[p1] = ll;
    }
}

// ---------------------------------------------------------------------------
// Launch
// ---------------------------------------------------------------------------
#define SYMADDR(p, s) do { void* _tmp; cudaGetSymbolAddress(&_tmp, s); p = (unsigned*)_tmp; } while (0)

extern "C" void kernel_launch(void* const* d_in, const int* in_sizes, int n_in,
                              void* d_out, int out_size)
{
    const float* q  = (const float*)d_in[0];
    const float* k  = (const float*)d_in[1];
    const float* v  = (const float*)d_in[2];
    const float* Wq = (const float*)d_in[4];
    const float* bq = (const float*)d_in[5];
    const float* Wk = (const float*)d_in[6];
    const float* bk = (const float*)d_in[7];
    const float* Wv = (const float*)d_in[8];
    const float* bv = (const float*)d_in[9];
    const float* Wo = (const float*)d_in[10];
    const float* bo = (const float*)d_in[11];
    float* out = (float*)d_out;

    unsigned *wqh,*wql,*wkh,*wkl,*wvh,*wvl,*woh,*wol;
    unsigned *xqh,*xql,*xkh,*xkl,*xvh,*xvl;
    unsigned *qh,*ql,*kh,*vth,*vtl,*ch,*cl;
    SYMADDR(wqh, g_Wqhi); SYMADDR(wql, g_Wqlo);
    SYMADDR(wkh, g_Wkhi); SYMADDR(wkl, g_Wklo);
    SYMADDR(wvh, g_Wvhi); SYMADDR(wvl, g_Wvlo);
    SYMADDR(woh, g_Wohi); SYMADDR(wol, g_Wolo);
    SYMADDR(xqh, g_Xqhi); SYMADDR(xql, g_Xqlo);
    SYMADDR(xkh, g_Xkhi); SYMADDR(xkl, g_Xklo);
    SYMADDR(xvh, g_Xvhi); SYMADDR(xvl, g_Xvlo);
    SYMADDR(qh, g_Qhi);   SYMADDR(ql, g_Qlo);
    SYMADDR(kh, g_Khi);
    SYMADDR(vth, g_Vthi); SYMADDR(vtl, g_Vtlo);
    SYMADDR(ch, g_Chi);   SYMADDR(cl, g_Clo);

    cudaFuncSetAttribute(gemm_qkv_kernel, cudaFuncAttributeMaxDynamicSharedMemorySize, GEMM_SMEM);
    cudaFuncSetAttribute(gemm_out_kernel, cudaFuncAttributeMaxDynamicSharedMemorySize, GEMM_SMEM);
    cudaFuncSetAttribute(attn_mma_kernel, cudaFuncAttributeMaxDynamicSharedMemorySize, ATTN4_SMEM_BYTES);

    split4_kernel<<<dim3(1024, 4), 256>>>(
        (const float4*)Wq, (const float4*)Wk, (const float4*)Wv, (const float4*)Wo,
        (uint2*)wqh, (uint2*)wkh, (uint2*)wvh, (uint2*)woh,
        (uint2*)wql, (uint2*)wkl, (uint2*)wvl, (uint2*)wol);
    split4_kernel<<<dim3(8192, 3), 256>>>(
        (const float4*)q, (const float4*)k, (const float4*)v, (const float4*)v,
        (uint2*)xqh, (uint2*)xkh, (uint2*)xvh, (uint2*)xvh,
        (uint2*)xql, (uint2*)xkl, (uint2*)xvl, (uint2*)xvl);

    dim3 gg3(Dc / 128, Mrows / 128, 3);   // (8, 64, 3)
    gemm_qkv_kernel<<<gg3, 256, GEMM_SMEM>>>(
        xqh, xql, xkh, xkl, xvh, xvl,
        wqh, wkh, wvh,
        bq, bk, bv,
        qh, ql, kh, vth, vtl);

    dim3 ga(Sc / 128, Bc * Hc);           // (16, 64)
    attn_mma_kernel<<<ga, 256, ATTN4_SMEM_BYTES>>>(qh, ql, kh, vth, vtl, ch, cl);

    dim3 gg(Dc / 128, Mrows / 128);       // (8, 64)
    gemm_out_kernel<<<gg, 256, GEMM_SMEM>>>(ch, cl, woh, bo, out);
}